// round 9
// baseline (speedup 1.0000x reference)
#include <cuda_runtime.h>
#include <cuda_bf16.h>
#include <cuda_fp16.h>
#include <math.h>
#include <stdint.h>

#define BATCH   2
#define SEQLEN  4096
#define DMODEL  1024
#define DINNER  2048
#define HEADDIM 64
#define NHEADS  32
#define DSTATE  128
#define DCONV   4
#define CHUNK   256
#define NCHUNK  (SEQLEN / CHUNK)   // 16
#define NBC     (BATCH * NCHUNK)   // 32
#define DPROJ   4384               // 2*DINNER + 2*DSTATE + NHEADS
#define CONVDIM 2304               // DINNER + 2*DSTATE
#define DT_OFF  4352               // 2*DINNER + 2*DSTATE
#define ROWS    (BATCH * SEQLEN)   // 8192
#define NPAD1   4480               // DPROJ padded to multiple of 128

// ---------------- scratch (device globals; no allocation allowed) ----------
__device__ float g_zxbcdt[(size_t)ROWS * DPROJ];
__device__ float g_xBC[(size_t)ROWS * CONVDIM];
__device__ float g_dt[ROWS * NHEADS];
__device__ float g_acs[NBC * NHEADS * CHUNK];
__device__ float g_asum[NBC * NHEADS];
__device__ float g_CB[(size_t)NBC * CHUNK * CHUNK];
__device__ float g_Y[(size_t)ROWS * DINNER];
__device__ float g_S[(size_t)NBC * NHEADS * HEADDIM * DSTATE];
__device__ float g_Sinit[(size_t)NBC * NHEADS * HEADDIM * DSTATE];

// fp16 GEMM operands: activations single, weights hi/lo split
__device__ __half g_uf[(size_t)ROWS * DMODEL];
__device__ __half g_wih[(size_t)DMODEL * NPAD1];
__device__ __half g_wil[(size_t)DMODEL * NPAD1];
__device__ __half g_woh[(size_t)DINNER * DMODEL];
__device__ __half g_wol[(size_t)DINNER * DMODEL];
__device__ __half g_yg[(size_t)ROWS * DINNER];

// ---------------- helpers ---------------------------------------------------
__device__ __forceinline__ uint32_t s2u(const void* p) {
    return (uint32_t)__cvta_generic_to_shared(p);
}
#define CP16(dst, src) \
    asm volatile("cp.async.cg.shared.global [%0], [%1], 16;\n" :: "r"(dst), "l"(src))
#define CP_COMMIT() asm volatile("cp.async.commit_group;\n")
#define CP_WAIT1()  asm volatile("cp.async.wait_group 1;\n")

__device__ __forceinline__ void ldsm4(uint32_t& r0, uint32_t& r1, uint32_t& r2,
                                      uint32_t& r3, uint32_t addr) {
    asm volatile("ldmatrix.sync.aligned.m8n8.x4.shared.b16 {%0,%1,%2,%3}, [%4];"
                 : "=r"(r0), "=r"(r1), "=r"(r2), "=r"(r3) : "r"(addr));
}
__device__ __forceinline__ void ldsm4t(uint32_t& r0, uint32_t& r1, uint32_t& r2,
                                       uint32_t& r3, uint32_t addr) {
    asm volatile("ldmatrix.sync.aligned.m8n8.x4.trans.shared.b16 {%0,%1,%2,%3}, [%4];"
                 : "=r"(r0), "=r"(r1), "=r"(r2), "=r"(r3) : "r"(addr));
}
// fp16 mma
__device__ __forceinline__ void mma16816h(float* d, const uint32_t* a, const uint32_t* b) {
    asm volatile(
        "mma.sync.aligned.m16n8k16.row.col.f32.f16.f16.f32 "
        "{%0,%1,%2,%3}, {%4,%5,%6,%7}, {%8,%9}, {%0,%1,%2,%3};"
        : "+f"(d[0]), "+f"(d[1]), "+f"(d[2]), "+f"(d[3])
        : "r"(a[0]), "r"(a[1]), "r"(a[2]), "r"(a[3]), "r"(b[0]), "r"(b[1]));
}
// bf16 mma (yfused)
__device__ __forceinline__ void mma16816(float* d, const uint32_t* a, const uint32_t* b) {
    asm volatile(
        "mma.sync.aligned.m16n8k16.row.col.f32.bf16.bf16.f32 "
        "{%0,%1,%2,%3}, {%4,%5,%6,%7}, {%8,%9}, {%0,%1,%2,%3};"
        : "+f"(d[0]), "+f"(d[1]), "+f"(d[2]), "+f"(d[3])
        : "r"(a[0]), "r"(a[1]), "r"(a[2]), "r"(a[3]), "r"(b[0]), "r"(b[1]));
}
__device__ __forceinline__ void split2(float a, float b,
                                       __nv_bfloat162& h, __nv_bfloat162& l) {
    __nv_bfloat16 ha = __float2bfloat16(a), hb = __float2bfloat16(b);
    h = __halves2bfloat162(ha, hb);
    l = __halves2bfloat162(__float2bfloat16(a - __bfloat162float(ha)),
                           __float2bfloat16(b - __bfloat162float(hb)));
}

// ---------------- GEMM smem layout (bytes), tile 128x128, BK=32 -------------
// per stage: A[128][40] | Bh[32][136] | Bl[32][136]   (fp16)
#define A_B        10240         // 128*40*2
#define B_HALF_B   8704          // 32*136*2
#define OFF_BH     A_B
#define OFF_BL     (A_B + B_HALF_B)
#define STAGE_B    (A_B + 2 * B_HALF_B)            // 27648
#define NSTAGE     3
#define GEMM_SMEM  (NSTAGE * STAGE_B)              // 82944

// ---------------- fp16 2-term tensor-core GEMM (2 CTAs/SM, 128x128) ---------
// C[M,N] = A[M,K] * (Bh+Bl)[K,N]. 128x128 block, BK=32, 256 threads
// (8 warps 2x4), warp tile 64x32, 3-stage cp.async ring.
__global__ __launch_bounds__(256, 2) void mma_gemm(
    const __half* __restrict__ A,
    const __half* __restrict__ Bh, const __half* __restrict__ Bl,
    float* __restrict__ C, int M, int N, int K, int ldb, int ldc)
{
    extern __shared__ __half smem[];
    const uint32_t sbase = s2u(smem);
    const int rowBase = blockIdx.y * 128;
    const int colBase = blockIdx.x * 128;
    const int t = threadIdx.x;

    // A: 512 16B-chunks; thread t owns chunks t, t+256 (rows 0-63, 64-127)
    const int ar = t >> 2, aq = t & 3;
    const __half* aS = A + (size_t)(rowBase + ar) * K + aq * 8;
    const uint32_t aD = sbase + (ar * 40 + aq * 8) * 2;
    // B half: 512 chunks; thread t owns chunks t, t+256 (rows 0-15, 16-31)
    const int br = t >> 4, bq = t & 15;
    const __half* bSh = Bh + (size_t)br * ldb + colBase + bq * 8;
    const __half* bSl = Bl + (size_t)br * ldb + colBase + bq * 8;
    const uint32_t bD = sbase + OFF_BH + (br * 136 + bq * 8) * 2;

    const int lane = t & 31, warp = t >> 5;
    const int wm = warp >> 2, wn = warp & 3;
    const int grp = lane >> 3, rr = lane & 7;

    uint32_t aAddr[4], bAddr[2];
#pragma unroll
    for (int mi = 0; mi < 4; mi++)
        aAddr[mi] = sbase + ((wm * 64 + mi * 16 + (grp & 1) * 8 + rr) * 40
                             + (grp >> 1) * 8) * 2;
#pragma unroll
    for (int pi = 0; pi < 2; pi++)
        bAddr[pi] = sbase + OFF_BH + (((grp & 1) * 8 + rr) * 136
                             + wn * 32 + pi * 16 + (grp >> 1) * 8) * 2;

    float d[4][4][4];
#pragma unroll
    for (int mi = 0; mi < 4; mi++)
#pragma unroll
        for (int ni = 0; ni < 4; ni++)
#pragma unroll
            for (int k = 0; k < 4; k++) d[mi][ni][k] = 0.f;

    const int nk = K / 32;

#define LOAD_SLAB(st, kt) do {                                                  \
    const uint32_t _d = (st) * STAGE_B;                                         \
    const int _k = (kt) * 32;                                                   \
    CP16(aD + _d, aS + _k);                                                     \
    CP16(aD + _d + 64 * 40 * 2, aS + (size_t)64 * K + _k);                      \
    CP16(bD + _d, bSh + (size_t)_k * ldb);                                      \
    CP16(bD + _d + 16 * 136 * 2, bSh + (size_t)(_k + 16) * ldb);                \
    CP16(bD + _d + B_HALF_B, bSl + (size_t)_k * ldb);                           \
    CP16(bD + _d + B_HALF_B + 16 * 136 * 2, bSl + (size_t)(_k + 16) * ldb);     \
} while (0)

#define FRAGS_MMA(sd, koff_a, koff_b) do {                                      \
    uint32_t a_f[4][4], b_h[4][2], b_l[4][2];                                   \
    _Pragma("unroll")                                                           \
    for (int mi = 0; mi < 4; mi++)                                              \
        ldsm4(a_f[mi][0], a_f[mi][1], a_f[mi][2], a_f[mi][3],                   \
              aAddr[mi] + (sd) + (koff_a));                                     \
    _Pragma("unroll")                                                           \
    for (int pi = 0; pi < 2; pi++) {                                            \
        ldsm4t(b_h[2*pi][0], b_h[2*pi][1], b_h[2*pi+1][0], b_h[2*pi+1][1],      \
               bAddr[pi] + (sd) + (koff_b));                                    \
        ldsm4t(b_l[2*pi][0], b_l[2*pi][1], b_l[2*pi+1][0], b_l[2*pi+1][1],      \
               bAddr[pi] + (sd) + (koff_b) + B_HALF_B);                         \
    }                                                                           \
    _Pragma("unroll")                                                           \
    for (int mi = 0; mi < 4; mi++)                                              \
        _Pragma("unroll")                                                       \
        for (int ni = 0; ni < 4; ni++) {                                        \
            mma16816h(d[mi][ni], a_f[mi], b_h[ni]);                             \
            mma16816h(d[mi][ni], a_f[mi], b_l[ni]);                             \
        }                                                                       \
} while (0)

    LOAD_SLAB(0, 0); CP_COMMIT();
    LOAD_SLAB(1, 1); CP_COMMIT();
    CP_WAIT1();
    __syncthreads();

    for (int kt = 0; kt < nk; kt++) {
        const uint32_t sd = (uint32_t)(kt % 3) * STAGE_B;
        if (kt + 2 < nk) LOAD_SLAB((kt + 2) % 3, kt + 2);
        CP_COMMIT();
        FRAGS_MMA(sd, 0, 0);
        FRAGS_MMA(sd, 32, 16 * 136 * 2);
        if (kt + 1 < nk) {
            CP_WAIT1();
            __syncthreads();
        }
    }

    const int r0 = rowBase + wm * 64 + (lane >> 2);
    const int c0 = colBase + wn * 32 + (lane & 3) * 2;
#pragma unroll
    for (int mi = 0; mi < 4; mi++)
#pragma unroll
        for (int ni = 0; ni < 4; ni++) {
            int col = c0 + ni * 8;
            if (col < N) {
                float2 v0 = make_float2(d[mi][ni][0], d[mi][ni][1]);
                float2 v1 = make_float2(d[mi][ni][2], d[mi][ni][3]);
                *(float2*)&C[(size_t)(r0 + mi * 16) * ldc + col] = v0;
                *(float2*)&C[(size_t)(r0 + mi * 16 + 8) * ldc + col] = v1;
            }
        }
#undef LOAD_SLAB
#undef FRAGS_MMA
}

// ---------------- fused Y = (CB.L)X + exp(acs) C Sinit (bf16 3-term) --------
#define YF_WH    0
#define YF_WL    36864               // 256*72*2
#define YF_XH    73728
#define YF_XL    82944               // + 64*72*2
#define YF_ACS   92160
#define YF_DT    93184
#define YF_SMEM  94208

__global__ __launch_bounds__(256, 2) void yfused_kernel()
{
    extern __shared__ char ysm[];
    __nv_bfloat16* Wh = (__nv_bfloat16*)(ysm + YF_WH);
    __nv_bfloat16* Wl = (__nv_bfloat16*)(ysm + YF_WL);
    __nv_bfloat16* Xh = (__nv_bfloat16*)(ysm + YF_XH);
    __nv_bfloat16* Xl = (__nv_bfloat16*)(ysm + YF_XL);
    float* sacs = (float*)(ysm + YF_ACS);
    float* sdt  = (float*)(ysm + YF_DT);

    const int bc = blockIdx.x, h = blockIdx.y;
    const int b = bc >> 4, c = bc & 15;
    const int t = threadIdx.x;
    const size_t rowB = (size_t)b * SEQLEN + c * CHUNK;

    sacs[t] = g_acs[((size_t)bc * NHEADS + h) * CHUNK + t];
    sdt[t]  = g_dt[(rowB + t) * NHEADS + h];
    __syncthreads();
    const float acs_l = sacs[t];

    const int lane = t & 31, warp = t >> 5;
    const int grp = lane >> 3, rr = lane & 7;
    const uint32_t whB = s2u(Wh), wlB = s2u(Wl), xhB = s2u(Xh), xlB = s2u(Xl);

    uint32_t aOff[2], bOff[4];
#pragma unroll
    for (int mi = 0; mi < 2; mi++)
        aOff[mi] = ((warp * 32 + mi * 16 + (grp & 1) * 8 + rr) * 72
                    + (grp >> 1) * 8) * 2;
#pragma unroll
    for (int pi = 0; pi < 4; pi++)
        bOff[pi] = (((grp & 1) * 8 + rr) * 72 + pi * 16 + (grp >> 1) * 8) * 2;

    float d[2][8][4];
#pragma unroll
    for (int mi = 0; mi < 2; mi++)
#pragma unroll
        for (int ni = 0; ni < 8; ni++)
#pragma unroll
            for (int k = 0; k < 4; k++) d[mi][ni][k] = 0.f;

#define YF_MMA() do {                                                           \
    _Pragma("unroll")                                                           \
    for (int k = 0; k < 4; k++) {                                               \
        const uint32_t ka = k * 32;                                             \
        const uint32_t kb = k * 16 * 144;                                       \
        uint32_t a_h[2][4], a_l[2][4];                                          \
        _Pragma("unroll")                                                       \
        for (int mi = 0; mi < 2; mi++) {                                        \
            ldsm4(a_h[mi][0], a_h[mi][1], a_h[mi][2], a_h[mi][3],               \
                  whB + aOff[mi] + ka);                                         \
            ldsm4(a_l[mi][0], a_l[mi][1], a_l[mi][2], a_l[mi][3],               \
                  wlB + aOff[mi] + ka);                                         \
        }                                                                       \
        _Pragma("unroll")                                                       \
        for (int pi = 0; pi < 4; pi++) {                                        \
            uint32_t bh[2][2], bl[2][2];                                        \
            ldsm4t(bh[0][0], bh[0][1], bh[1][0], bh[1][1],                      \
                   xhB + bOff[pi] + kb);                                        \
            ldsm4t(bl[0][0], bl[0][1], bl[1][0], bl[1][1],                      \
                   xlB + bOff[pi] + kb);                                        \
            _Pragma("unroll")                                                   \
            for (int mi = 0; mi < 2; mi++)                                      \
                _Pragma("unroll")                                               \
                for (int q = 0; q < 2; q++) {                                   \
                    mma16816(d[mi][2*pi+q], a_h[mi], bh[q]);                    \
                    mma16816(d[mi][2*pi+q], a_h[mi], bl[q]);                    \
                    mma16816(d[mi][2*pi+q], a_l[mi], bh[q]);                    \
                }                                                               \
        }                                                                       \
    }                                                                           \
} while (0)

    // ---- part 1: Y_diag, 4 s-tiles of 64 ----
    const float* CBrow = g_CB + ((size_t)bc * CHUNK + t) * CHUNK;
    for (int st = 0; st < 4; st++) {
        const int s0 = st * 64;
        __nv_bfloat162* wh2 = (__nv_bfloat162*)(Wh + t * 72);
        __nv_bfloat162* wl2 = (__nv_bfloat162*)(Wl + t * 72);
#pragma unroll
        for (int j = 0; j < 64; j += 4) {
            float4 cb4 = *(const float4*)(CBrow + s0 + j);
            float w[4];
            const float* cbp = (const float*)&cb4;
#pragma unroll
            for (int e = 0; e < 4; e++) {
                int s = s0 + j + e;
                float arg = fminf(acs_l - sacs[s], 0.f);
                w[e] = (s <= t) ? cbp[e] * __expf(arg) : 0.f;
            }
            __nv_bfloat162 h01, l01, h23, l23;
            split2(w[0], w[1], h01, l01);
            split2(w[2], w[3], h23, l23);
            wh2[(j >> 1) + 0] = h01; wh2[(j >> 1) + 1] = h23;
            wl2[(j >> 1) + 0] = l01; wl2[(j >> 1) + 1] = l23;
        }
        {
            const int r = t >> 2, c16 = (t & 3) * 16;
            const float dts = sdt[s0 + r];
            const float* xr = g_xBC + (rowB + s0 + r) * CONVDIM + h * HEADDIM + c16;
            __nv_bfloat162* xh2 = (__nv_bfloat162*)(Xh + r * 72 + c16);
            __nv_bfloat162* xl2 = (__nv_bfloat162*)(Xl + r * 72 + c16);
#pragma unroll
            for (int j = 0; j < 16; j += 4) {
                float4 v = *(const float4*)(xr + j);
                __nv_bfloat162 h01, l01, h23, l23;
                split2(v.x * dts, v.y * dts, h01, l01);
                split2(v.z * dts, v.w * dts, h23, l23);
                xh2[(j >> 1) + 0] = h01; xh2[(j >> 1) + 1] = h23;
                xl2[(j >> 1) + 0] = l01; xl2[(j >> 1) + 1] = l23;
            }
        }
        __syncthreads();
        YF_MMA();
        __syncthreads();
    }

    // ---- part 2: Y_off, 2 n-tiles of 64 ----
    const float el = __expf(acs_l);
    const float* Crow = g_xBC + (rowB + t) * CONVDIM + DINNER + DSTATE;
    const float* S0p = g_Sinit + ((size_t)bc * NHEADS + h) * (HEADDIM * DSTATE);
    for (int nt = 0; nt < 2; nt++) {
        const int n0 = nt * 64;
        __nv_bfloat162* wh2 = (__nv_bfloat162*)(Wh + t * 72);
        __nv_bfloat162* wl2 = (__nv_bfloat162*)(Wl + t * 72);
#pragma unroll
        for (int j = 0; j < 64; j += 4) {
            float4 c4 = *(const float4*)(Crow + n0 + j);
            __nv_bfloat162 h01, l01, h23, l23;
            split2(c4.x * el, c4.y * el, h01, l01);
            split2(c4.z * el, c4.w * el, h23, l23);
            wh2[(j >> 1) + 0] = h01; wh2[(j >> 1) + 1] = h23;
            wl2[(j >> 1) + 0] = l01; wl2[(j >> 1) + 1] = l23;
        }
        {
            const int p = t >> 2, nb = (t & 3) * 16;
            const float* sp = S0p + (size_t)p * DSTATE + n0 + nb;
#pragma unroll
            for (int j = 0; j < 16; j++) {
                float v = sp[j];
                __nv_bfloat16 hh = __float2bfloat16(v);
                Xh[(nb + j) * 72 + p] = hh;
                Xl[(nb + j) * 72 + p] = __float2bfloat16(v - __bfloat162float(hh));
            }
        }
        __syncthreads();
        YF_MMA();
        __syncthreads();
    }
#undef YF_MMA

    const int c0 = (lane & 3) * 2;
#pragma unroll
    for (int mi = 0; mi < 2; mi++) {
        const size_t gr0 = (rowB + warp * 32 + (lane >> 2) + mi * 16) * DINNER + h * HEADDIM;
#pragma unroll
        for (int ni = 0; ni < 8; ni++) {
            int col = c0 + ni * 8;
            *(float2*)&g_Y[gr0 + col] = make_float2(d[mi][ni][0], d[mi][ni][1]);
            *(float2*)&g_Y[gr0 + 8 * DINNER + col] = make_float2(d[mi][ni][2], d[mi][ni][3]);
        }
    }
}

// ---------------- convert kernels -------------------------------------------
__global__ void tofp16_kernel(const float* __restrict__ x, __half* __restrict__ o, size_t n)
{
    size_t i = (size_t)blockIdx.x * blockDim.x + threadIdx.x;
    if (i >= n) return;
    o[i] = __float2half(x[i]);
}

__global__ void splitf16_kernel(const float* __restrict__ x, __half* __restrict__ hi,
                                __half* __restrict__ lo, size_t n)
{
    size_t i = (size_t)blockIdx.x * blockDim.x + threadIdx.x;
    if (i >= n) return;
    float v = x[i];
    __half h = __float2half(v);
    hi[i] = h;
    lo[i] = __float2half(v - __half2float(h));
}

__global__ void splitf16_pad_kernel(const float* __restrict__ x, __half* __restrict__ hi,
                                    __half* __restrict__ lo, int K, int N, int Np)
{
    size_t i = (size_t)blockIdx.x * blockDim.x + threadIdx.x;
    if (i >= (size_t)K * Np) return;
    int r = (int)(i / Np), c = (int)(i % Np);
    float v = (c < N) ? x[(size_t)r * N + c] : 0.f;
    __half h = __float2half(v);
    hi[i] = h;
    lo[i] = __float2half(v - __half2float(h));
}

// ---------------- causal depthwise conv1d (width 4) + SiLU, float4 ----------
__global__ void conv_silu_kernel(const float* __restrict__ conv_w,
                                 const float* __restrict__ conv_b)
{
    int idx = blockIdx.x * blockDim.x + threadIdx.x;
    if (idx >= ROWS * (CONVDIM / 4)) return;
    int c4  = idx % (CONVDIM / 4);
    int row = idx / (CONVDIM / 4);
    int c   = c4 * 4;
    int l   = row & (SEQLEN - 1);
    const float* base = g_zxbcdt + (size_t)row * DPROJ + DINNER + c;
    float4 acc = *(const float4*)(conv_b + c);
#pragma unroll
    for (int j = 0; j < DCONV; j++) {
        int ls = l - (DCONV - 1) + j;
        if (ls >= 0) {
            float4 v = *(const float4*)(base + (long)(j - (DCONV - 1)) * DPROJ);
            acc.x += v.x * conv_w[(c + 0) * DCONV + j];
            acc.y += v.y * conv_w[(c + 1) * DCONV + j];
            acc.z += v.z * conv_w[(c + 2) * DCONV + j];
            acc.w += v.w * conv_w[(c + 3) * DCONV + j];
        }
    }
    float4 o;
    o.x = acc.x / (1.f + __expf(-acc.x));
    o.y = acc.y / (1.f + __expf(-acc.y));
    o.z = acc.z / (1.f + __expf(-acc.z));
    o.w = acc.w / (1.f + __expf(-acc.w));
    *(float4*)(g_xBC + (size_t)row * CONVDIM + c) = o;
}

// ---------------- dt = softplus(dt_raw + dt_bias) --------------------------
__global__ void dt_kernel(const float* __restrict__ dt_bias)
{
    int idx = blockIdx.x * blockDim.x + threadIdx.x;
    if (idx >= ROWS * NHEADS) return;
    int h   = idx & (NHEADS - 1);
    int row = idx >> 5;
    float v = g_zxbcdt[(size_t)row * DPROJ + DT_OFF + h] + dt_bias[h];
    g_dt[idx] = (v > 20.f) ? v : log1pf(expf(v));
}

// ---------------- per-chunk inclusive cumsum of a = A*dt -------------------
__global__ void ascan_kernel(const float* __restrict__ A_log)
{
    int bc = blockIdx.x;
    int h  = blockIdx.y;
    int t  = threadIdx.x;
    int b = bc >> 4, c = bc & 15;
    __shared__ float sa[CHUNK];
    int row = b * SEQLEN + c * CHUNK + t;
    float A = -expf(A_log[h]);
    sa[t] = A * g_dt[row * NHEADS + h];
    __syncthreads();
    for (int off = 1; off < CHUNK; off <<= 1) {
        float v = (t >= off) ? sa[t - off] : 0.f;
        __syncthreads();
        sa[t] += v;
        __syncthreads();
    }
    g_acs[(bc * NHEADS + h) * CHUNK + t] = sa[t];
    if (t == CHUNK - 1) g_asum[bc * NHEADS + h] = sa[t];
}

// ---------------- CB[l,s] = sum_n C[l,n] * B[s,n]  (head-independent) ------
__global__ __launch_bounds__(256) void cb_kernel()
{
    int bc = blockIdx.x;
    int lt = blockIdx.y;
    int st = blockIdx.z;
    if (st > lt) return;
    int b = bc >> 4, c = bc & 15;
    int t = threadIdx.x;
    int ty = t >> 4, tx = t & 15;
    __shared__ float Ct[32][68];
    __shared__ float Bt[32][68];
    size_t rowB = (size_t)b * SEQLEN + c * CHUNK;
    float acc[4][4];
#pragma unroll
    for (int i = 0; i < 4; i++)
#pragma unroll
        for (int j = 0; j < 4; j++) acc[i][j] = 0.f;

    for (int n0 = 0; n0 < DSTATE; n0 += 32) {
        for (int v = t; v < 512; v += 256) {
            int r = v >> 3, n4 = v & 7;
            float4 cv = *(const float4*)(g_xBC + (rowB + lt*64 + r) * CONVDIM
                                         + (DINNER + DSTATE) + n0 + n4*4);
            Ct[n4*4+0][r]=cv.x; Ct[n4*4+1][r]=cv.y; Ct[n4*4+2][r]=cv.z; Ct[n4*4+3][r]=cv.w;
            float4 bvv = *(const float4*)(g_xBC + (rowB + st*64 + r) * CONVDIM
                                          + DINNER + n0 + n4*4);
            Bt[n4*4+0][r]=bvv.x; Bt[n4*4+1][r]=bvv.y; Bt[n4*4+2][r]=bvv.z; Bt[n4*4+3][r]=bvv.w;
        }
        __syncthreads();
#pragma unroll
        for (int n = 0; n < 32; n++) {
            float4 ca = *(const float4*)&Ct[n][ty*4];
            float4 bb = *(const float4*)&Bt[n][tx*4];
            float ra[4] = {ca.x, ca.y, ca.z, ca.w};
            float rb[4] = {bb.x, bb.y, bb.z, bb.w};
#pragma unroll
            for (int i = 0; i < 4; i++)
#pragma unroll
                for (int j = 0; j < 4; j++) acc[i][j] += ra[i] * rb[j];
        }
        __syncthreads();
    }
#pragma unroll
    for (int i = 0; i < 4; i++) {
        int l = lt*64 + ty*4 + i;
        float4 o = make_float4(acc[i][0], acc[i][1], acc[i][2], acc[i][3]);
        *(float4*)(g_CB + ((size_t)bc * CHUNK + l) * CHUNK + st*64 + tx*4) = o;
    }
}

// ---------------- per-chunk state S[p,n] -----------------------------------
__global__ __launch_bounds__(256, 1) void state_kernel()
{
    int bc = blockIdx.x, h = blockIdx.y;
    int b = bc >> 4, c = bc & 15;
    int t = threadIdx.x;
    __shared__ float Bs[64][132];
    __shared__ float warr[64];
    size_t rowB = (size_t)b * SEQLEN + c * CHUNK;
    float asum = g_asum[bc * NHEADS + h];
    int p  = t >> 2;
    int nq = (t & 3) * 4;
    const float* xptr = g_xBC + rowB * CONVDIM + h * HEADDIM + p;
    float4 acc4[8];
#pragma unroll
    for (int i = 0; i < 8; i++) acc4[i] = make_float4(0.f, 0.f, 0.f, 0.f);

    for (int stile = 0; stile < CHUNK; stile += 64) {
        {
            int r = t >> 2, qq = (t & 3) * 32;
            const float4* src = (const float4*)(g_xBC + (rowB + stile + r) * CONVDIM
                                                + DINNER + qq);
#pragma unroll
            for (int i = 0; i < 8; i++)
                *(float4*)&Bs[r][qq + i*4] = src[i];
        }
        if (t < 64) {
            int gl = stile + t;
            warr[t] = g_dt[(rowB + gl) * NHEADS + h] *
                      __expf(asum - g_acs[((size_t)bc * NHEADS + h) * CHUNK + gl]);
        }
        __syncthreads();
        for (int s = 0; s < 64; s++) {
            float xv = __ldg(xptr + (size_t)(stile + s) * CONVDIM) * warr[s];
#pragma unroll
            for (int i = 0; i < 8; i++) {
                float4 bv = *(const float4*)&Bs[s][nq + 16*i];
                acc4[i].x += xv * bv.x;
                acc4[i].y += xv * bv.y;
                acc4[i].z += xv * bv.z;
                acc4[i].w += xv * bv.w;
            }
        }
        __syncthreads();
    }
    float* Sout = g_S + (((size_t)bc * NHEADS + h) * HEADDIM + p) * DSTATE;
#pragma unroll
    for (int i = 0; i < 8; i++)
        *(float4*)(Sout + nq + 16*i) = acc4[i];
}

// ---------------- sequential inter-chunk recurrence ------------------------
__global__ void chunkrec_kernel()
{
    int b = blockIdx.x, h = blockIdx.y;
    int t = threadIdx.x;
    float cur[32];
#pragma unroll
    for (int k = 0; k < 32; k++) cur[k] = 0.f;
    for (int c = 0; c < NCHUNK; c++) {
        int bc = b * NCHUNK + c;
        size_t base = ((size_t)bc * NHEADS + h) * (HEADDIM * DSTATE);
        float dd = __expf(g_asum[bc * NHEADS + h]);
#pragma unroll
        for (int k = 0; k < 32; k++) {
            size_t e = base + t + 256 * k;
            g_Sinit[e] = cur[k];
            cur[k] = cur[k] * dd + g_S[e];
        }
    }
}

// ---------------- layernorm + z-gate -> fp16 yg ----------------------------
__global__ __launch_bounds__(256) void normgate_kernel(const float* __restrict__ norm_w)
{
    int row = blockIdx.x;
    int t = threadIdx.x;
    const float* yrow = g_Y + (size_t)row * DINNER;
    const float* zrow = g_zxbcdt + (size_t)row * DPROJ;
    float v[8];
    float s = 0.f;
#pragma unroll
    for (int i = 0; i < 8; i++) { v[i] = yrow[t + 256*i]; s += v[i]; }
    __shared__ float red[256];
    red[t] = s; __syncthreads();
    for (int o = 128; o > 0; o >>= 1) { if (t < o) red[t] += red[t+o]; __syncthreads(); }
    float mu = red[0] * (1.f / DINNER);
    __syncthreads();
    float s2 = 0.f;
#pragma unroll
    for (int i = 0; i < 8; i++) { float dv = v[i] - mu; s2 += dv * dv; }
    red[t] = s2; __syncthreads();
    for (int o = 128; o > 0; o >>= 1) { if (t < o) red[t] += red[t+o]; __syncthreads(); }
    float inv = rsqrtf(red[0] * (1.f / DINNER) + 1e-5f);
    __half* orow = g_yg + (size_t)row * DINNER;
#pragma unroll
    for (int i = 0; i < 8; i++) {
        int idx = t + 256*i;
        float z = zrow[idx];
        float g = z / (1.f + __expf(-z));
        orow[idx] = __float2half((v[i] - mu) * inv * norm_w[idx] * g);
    }
}

// ---------------- launch ---------------------------------------------------
extern "C" void kernel_launch(void* const* d_in, const int* in_sizes, int n_in,
                              void* d_out, int out_size)
{
    const float* u       = (const float*)d_in[0];
    const float* W_in    = (const float*)d_in[1];
    const float* conv_w  = (const float*)d_in[2];
    const float* conv_b  = (const float*)d_in[3];
    const float* dt_bias = (const float*)d_in[4];
    const float* A_log   = (const float*)d_in[5];
    const float* norm_w  = (const float*)d_in[6];
    const float* W_out   = (const float*)d_in[7];
    float* out = (float*)d_out;

    float* p_zx = nullptr;
    __half *p_uf, *p_wih, *p_wil, *p_woh, *p_wol, *p_yg;
    cudaGetSymbolAddress((void**)&p_zx,  g_zxbcdt);
    cudaGetSymbolAddress((void**)&p_uf,  g_uf);
    cudaGetSymbolAddress((void**)&p_wih, g_wih);
    cudaGetSymbolAddress((void**)&p_wil, g_wil);
    cudaGetSymbolAddress((void**)&p_woh, g_woh);
    cudaGetSymbolAddress((void**)&p_wol, g_wol);
    cudaGetSymbolAddress((void**)&p_yg,  g_yg);

    cudaFuncSetAttribute(mma_gemm, cudaFuncAttributeMaxDynamicSharedMemorySize, GEMM_SMEM);
    cudaFuncSetAttribute(yfused_kernel, cudaFuncAttributeMaxDynamicSharedMemorySize, YF_SMEM);

    // 0. fp16 conversions
    {
        size_t n = (size_t)ROWS * DMODEL;
        tofp16_kernel<<<(unsigned)((n + 255) / 256), 256>>>(u, p_uf, n);
    }
    splitf16_pad_kernel<<<(unsigned)(((size_t)DMODEL * NPAD1 + 255) / 256), 256>>>(
        W_in, p_wih, p_wil, DMODEL, DPROJ, NPAD1);
    {
        size_t n = (size_t)DINNER * DMODEL;
        splitf16_kernel<<<(unsigned)((n + 255) / 256), 256>>>(W_out, p_woh, p_wol, n);
    }

    // 1. zxbcdt = u @ W_in  (8192 x 4384 x 1024)
    mma_gemm<<<dim3(NPAD1 / 128, ROWS / 128), 256, GEMM_SMEM>>>(
        p_uf, p_wih, p_wil, p_zx, ROWS, DPROJ, DMODEL, NPAD1, DPROJ);
    // 2. causal conv1d + SiLU (float4)
    conv_silu_kernel<<<(ROWS * (CONVDIM / 4) + 255) / 256, 256>>>(conv_w, conv_b);
    // 3. dt softplus
    dt_kernel<<<(ROWS * NHEADS + 255) / 256, 256>>>(dt_bias);
    // 4. per-chunk cumsum of A*dt
    ascan_kernel<<<dim3(NBC, NHEADS), CHUNK>>>(A_log);
    // 5. head-independent CB gram matrices
    cb_kernel<<<dim3(NBC, 4, 4), 256>>>();
    // 6. per-chunk end states
    state_kernel<<<dim3(NBC, NHEADS), 256>>>();
    // 7. inter-chunk recurrence
    chunkrec_kernel<<<dim3(BATCH, NHEADS), 256>>>();
    // 8. fused Y_diag + Y_off (tensor cores)
    yfused_kernel<<<dim3(NBC, NHEADS), 256, YF_SMEM>>>();
    // 9. layernorm + silu(z) gate -> fp16
    normgate_kernel<<<ROWS, 256>>>(norm_w);
    // 10. out = yg @ W_out  (8192 x 1024 x 2048)
    mma_gemm<<<dim3(DMODEL / 128, ROWS / 128), 256, GEMM_SMEM>>>(
        p_yg, p_woh, p_wol, out, ROWS, DMODEL, DINNER, DMODEL, DMODEL);
}

// round 10
// speedup vs baseline: 1.2307x; 1.2307x over previous
#include <cuda_runtime.h>
#include <cuda_bf16.h>
#include <cuda_fp16.h>
#include <math.h>
#include <stdint.h>

#define BATCH   2
#define SEQLEN  4096
#define DMODEL  1024
#define DINNER  2048
#define HEADDIM 64
#define NHEADS  32
#define DSTATE  128
#define DCONV   4
#define CHUNK   256
#define NCHUNK  (SEQLEN / CHUNK)   // 16
#define NBC     (BATCH * NCHUNK)   // 32
#define DPROJ   4384               // 2*DINNER + 2*DSTATE + NHEADS
#define CONVDIM 2304               // DINNER + 2*DSTATE
#define DT_OFF  4352               // 2*DINNER + 2*DSTATE
#define ROWS    (BATCH * SEQLEN)   // 8192
#define NPAD1   4480               // DPROJ padded to multiple of 128

// ---------------- scratch (device globals; no allocation allowed) ----------
__device__ float g_zxbcdt[(size_t)ROWS * DPROJ];
__device__ float g_xBC[(size_t)ROWS * CONVDIM];
__device__ float g_dt[ROWS * NHEADS];
__device__ float g_acs[NBC * NHEADS * CHUNK];
__device__ float g_asum[NBC * NHEADS];
__device__ float g_CB[(size_t)NBC * CHUNK * CHUNK];
__device__ float g_Y[(size_t)ROWS * DINNER];
__device__ float g_S[(size_t)NBC * NHEADS * HEADDIM * DSTATE];
__device__ float g_Sinit[(size_t)NBC * NHEADS * HEADDIM * DSTATE];

// fp16 GEMM operands: activations single, weights hi/lo split
__device__ __half g_uf[(size_t)ROWS * DMODEL];
__device__ __half g_wih[(size_t)DMODEL * NPAD1];
__device__ __half g_wil[(size_t)DMODEL * NPAD1];
__device__ __half g_woh[(size_t)DINNER * DMODEL];
__device__ __half g_wol[(size_t)DINNER * DMODEL];
__device__ __half g_yg[(size_t)ROWS * DINNER];

// ---------------- helpers ---------------------------------------------------
__device__ __forceinline__ uint32_t s2u(const void* p) {
    return (uint32_t)__cvta_generic_to_shared(p);
}
#define CP16(dst, src) \
    asm volatile("cp.async.cg.shared.global [%0], [%1], 16;\n" :: "r"(dst), "l"(src))
#define CP_COMMIT() asm volatile("cp.async.commit_group;\n")
#define CP_WAIT1()  asm volatile("cp.async.wait_group 1;\n")

__device__ __forceinline__ void ldsm4(uint32_t& r0, uint32_t& r1, uint32_t& r2,
                                      uint32_t& r3, uint32_t addr) {
    asm volatile("ldmatrix.sync.aligned.m8n8.x4.shared.b16 {%0,%1,%2,%3}, [%4];"
                 : "=r"(r0), "=r"(r1), "=r"(r2), "=r"(r3) : "r"(addr));
}
__device__ __forceinline__ void ldsm4t(uint32_t& r0, uint32_t& r1, uint32_t& r2,
                                       uint32_t& r3, uint32_t addr) {
    asm volatile("ldmatrix.sync.aligned.m8n8.x4.trans.shared.b16 {%0,%1,%2,%3}, [%4];"
                 : "=r"(r0), "=r"(r1), "=r"(r2), "=r"(r3) : "r"(addr));
}
// fp16 mma
__device__ __forceinline__ void mma16816h(float* d, const uint32_t* a, const uint32_t* b) {
    asm volatile(
        "mma.sync.aligned.m16n8k16.row.col.f32.f16.f16.f32 "
        "{%0,%1,%2,%3}, {%4,%5,%6,%7}, {%8,%9}, {%0,%1,%2,%3};"
        : "+f"(d[0]), "+f"(d[1]), "+f"(d[2]), "+f"(d[3])
        : "r"(a[0]), "r"(a[1]), "r"(a[2]), "r"(a[3]), "r"(b[0]), "r"(b[1]));
}
// bf16 mma (yfused / state)
__device__ __forceinline__ void mma16816(float* d, const uint32_t* a, const uint32_t* b) {
    asm volatile(
        "mma.sync.aligned.m16n8k16.row.col.f32.bf16.bf16.f32 "
        "{%0,%1,%2,%3}, {%4,%5,%6,%7}, {%8,%9}, {%0,%1,%2,%3};"
        : "+f"(d[0]), "+f"(d[1]), "+f"(d[2]), "+f"(d[3])
        : "r"(a[0]), "r"(a[1]), "r"(a[2]), "r"(a[3]), "r"(b[0]), "r"(b[1]));
}
__device__ __forceinline__ void split2(float a, float b,
                                       __nv_bfloat162& h, __nv_bfloat162& l) {
    __nv_bfloat16 ha = __float2bfloat16(a), hb = __float2bfloat16(b);
    h = __halves2bfloat162(ha, hb);
    l = __halves2bfloat162(__float2bfloat16(a - __bfloat162float(ha)),
                           __float2bfloat16(b - __bfloat162float(hb)));
}

// ---------------- GEMM smem layout (bytes), tile 128x128, BK=32 -------------
// per stage: A[128][40] | Bh[32][136] | Bl[32][136]   (fp16)
#define A_B        10240         // 128*40*2
#define B_HALF_B   8704          // 32*136*2
#define OFF_BH     A_B
#define OFF_BL     (A_B + B_HALF_B)
#define STAGE_B    (A_B + 2 * B_HALF_B)            // 27648
#define NSTAGE     3
#define GEMM_SMEM  (NSTAGE * STAGE_B)              // 82944

// ---------------- fp16 2-term tensor-core GEMM (2 CTAs/SM, 128x128) ---------
__global__ __launch_bounds__(256, 2) void mma_gemm(
    const __half* __restrict__ A,
    const __half* __restrict__ Bh, const __half* __restrict__ Bl,
    float* __restrict__ C, int M, int N, int K, int ldb, int ldc)
{
    extern __shared__ __half smem[];
    const uint32_t sbase = s2u(smem);
    const int rowBase = blockIdx.y * 128;
    const int colBase = blockIdx.x * 128;
    const int t = threadIdx.x;

    const int ar = t >> 2, aq = t & 3;
    const __half* aS = A + (size_t)(rowBase + ar) * K + aq * 8;
    const uint32_t aD = sbase + (ar * 40 + aq * 8) * 2;
    const int br = t >> 4, bq = t & 15;
    const __half* bSh = Bh + (size_t)br * ldb + colBase + bq * 8;
    const __half* bSl = Bl + (size_t)br * ldb + colBase + bq * 8;
    const uint32_t bD = sbase + OFF_BH + (br * 136 + bq * 8) * 2;

    const int lane = t & 31, warp = t >> 5;
    const int wm = warp >> 2, wn = warp & 3;
    const int grp = lane >> 3, rr = lane & 7;

    uint32_t aAddr[4], bAddr[2];
#pragma unroll
    for (int mi = 0; mi < 4; mi++)
        aAddr[mi] = sbase + ((wm * 64 + mi * 16 + (grp & 1) * 8 + rr) * 40
                             + (grp >> 1) * 8) * 2;
#pragma unroll
    for (int pi = 0; pi < 2; pi++)
        bAddr[pi] = sbase + OFF_BH + (((grp & 1) * 8 + rr) * 136
                             + wn * 32 + pi * 16 + (grp >> 1) * 8) * 2;

    float d[4][4][4];
#pragma unroll
    for (int mi = 0; mi < 4; mi++)
#pragma unroll
        for (int ni = 0; ni < 4; ni++)
#pragma unroll
            for (int k = 0; k < 4; k++) d[mi][ni][k] = 0.f;

    const int nk = K / 32;

#define LOAD_SLAB(st, kt) do {                                                  \
    const uint32_t _d = (st) * STAGE_B;                                         \
    const int _k = (kt) * 32;                                                   \
    CP16(aD + _d, aS + _k);                                                     \
    CP16(aD + _d + 64 * 40 * 2, aS + (size_t)64 * K + _k);                      \
    CP16(bD + _d, bSh + (size_t)_k * ldb);                                      \
    CP16(bD + _d + 16 * 136 * 2, bSh + (size_t)(_k + 16) * ldb);                \
    CP16(bD + _d + B_HALF_B, bSl + (size_t)_k * ldb);                           \
    CP16(bD + _d + B_HALF_B + 16 * 136 * 2, bSl + (size_t)(_k + 16) * ldb);     \
} while (0)

#define FRAGS_MMA(sd, koff_a, koff_b) do {                                      \
    uint32_t a_f[4][4], b_h[4][2], b_l[4][2];                                   \
    _Pragma("unroll")                                                           \
    for (int mi = 0; mi < 4; mi++)                                              \
        ldsm4(a_f[mi][0], a_f[mi][1], a_f[mi][2], a_f[mi][3],                   \
              aAddr[mi] + (sd) + (koff_a));                                     \
    _Pragma("unroll")                                                           \
    for (int pi = 0; pi < 2; pi++) {                                            \
        ldsm4t(b_h[2*pi][0], b_h[2*pi][1], b_h[2*pi+1][0], b_h[2*pi+1][1],      \
               bAddr[pi] + (sd) + (koff_b));                                    \
        ldsm4t(b_l[2*pi][0], b_l[2*pi][1], b_l[2*pi+1][0], b_l[2*pi+1][1],      \
               bAddr[pi] + (sd) + (koff_b) + B_HALF_B);                         \
    }                                                                           \
    _Pragma("unroll")                                                           \
    for (int mi = 0; mi < 4; mi++)                                              \
        _Pragma("unroll")                                                       \
        for (int ni = 0; ni < 4; ni++) {                                        \
            mma16816h(d[mi][ni], a_f[mi], b_h[ni]);                             \
            mma16816h(d[mi][ni], a_f[mi], b_l[ni]);                             \
        }                                                                       \
} while (0)

    LOAD_SLAB(0, 0); CP_COMMIT();
    LOAD_SLAB(1, 1); CP_COMMIT();
    CP_WAIT1();
    __syncthreads();

    for (int kt = 0; kt < nk; kt++) {
        const uint32_t sd = (uint32_t)(kt % 3) * STAGE_B;
        if (kt + 2 < nk) LOAD_SLAB((kt + 2) % 3, kt + 2);
        CP_COMMIT();
        FRAGS_MMA(sd, 0, 0);
        FRAGS_MMA(sd, 32, 16 * 136 * 2);
        if (kt + 1 < nk) {
            CP_WAIT1();
            __syncthreads();
        }
    }

    const int r0 = rowBase + wm * 64 + (lane >> 2);
    const int c0 = colBase + wn * 32 + (lane & 3) * 2;
#pragma unroll
    for (int mi = 0; mi < 4; mi++)
#pragma unroll
        for (int ni = 0; ni < 4; ni++) {
            int col = c0 + ni * 8;
            if (col < N) {
                float2 v0 = make_float2(d[mi][ni][0], d[mi][ni][1]);
                float2 v1 = make_float2(d[mi][ni][2], d[mi][ni][3]);
                *(float2*)&C[(size_t)(r0 + mi * 16) * ldc + col] = v0;
                *(float2*)&C[(size_t)(r0 + mi * 16 + 8) * ldc + col] = v1;
            }
        }
#undef LOAD_SLAB
#undef FRAGS_MMA
}

// ---------------- fused Y = (CB.L)X + exp(acs) C Sinit (bf16 3-term) --------
#define YF_WH    0
#define YF_WL    36864               // 256*72*2
#define YF_XH    73728
#define YF_XL    82944               // + 64*72*2
#define YF_ACS   92160
#define YF_DT    93184
#define YF_SMEM  94208

__global__ __launch_bounds__(256, 2) void yfused_kernel()
{
    extern __shared__ char ysm[];
    __nv_bfloat16* Wh = (__nv_bfloat16*)(ysm + YF_WH);
    __nv_bfloat16* Wl = (__nv_bfloat16*)(ysm + YF_WL);
    __nv_bfloat16* Xh = (__nv_bfloat16*)(ysm + YF_XH);
    __nv_bfloat16* Xl = (__nv_bfloat16*)(ysm + YF_XL);
    float* sacs = (float*)(ysm + YF_ACS);
    float* sdt  = (float*)(ysm + YF_DT);

    const int bc = blockIdx.x, h = blockIdx.y;
    const int b = bc >> 4, c = bc & 15;
    const int t = threadIdx.x;
    const size_t rowB = (size_t)b * SEQLEN + c * CHUNK;

    sacs[t] = g_acs[((size_t)bc * NHEADS + h) * CHUNK + t];
    sdt[t]  = g_dt[(rowB + t) * NHEADS + h];
    __syncthreads();
    const float acs_l = sacs[t];

    const int lane = t & 31, warp = t >> 5;
    const int grp = lane >> 3, rr = lane & 7;
    const uint32_t whB = s2u(Wh), wlB = s2u(Wl), xhB = s2u(Xh), xlB = s2u(Xl);

    uint32_t aOff[2], bOff[4];
#pragma unroll
    for (int mi = 0; mi < 2; mi++)
        aOff[mi] = ((warp * 32 + mi * 16 + (grp & 1) * 8 + rr) * 72
                    + (grp >> 1) * 8) * 2;
#pragma unroll
    for (int pi = 0; pi < 4; pi++)
        bOff[pi] = (((grp & 1) * 8 + rr) * 72 + pi * 16 + (grp >> 1) * 8) * 2;

    float d[2][8][4];
#pragma unroll
    for (int mi = 0; mi < 2; mi++)
#pragma unroll
        for (int ni = 0; ni < 8; ni++)
#pragma unroll
            for (int k = 0; k < 4; k++) d[mi][ni][k] = 0.f;

#define YF_MMA() do {                                                           \
    _Pragma("unroll")                                                           \
    for (int k = 0; k < 4; k++) {                                               \
        const uint32_t ka = k * 32;                                             \
        const uint32_t kb = k * 16 * 144;                                       \
        uint32_t a_h[2][4], a_l[2][4];                                          \
        _Pragma("unroll")                                                       \
        for (int mi = 0; mi < 2; mi++) {                                        \
            ldsm4(a_h[mi][0], a_h[mi][1], a_h[mi][2], a_h[mi][3],               \
                  whB + aOff[mi] + ka);                                         \
            ldsm4(a_l[mi][0], a_l[mi][1], a_l[mi][2], a_l[mi][3],               \
                  wlB + aOff[mi] + ka);                                         \
        }                                                                       \
        _Pragma("unroll")                                                       \
        for (int pi = 0; pi < 4; pi++) {                                        \
            uint32_t bh[2][2], bl[2][2];                                        \
            ldsm4t(bh[0][0], bh[0][1], bh[1][0], bh[1][1],                      \
                   xhB + bOff[pi] + kb);                                        \
            ldsm4t(bl[0][0], bl[0][1], bl[1][0], bl[1][1],                      \
                   xlB + bOff[pi] + kb);                                        \
            _Pragma("unroll")                                                   \
            for (int mi = 0; mi < 2; mi++)                                      \
                _Pragma("unroll")                                               \
                for (int q = 0; q < 2; q++) {                                   \
                    mma16816(d[mi][2*pi+q], a_h[mi], bh[q]);                    \
                    mma16816(d[mi][2*pi+q], a_h[mi], bl[q]);                    \
                    mma16816(d[mi][2*pi+q], a_l[mi], bh[q]);                    \
                }                                                               \
        }                                                                       \
    }                                                                           \
} while (0)

    // ---- part 1: Y_diag, 4 s-tiles of 64 ----
    const float* CBrow = g_CB + ((size_t)bc * CHUNK + t) * CHUNK;
    for (int st = 0; st < 4; st++) {
        const int s0 = st * 64;
        __nv_bfloat162* wh2 = (__nv_bfloat162*)(Wh + t * 72);
        __nv_bfloat162* wl2 = (__nv_bfloat162*)(Wl + t * 72);
#pragma unroll
        for (int j = 0; j < 64; j += 4) {
            float4 cb4 = *(const float4*)(CBrow + s0 + j);
            float w[4];
            const float* cbp = (const float*)&cb4;
#pragma unroll
            for (int e = 0; e < 4; e++) {
                int s = s0 + j + e;
                float arg = fminf(acs_l - sacs[s], 0.f);
                w[e] = (s <= t) ? cbp[e] * __expf(arg) : 0.f;
            }
            __nv_bfloat162 h01, l01, h23, l23;
            split2(w[0], w[1], h01, l01);
            split2(w[2], w[3], h23, l23);
            wh2[(j >> 1) + 0] = h01; wh2[(j >> 1) + 1] = h23;
            wl2[(j >> 1) + 0] = l01; wl2[(j >> 1) + 1] = l23;
        }
        {
            const int r = t >> 2, c16 = (t & 3) * 16;
            const float dts = sdt[s0 + r];
            const float* xr = g_xBC + (rowB + s0 + r) * CONVDIM + h * HEADDIM + c16;
            __nv_bfloat162* xh2 = (__nv_bfloat162*)(Xh + r * 72 + c16);
            __nv_bfloat162* xl2 = (__nv_bfloat162*)(Xl + r * 72 + c16);
#pragma unroll
            for (int j = 0; j < 16; j += 4) {
                float4 v = *(const float4*)(xr + j);
                __nv_bfloat162 h01, l01, h23, l23;
                split2(v.x * dts, v.y * dts, h01, l01);
                split2(v.z * dts, v.w * dts, h23, l23);
                xh2[(j >> 1) + 0] = h01; xh2[(j >> 1) + 1] = h23;
                xl2[(j >> 1) + 0] = l01; xl2[(j >> 1) + 1] = l23;
            }
        }
        __syncthreads();
        YF_MMA();
        __syncthreads();
    }

    // ---- part 2: Y_off, 2 n-tiles of 64 ----
    const float el = __expf(acs_l);
    const float* Crow = g_xBC + (rowB + t) * CONVDIM + DINNER + DSTATE;
    const float* S0p = g_Sinit + ((size_t)bc * NHEADS + h) * (HEADDIM * DSTATE);
    for (int nt = 0; nt < 2; nt++) {
        const int n0 = nt * 64;
        __nv_bfloat162* wh2 = (__nv_bfloat162*)(Wh + t * 72);
        __nv_bfloat162* wl2 = (__nv_bfloat162*)(Wl + t * 72);
#pragma unroll
        for (int j = 0; j < 64; j += 4) {
            float4 c4 = *(const float4*)(Crow + n0 + j);
            __nv_bfloat162 h01, l01, h23, l23;
            split2(c4.x * el, c4.y * el, h01, l01);
            split2(c4.z * el, c4.w * el, h23, l23);
            wh2[(j >> 1) + 0] = h01; wh2[(j >> 1) + 1] = h23;
            wl2[(j >> 1) + 0] = l01; wl2[(j >> 1) + 1] = l23;
        }
        {
            const int p = t >> 2, nb = (t & 3) * 16;
            const float* sp = S0p + (size_t)p * DSTATE + n0 + nb;
#pragma unroll
            for (int j = 0; j < 16; j++) {
                float v = sp[j];
                __nv_bfloat16 hh = __float2bfloat16(v);
                Xh[(nb + j) * 72 + p] = hh;
                Xl[(nb + j) * 72 + p] = __float2bfloat16(v - __bfloat162float(hh));
            }
        }
        __syncthreads();
        YF_MMA();
        __syncthreads();
    }
#undef YF_MMA

    const int c0 = (lane & 3) * 2;
#pragma unroll
    for (int mi = 0; mi < 2; mi++) {
        const size_t gr0 = (rowB + warp * 32 + (lane >> 2) + mi * 16) * DINNER + h * HEADDIM;
#pragma unroll
        for (int ni = 0; ni < 8; ni++) {
            int col = c0 + ni * 8;
            *(float2*)&g_Y[gr0 + col] = make_float2(d[mi][ni][0], d[mi][ni][1]);
            *(float2*)&g_Y[gr0 + 8 * DINNER + col] = make_float2(d[mi][ni][2], d[mi][ni][3]);
        }
    }
}

// ---------------- state S[64p x 128n] = x^T . (w.B), bf16 3-term mma --------
#define ST_AH    0
#define ST_AL    9216                // 64*72*2
#define ST_BH    18432
#define ST_BL    35840               // + 64*136*2
#define ST_SMEM  53248

__global__ __launch_bounds__(256, 2) void state_mma_kernel()
{
    extern __shared__ char ssm[];
    __nv_bfloat16* Ah = (__nv_bfloat16*)(ssm + ST_AH);   // [p(64)][s(72 pad)]
    __nv_bfloat16* Al = (__nv_bfloat16*)(ssm + ST_AL);
    __nv_bfloat16* Bh = (__nv_bfloat16*)(ssm + ST_BH);   // [s(64)][n(136 pad)]
    __nv_bfloat16* Bl = (__nv_bfloat16*)(ssm + ST_BL);

    const int bc = blockIdx.x, h = blockIdx.y;
    const int b = bc >> 4, c = bc & 15;
    const int t = threadIdx.x;
    const size_t rowB = (size_t)b * SEQLEN + c * CHUNK;
    const float asum = g_asum[bc * NHEADS + h];
    const float* acsp = g_acs + ((size_t)bc * NHEADS + h) * CHUNK;

    const int lane = t & 31, warp = t >> 5;
    const int wm = warp >> 2, wn = warp & 3;
    const int grp = lane >> 3, rr = lane & 7;
    const uint32_t ahB = s2u(Ah), alB = s2u(Al), bhB = s2u(Bh), blB = s2u(Bl);

    uint32_t aOff[2], bOff[2];
#pragma unroll
    for (int mi = 0; mi < 2; mi++)
        aOff[mi] = ((wm * 32 + mi * 16 + (grp & 1) * 8 + rr) * 72
                    + (grp >> 1) * 8) * 2;
#pragma unroll
    for (int pi = 0; pi < 2; pi++)
        bOff[pi] = (((grp & 1) * 8 + rr) * 136
                    + wn * 32 + pi * 16 + (grp >> 1) * 8) * 2;

    float d[2][4][4];
#pragma unroll
    for (int mi = 0; mi < 2; mi++)
#pragma unroll
        for (int ni = 0; ni < 4; ni++)
#pragma unroll
            for (int k = 0; k < 4; k++) d[mi][ni][k] = 0.f;

    for (int st4 = 0; st4 < 4; st4++) {
        const int s0 = st4 * 64;
        const int r = t >> 2;                 // s-row 0..63 (4 threads each)
        const float w = g_dt[(rowB + s0 + r) * NHEADS + h] *
                        __expf(asum - acsp[s0 + r]);
        // A tile: pure x, transposed [p][s]
        {
            const int q = (t & 3) * 16;       // p base
            const float* xr = g_xBC + (rowB + s0 + r) * CONVDIM + h * HEADDIM + q;
#pragma unroll
            for (int j = 0; j < 16; j += 4) {
                float4 v = *(const float4*)(xr + j);
                float vals[4] = {v.x, v.y, v.z, v.w};
#pragma unroll
                for (int e = 0; e < 4; e++) {
                    __nv_bfloat16 hh = __float2bfloat16(vals[e]);
                    Ah[(q + j + e) * 72 + r] = hh;
                    Al[(q + j + e) * 72 + r] =
                        __float2bfloat16(vals[e] - __bfloat162float(hh));
                }
            }
        }
        // B tile: (w . B) natural [s][n]
        {
            const int nq = (t & 3) * 32;
            const float* brp = g_xBC + (rowB + s0 + r) * CONVDIM + DINNER + nq;
            __nv_bfloat162* bh2 = (__nv_bfloat162*)(Bh + r * 136 + nq);
            __nv_bfloat162* bl2 = (__nv_bfloat162*)(Bl + r * 136 + nq);
#pragma unroll
            for (int j = 0; j < 32; j += 4) {
                float4 v = *(const float4*)(brp + j);
                __nv_bfloat162 h01, l01, h23, l23;
                split2(v.x * w, v.y * w, h01, l01);
                split2(v.z * w, v.w * w, h23, l23);
                bh2[(j >> 1) + 0] = h01; bh2[(j >> 1) + 1] = h23;
                bl2[(j >> 1) + 0] = l01; bl2[(j >> 1) + 1] = l23;
            }
        }
        __syncthreads();
#pragma unroll
        for (int k = 0; k < 4; k++) {
            const uint32_t ka = k * 32;             // 16 halfs
            const uint32_t kb = (uint32_t)k * 16 * 136 * 2;
            uint32_t a_h[2][4], a_l[2][4], bhf[4][2], blf[4][2];
#pragma unroll
            for (int mi = 0; mi < 2; mi++) {
                ldsm4(a_h[mi][0], a_h[mi][1], a_h[mi][2], a_h[mi][3],
                      ahB + aOff[mi] + ka);
                ldsm4(a_l[mi][0], a_l[mi][1], a_l[mi][2], a_l[mi][3],
                      alB + aOff[mi] + ka);
            }
#pragma unroll
            for (int pi = 0; pi < 2; pi++) {
                ldsm4t(bhf[2*pi][0], bhf[2*pi][1], bhf[2*pi+1][0], bhf[2*pi+1][1],
                       bhB + bOff[pi] + kb);
                ldsm4t(blf[2*pi][0], blf[2*pi][1], blf[2*pi+1][0], blf[2*pi+1][1],
                       blB + bOff[pi] + kb);
            }
#pragma unroll
            for (int mi = 0; mi < 2; mi++)
#pragma unroll
                for (int ni = 0; ni < 4; ni++) {
                    mma16816(d[mi][ni], a_h[mi], bhf[ni]);
                    mma16816(d[mi][ni], a_h[mi], blf[ni]);
                    mma16816(d[mi][ni], a_l[mi], bhf[ni]);
                }
        }
        __syncthreads();
    }

    float* Sout = g_S + ((size_t)bc * NHEADS + h) * (HEADDIM * DSTATE);
    const int p0 = wm * 32 + (lane >> 2);
    const int n0 = wn * 32 + (lane & 3) * 2;
#pragma unroll
    for (int mi = 0; mi < 2; mi++)
#pragma unroll
        for (int ni = 0; ni < 4; ni++) {
            int col = n0 + ni * 8;
            *(float2*)&Sout[(size_t)(p0 + mi * 16) * DSTATE + col] =
                make_float2(d[mi][ni][0], d[mi][ni][1]);
            *(float2*)&Sout[(size_t)(p0 + mi * 16 + 8) * DSTATE + col] =
                make_float2(d[mi][ni][2], d[mi][ni][3]);
        }
}

// ---------------- convert kernels -------------------------------------------
__global__ void tofp16_kernel(const float* __restrict__ x, __half* __restrict__ o, size_t n)
{
    size_t i = (size_t)blockIdx.x * blockDim.x + threadIdx.x;
    if (i >= n) return;
    o[i] = __float2half(x[i]);
}

__global__ void splitf16_kernel(const float* __restrict__ x, __half* __restrict__ hi,
                                __half* __restrict__ lo, size_t n)
{
    size_t i = (size_t)blockIdx.x * blockDim.x + threadIdx.x;
    if (i >= n) return;
    float v = x[i];
    __half h = __float2half(v);
    hi[i] = h;
    lo[i] = __float2half(v - __half2float(h));
}

__global__ void splitf16_pad_kernel(const float* __restrict__ x, __half* __restrict__ hi,
                                    __half* __restrict__ lo, int K, int N, int Np)
{
    size_t i = (size_t)blockIdx.x * blockDim.x + threadIdx.x;
    if (i >= (size_t)K * Np) return;
    int r = (int)(i / Np), c = (int)(i % Np);
    float v = (c < N) ? x[(size_t)r * N + c] : 0.f;
    __half h = __float2half(v);
    hi[i] = h;
    lo[i] = __float2half(v - __half2float(h));
}

// ---------------- causal depthwise conv1d (width 4) + SiLU -----------------
__global__ void conv_silu_kernel(const float* __restrict__ conv_w,
                                 const float* __restrict__ conv_b)
{
    int idx = blockIdx.x * blockDim.x + threadIdx.x;
    if (idx >= ROWS * CONVDIM) return;
    int c   = idx % CONVDIM;
    int row = idx / CONVDIM;
    int l   = row & (SEQLEN - 1);
    const float* base = g_zxbcdt + (size_t)row * DPROJ + DINNER + c;
    float acc = conv_b[c];
#pragma unroll
    for (int j = 0; j < DCONV; j++) {
        int ls = l - (DCONV - 1) + j;
        if (ls >= 0) acc += base[(long)(j - (DCONV - 1)) * DPROJ] * conv_w[c * DCONV + j];
    }
    g_xBC[(size_t)row * CONVDIM + c] = acc / (1.f + __expf(-acc));
}

// ---------------- dt = softplus(dt_raw + dt_bias) --------------------------
__global__ void dt_kernel(const float* __restrict__ dt_bias)
{
    int idx = blockIdx.x * blockDim.x + threadIdx.x;
    if (idx >= ROWS * NHEADS) return;
    int h   = idx & (NHEADS - 1);
    int row = idx >> 5;
    float v = g_zxbcdt[(size_t)row * DPROJ + DT_OFF + h] + dt_bias[h];
    g_dt[idx] = (v > 20.f) ? v : log1pf(expf(v));
}

// ---------------- per-chunk inclusive cumsum of a = A*dt -------------------
__global__ void ascan_kernel(const float* __restrict__ A_log)
{
    int bc = blockIdx.x;
    int h  = blockIdx.y;
    int t  = threadIdx.x;
    int b = bc >> 4, c = bc & 15;
    __shared__ float sa[CHUNK];
    int row = b * SEQLEN + c * CHUNK + t;
    float A = -expf(A_log[h]);
    sa[t] = A * g_dt[row * NHEADS + h];
    __syncthreads();
    for (int off = 1; off < CHUNK; off <<= 1) {
        float v = (t >= off) ? sa[t - off] : 0.f;
        __syncthreads();
        sa[t] += v;
        __syncthreads();
    }
    g_acs[(bc * NHEADS + h) * CHUNK + t] = sa[t];
    if (t == CHUNK - 1) g_asum[bc * NHEADS + h] = sa[t];
}

// ---------------- CB[l,s] = sum_n C[l,n] * B[s,n]  (head-independent) ------
__global__ __launch_bounds__(256) void cb_kernel()
{
    int bc = blockIdx.x;
    int lt = blockIdx.y;
    int st = blockIdx.z;
    if (st > lt) return;
    int b = bc >> 4, c = bc & 15;
    int t = threadIdx.x;
    int ty = t >> 4, tx = t & 15;
    __shared__ float Ct[32][68];
    __shared__ float Bt[32][68];
    size_t rowB = (size_t)b * SEQLEN + c * CHUNK;
    float acc[4][4];
#pragma unroll
    for (int i = 0; i < 4; i++)
#pragma unroll
        for (int j = 0; j < 4; j++) acc[i][j] = 0.f;

    for (int n0 = 0; n0 < DSTATE; n0 += 32) {
        for (int v = t; v < 512; v += 256) {
            int r = v >> 3, n4 = v & 7;
            float4 cv = *(const float4*)(g_xBC + (rowB + lt*64 + r) * CONVDIM
                                         + (DINNER + DSTATE) + n0 + n4*4);
            Ct[n4*4+0][r]=cv.x; Ct[n4*4+1][r]=cv.y; Ct[n4*4+2][r]=cv.z; Ct[n4*4+3][r]=cv.w;
            float4 bvv = *(const float4*)(g_xBC + (rowB + st*64 + r) * CONVDIM
                                          + DINNER + n0 + n4*4);
            Bt[n4*4+0][r]=bvv.x; Bt[n4*4+1][r]=bvv.y; Bt[n4*4+2][r]=bvv.z; Bt[n4*4+3][r]=bvv.w;
        }
        __syncthreads();
#pragma unroll
        for (int n = 0; n < 32; n++) {
            float4 ca = *(const float4*)&Ct[n][ty*4];
            float4 bb = *(const float4*)&Bt[n][tx*4];
            float ra[4] = {ca.x, ca.y, ca.z, ca.w};
            float rb[4] = {bb.x, bb.y, bb.z, bb.w};
#pragma unroll
            for (int i = 0; i < 4; i++)
#pragma unroll
                for (int j = 0; j < 4; j++) acc[i][j] += ra[i] * rb[j];
        }
        __syncthreads();
    }
#pragma unroll
    for (int i = 0; i < 4; i++) {
        int l = lt*64 + ty*4 + i;
        float4 o = make_float4(acc[i][0], acc[i][1], acc[i][2], acc[i][3]);
        *(float4*)(g_CB + ((size_t)bc * CHUNK + l) * CHUNK + st*64 + tx*4) = o;
    }
}

// ---------------- sequential inter-chunk recurrence ------------------------
__global__ void chunkrec_kernel()
{
    int b = blockIdx.x, h = blockIdx.y;
    int t = threadIdx.x;
    float cur[32];
#pragma unroll
    for (int k = 0; k < 32; k++) cur[k] = 0.f;
    for (int c = 0; c < NCHUNK; c++) {
        int bc = b * NCHUNK + c;
        size_t base = ((size_t)bc * NHEADS + h) * (HEADDIM * DSTATE);
        float dd = __expf(g_asum[bc * NHEADS + h]);
#pragma unroll
        for (int k = 0; k < 32; k++) {
            size_t e = base + t + 256 * k;
            g_Sinit[e] = cur[k];
            cur[k] = cur[k] * dd + g_S[e];
        }
    }
}

// ---------------- layernorm + z-gate -> fp16 yg ----------------------------
__global__ __launch_bounds__(256) void normgate_kernel(const float* __restrict__ norm_w)
{
    int row = blockIdx.x;
    int t = threadIdx.x;
    const float* yrow = g_Y + (size_t)row * DINNER;
    const float* zrow = g_zxbcdt + (size_t)row * DPROJ;
    float v[8];
    float s = 0.f;
#pragma unroll
    for (int i = 0; i < 8; i++) { v[i] = yrow[t + 256*i]; s += v[i]; }
    __shared__ float red[256];
    red[t] = s; __syncthreads();
    for (int o = 128; o > 0; o >>= 1) { if (t < o) red[t] += red[t+o]; __syncthreads(); }
    float mu = red[0] * (1.f / DINNER);
    __syncthreads();
    float s2 = 0.f;
#pragma unroll
    for (int i = 0; i < 8; i++) { float dv = v[i] - mu; s2 += dv * dv; }
    red[t] = s2; __syncthreads();
    for (int o = 128; o > 0; o >>= 1) { if (t < o) red[t] += red[t+o]; __syncthreads(); }
    float inv = rsqrtf(red[0] * (1.f / DINNER) + 1e-5f);
    __half* orow = g_yg + (size_t)row * DINNER;
#pragma unroll
    for (int i = 0; i < 8; i++) {
        int idx = t + 256*i;
        float z = zrow[idx];
        float g = z / (1.f + __expf(-z));
        orow[idx] = __float2half((v[i] - mu) * inv * norm_w[idx] * g);
    }
}

// ---------------- launch ---------------------------------------------------
extern "C" void kernel_launch(void* const* d_in, const int* in_sizes, int n_in,
                              void* d_out, int out_size)
{
    const float* u       = (const float*)d_in[0];
    const float* W_in    = (const float*)d_in[1];
    const float* conv_w  = (const float*)d_in[2];
    const float* conv_b  = (const float*)d_in[3];
    const float* dt_bias = (const float*)d_in[4];
    const float* A_log   = (const float*)d_in[5];
    const float* norm_w  = (const float*)d_in[6];
    const float* W_out   = (const float*)d_in[7];
    float* out = (float*)d_out;

    float* p_zx = nullptr;
    __half *p_uf, *p_wih, *p_wil, *p_woh, *p_wol, *p_yg;
    cudaGetSymbolAddress((void**)&p_zx,  g_zxbcdt);
    cudaGetSymbolAddress((void**)&p_uf,  g_uf);
    cudaGetSymbolAddress((void**)&p_wih, g_wih);
    cudaGetSymbolAddress((void**)&p_wil, g_wil);
    cudaGetSymbolAddress((void**)&p_woh, g_woh);
    cudaGetSymbolAddress((void**)&p_wol, g_wol);
    cudaGetSymbolAddress((void**)&p_yg,  g_yg);

    cudaFuncSetAttribute(mma_gemm, cudaFuncAttributeMaxDynamicSharedMemorySize, GEMM_SMEM);
    cudaFuncSetAttribute(yfused_kernel, cudaFuncAttributeMaxDynamicSharedMemorySize, YF_SMEM);
    cudaFuncSetAttribute(state_mma_kernel, cudaFuncAttributeMaxDynamicSharedMemorySize, ST_SMEM);

    // 0. fp16 conversions
    {
        size_t n = (size_t)ROWS * DMODEL;
        tofp16_kernel<<<(unsigned)((n + 255) / 256), 256>>>(u, p_uf, n);
    }
    splitf16_pad_kernel<<<(unsigned)(((size_t)DMODEL * NPAD1 + 255) / 256), 256>>>(
        W_in, p_wih, p_wil, DMODEL, DPROJ, NPAD1);
    {
        size_t n = (size_t)DINNER * DMODEL;
        splitf16_kernel<<<(unsigned)((n + 255) / 256), 256>>>(W_out, p_woh, p_wol, n);
    }

    // 1. zxbcdt = u @ W_in  (8192 x 4384 x 1024)
    mma_gemm<<<dim3(NPAD1 / 128, ROWS / 128), 256, GEMM_SMEM>>>(
        p_uf, p_wih, p_wil, p_zx, ROWS, DPROJ, DMODEL, NPAD1, DPROJ);
    // 2. causal conv1d + SiLU
    conv_silu_kernel<<<(ROWS * CONVDIM + 255) / 256, 256>>>(conv_w, conv_b);
    // 3. dt softplus
    dt_kernel<<<(ROWS * NHEADS + 255) / 256, 256>>>(dt_bias);
    // 4. per-chunk cumsum of A*dt
    ascan_kernel<<<dim3(NBC, NHEADS), CHUNK>>>(A_log);
    // 5. head-independent CB gram matrices
    cb_kernel<<<dim3(NBC, 4, 4), 256>>>();
    // 6. per-chunk end states (tensor cores)
    state_mma_kernel<<<dim3(NBC, NHEADS), 256, ST_SMEM>>>();
    // 7. inter-chunk recurrence
    chunkrec_kernel<<<dim3(BATCH, NHEADS), 256>>>();
    // 8. fused Y_diag + Y_off (tensor cores)
    yfused_kernel<<<dim3(NBC, NHEADS), 256, YF_SMEM>>>();
    // 9. layernorm + silu(z) gate -> fp16
    normgate_kernel<<<ROWS, 256>>>(norm_w);
    // 10. out = yg @ W_out  (8192 x 1024 x 2048)
    mma_gemm<<<dim3(DMODEL / 128, ROWS / 128), 256, GEMM_SMEM>>>(
        p_yg, p_woh, p_wol, out, ROWS, DMODEL, DINNER, DMODEL, DMODEL);
}

// round 11
// speedup vs baseline: 1.2580x; 1.0222x over previous
#include <cuda_runtime.h>
#include <cuda_bf16.h>
#include <cuda_fp16.h>
#include <math.h>
#include <stdint.h>

#define BATCH   2
#define SEQLEN  4096
#define DMODEL  1024
#define DINNER  2048
#define HEADDIM 64
#define NHEADS  32
#define DSTATE  128
#define DCONV   4
#define CHUNK   256
#define NCHUNK  (SEQLEN / CHUNK)   // 16
#define NBC     (BATCH * NCHUNK)   // 32
#define DPROJ   4384               // 2*DINNER + 2*DSTATE + NHEADS
#define CONVDIM 2304               // DINNER + 2*DSTATE
#define DT_OFF  4352               // 2*DINNER + 2*DSTATE
#define ROWS    (BATCH * SEQLEN)   // 8192
#define NPAD1   4480               // DPROJ padded to multiple of 128

// ---------------- scratch (device globals; no allocation allowed) ----------
__device__ float g_zxbcdt[(size_t)ROWS * DPROJ];
__device__ float g_xBC[(size_t)ROWS * CONVDIM];
__device__ float g_dt[ROWS * NHEADS];
__device__ float g_acs[NBC * NHEADS * CHUNK];
__device__ float g_asum[NBC * NHEADS];
__device__ float g_CB[(size_t)NBC * CHUNK * CHUNK];
__device__ float g_Y[(size_t)ROWS * DINNER];
__device__ float g_S[(size_t)NBC * NHEADS * HEADDIM * DSTATE];
__device__ float g_Sinit[(size_t)NBC * NHEADS * HEADDIM * DSTATE];

// fp16 GEMM operands: activations single, weights hi/lo split
__device__ __half g_uf[(size_t)ROWS * DMODEL];
__device__ __half g_wih[(size_t)DMODEL * NPAD1];
__device__ __half g_wil[(size_t)DMODEL * NPAD1];
__device__ __half g_woh[(size_t)DINNER * DMODEL];
__device__ __half g_wol[(size_t)DINNER * DMODEL];
__device__ __half g_yg[(size_t)ROWS * DINNER];

// ---------------- helpers ---------------------------------------------------
__device__ __forceinline__ uint32_t s2u(const void* p) {
    return (uint32_t)__cvta_generic_to_shared(p);
}
#define CP16(dst, src) \
    asm volatile("cp.async.cg.shared.global [%0], [%1], 16;\n" :: "r"(dst), "l"(src))
#define CP_COMMIT() asm volatile("cp.async.commit_group;\n")
#define CP_WAIT1()  asm volatile("cp.async.wait_group 1;\n")

__device__ __forceinline__ void ldsm4(uint32_t& r0, uint32_t& r1, uint32_t& r2,
                                      uint32_t& r3, uint32_t addr) {
    asm volatile("ldmatrix.sync.aligned.m8n8.x4.shared.b16 {%0,%1,%2,%3}, [%4];"
                 : "=r"(r0), "=r"(r1), "=r"(r2), "=r"(r3) : "r"(addr));
}
__device__ __forceinline__ void ldsm4t(uint32_t& r0, uint32_t& r1, uint32_t& r2,
                                       uint32_t& r3, uint32_t addr) {
    asm volatile("ldmatrix.sync.aligned.m8n8.x4.trans.shared.b16 {%0,%1,%2,%3}, [%4];"
                 : "=r"(r0), "=r"(r1), "=r"(r2), "=r"(r3) : "r"(addr));
}
// fp16 mma
__device__ __forceinline__ void mma16816h(float* d, const uint32_t* a, const uint32_t* b) {
    asm volatile(
        "mma.sync.aligned.m16n8k16.row.col.f32.f16.f16.f32 "
        "{%0,%1,%2,%3}, {%4,%5,%6,%7}, {%8,%9}, {%0,%1,%2,%3};"
        : "+f"(d[0]), "+f"(d[1]), "+f"(d[2]), "+f"(d[3])
        : "r"(a[0]), "r"(a[1]), "r"(a[2]), "r"(a[3]), "r"(b[0]), "r"(b[1]));
}
// bf16 mma
__device__ __forceinline__ void mma16816(float* d, const uint32_t* a, const uint32_t* b) {
    asm volatile(
        "mma.sync.aligned.m16n8k16.row.col.f32.bf16.bf16.f32 "
        "{%0,%1,%2,%3}, {%4,%5,%6,%7}, {%8,%9}, {%0,%1,%2,%3};"
        : "+f"(d[0]), "+f"(d[1]), "+f"(d[2]), "+f"(d[3])
        : "r"(a[0]), "r"(a[1]), "r"(a[2]), "r"(a[3]), "r"(b[0]), "r"(b[1]));
}
__device__ __forceinline__ void split2(float a, float b,
                                       __nv_bfloat162& h, __nv_bfloat162& l) {
    __nv_bfloat16 ha = __float2bfloat16(a), hb = __float2bfloat16(b);
    h = __halves2bfloat162(ha, hb);
    l = __halves2bfloat162(__float2bfloat16(a - __bfloat162float(ha)),
                           __float2bfloat16(b - __bfloat162float(hb)));
}

// ---------------- GEMM smem layout (bytes), tile 128x128, BK=32 -------------
#define A_B        10240         // 128*40*2
#define B_HALF_B   8704          // 32*136*2
#define OFF_BH     A_B
#define OFF_BL     (A_B + B_HALF_B)
#define STAGE_B    (A_B + 2 * B_HALF_B)            // 27648
#define NSTAGE     3
#define GEMM_SMEM  (NSTAGE * STAGE_B)              // 82944

// ---------------- fp16 2-term tensor-core GEMM (2 CTAs/SM, 128x128) ---------
__global__ __launch_bounds__(256, 2) void mma_gemm(
    const __half* __restrict__ A,
    const __half* __restrict__ Bh, const __half* __restrict__ Bl,
    float* __restrict__ C, int M, int N, int K, int ldb, int ldc)
{
    extern __shared__ __half smem[];
    const uint32_t sbase = s2u(smem);
    const int rowBase = blockIdx.y * 128;
    const int colBase = blockIdx.x * 128;
    const int t = threadIdx.x;

    const int ar = t >> 2, aq = t & 3;
    const __half* aS = A + (size_t)(rowBase + ar) * K + aq * 8;
    const uint32_t aD = sbase + (ar * 40 + aq * 8) * 2;
    const int br = t >> 4, bq = t & 15;
    const __half* bSh = Bh + (size_t)br * ldb + colBase + bq * 8;
    const __half* bSl = Bl + (size_t)br * ldb + colBase + bq * 8;
    const uint32_t bD = sbase + OFF_BH + (br * 136 + bq * 8) * 2;

    const int lane = t & 31, warp = t >> 5;
    const int wm = warp >> 2, wn = warp & 3;
    const int grp = lane >> 3, rr = lane & 7;

    uint32_t aAddr[4], bAddr[2];
#pragma unroll
    for (int mi = 0; mi < 4; mi++)
        aAddr[mi] = sbase + ((wm * 64 + mi * 16 + (grp & 1) * 8 + rr) * 40
                             + (grp >> 1) * 8) * 2;
#pragma unroll
    for (int pi = 0; pi < 2; pi++)
        bAddr[pi] = sbase + OFF_BH + (((grp & 1) * 8 + rr) * 136
                             + wn * 32 + pi * 16 + (grp >> 1) * 8) * 2;

    float d[4][4][4];
#pragma unroll
    for (int mi = 0; mi < 4; mi++)
#pragma unroll
        for (int ni = 0; ni < 4; ni++)
#pragma unroll
            for (int k = 0; k < 4; k++) d[mi][ni][k] = 0.f;

    const int nk = K / 32;

#define LOAD_SLAB(st, kt) do {                                                  \
    const uint32_t _d = (st) * STAGE_B;                                         \
    const int _k = (kt) * 32;                                                   \
    CP16(aD + _d, aS + _k);                                                     \
    CP16(aD + _d + 64 * 40 * 2, aS + (size_t)64 * K + _k);                      \
    CP16(bD + _d, bSh + (size_t)_k * ldb);                                      \
    CP16(bD + _d + 16 * 136 * 2, bSh + (size_t)(_k + 16) * ldb);                \
    CP16(bD + _d + B_HALF_B, bSl + (size_t)_k * ldb);                           \
    CP16(bD + _d + B_HALF_B + 16 * 136 * 2, bSl + (size_t)(_k + 16) * ldb);     \
} while (0)

#define FRAGS_MMA(sd, koff_a, koff_b) do {                                      \
    uint32_t a_f[4][4], b_h[4][2], b_l[4][2];                                   \
    _Pragma("unroll")                                                           \
    for (int mi = 0; mi < 4; mi++)                                              \
        ldsm4(a_f[mi][0], a_f[mi][1], a_f[mi][2], a_f[mi][3],                   \
              aAddr[mi] + (sd) + (koff_a));                                     \
    _Pragma("unroll")                                                           \
    for (int pi = 0; pi < 2; pi++) {                                            \
        ldsm4t(b_h[2*pi][0], b_h[2*pi][1], b_h[2*pi+1][0], b_h[2*pi+1][1],      \
               bAddr[pi] + (sd) + (koff_b));                                    \
        ldsm4t(b_l[2*pi][0], b_l[2*pi][1], b_l[2*pi+1][0], b_l[2*pi+1][1],      \
               bAddr[pi] + (sd) + (koff_b) + B_HALF_B);                         \
    }                                                                           \
    _Pragma("unroll")                                                           \
    for (int mi = 0; mi < 4; mi++)                                              \
        _Pragma("unroll")                                                       \
        for (int ni = 0; ni < 4; ni++) {                                        \
            mma16816h(d[mi][ni], a_f[mi], b_h[ni]);                             \
            mma16816h(d[mi][ni], a_f[mi], b_l[ni]);                             \
        }                                                                       \
} while (0)

    LOAD_SLAB(0, 0); CP_COMMIT();
    LOAD_SLAB(1, 1); CP_COMMIT();
    CP_WAIT1();
    __syncthreads();

    for (int kt = 0; kt < nk; kt++) {
        const uint32_t sd = (uint32_t)(kt % 3) * STAGE_B;
        if (kt + 2 < nk) LOAD_SLAB((kt + 2) % 3, kt + 2);
        CP_COMMIT();
        FRAGS_MMA(sd, 0, 0);
        FRAGS_MMA(sd, 32, 16 * 136 * 2);
        if (kt + 1 < nk) {
            CP_WAIT1();
            __syncthreads();
        }
    }

    const int r0 = rowBase + wm * 64 + (lane >> 2);
    const int c0 = colBase + wn * 32 + (lane & 3) * 2;
#pragma unroll
    for (int mi = 0; mi < 4; mi++)
#pragma unroll
        for (int ni = 0; ni < 4; ni++) {
            int col = c0 + ni * 8;
            if (col < N) {
                float2 v0 = make_float2(d[mi][ni][0], d[mi][ni][1]);
                float2 v1 = make_float2(d[mi][ni][2], d[mi][ni][3]);
                *(float2*)&C[(size_t)(r0 + mi * 16) * ldc + col] = v0;
                *(float2*)&C[(size_t)(r0 + mi * 16 + 8) * ldc + col] = v1;
            }
        }
#undef LOAD_SLAB
#undef FRAGS_MMA
}

// ---------------- CB gram via mma: CB[l,s] = sum_n C[l,n] B[s,n] ------------
// grid (bc, 4 l-tiles of 64). A = C (row-major [l][n]), B = B ([s][n] = k x s
// col-major) — both loaded with ldsm4 non-trans. bf16 3-term.
#define CB_AH    0
#define CB_AL    17408               // 64*136*2
#define CB_BH    34816
#define CB_BL    52224
#define CB_SMEM  69632

__global__ __launch_bounds__(256, 2) void cb_mma_kernel()
{
    extern __shared__ char csm[];
    __nv_bfloat16* Ah = (__nv_bfloat16*)(csm + CB_AH);   // [l(64)][n(136)]
    __nv_bfloat16* Al = (__nv_bfloat16*)(csm + CB_AL);
    __nv_bfloat16* Bh = (__nv_bfloat16*)(csm + CB_BH);   // [s(64)][n(136)]
    __nv_bfloat16* Bl = (__nv_bfloat16*)(csm + CB_BL);

    const int bc = blockIdx.x, lt = blockIdx.y;
    const int b = bc >> 4, c = bc & 15;
    const int t = threadIdx.x;
    const size_t rowB = (size_t)b * SEQLEN + c * CHUNK;

    const int lane = t & 31, warp = t >> 5;
    const int wm = warp >> 2, wn = warp & 3;
    const int grp = lane >> 3, rr = lane & 7;
    const uint32_t ahB = s2u(Ah), alB = s2u(Al), bhB = s2u(Bh), blB = s2u(Bl);

    // load A tile (C slice), rows lt*64 + r
    {
        const int r = t >> 2, q = (t & 3) * 32;
        const float* cr = g_xBC + (rowB + lt * 64 + r) * CONVDIM
                          + (DINNER + DSTATE) + q;
        __nv_bfloat162* ah2 = (__nv_bfloat162*)(Ah + r * 136 + q);
        __nv_bfloat162* al2 = (__nv_bfloat162*)(Al + r * 136 + q);
#pragma unroll
        for (int j = 0; j < 32; j += 4) {
            float4 v = *(const float4*)(cr + j);
            __nv_bfloat162 h01, l01, h23, l23;
            split2(v.x, v.y, h01, l01);
            split2(v.z, v.w, h23, l23);
            ah2[(j >> 1) + 0] = h01; ah2[(j >> 1) + 1] = h23;
            al2[(j >> 1) + 0] = l01; al2[(j >> 1) + 1] = l23;
        }
    }

    uint32_t aOff[2];
#pragma unroll
    for (int mi = 0; mi < 2; mi++)
        aOff[mi] = ((wm * 32 + mi * 16 + (grp & 1) * 8 + rr) * 136
                    + (grp >> 1) * 8) * 2;
    const uint32_t bOff = ((wn * 16 + (grp & 1) * 8 + rr) * 136
                           + (grp >> 1) * 8) * 2;

    float d[2][8][4];
#pragma unroll
    for (int mi = 0; mi < 2; mi++)
#pragma unroll
        for (int ni = 0; ni < 8; ni++)
#pragma unroll
            for (int k = 0; k < 4; k++) d[mi][ni][k] = 0.f;

    for (int stile = 0; stile < 4; stile++) {
        // load B tile, rows stile*64 + r
        {
            const int r = t >> 2, q = (t & 3) * 32;
            const float* br = g_xBC + (rowB + stile * 64 + r) * CONVDIM
                              + DINNER + q;
            __nv_bfloat162* bh2 = (__nv_bfloat162*)(Bh + r * 136 + q);
            __nv_bfloat162* bl2 = (__nv_bfloat162*)(Bl + r * 136 + q);
#pragma unroll
            for (int j = 0; j < 32; j += 4) {
                float4 v = *(const float4*)(br + j);
                __nv_bfloat162 h01, l01, h23, l23;
                split2(v.x, v.y, h01, l01);
                split2(v.z, v.w, h23, l23);
                bh2[(j >> 1) + 0] = h01; bh2[(j >> 1) + 1] = h23;
                bl2[(j >> 1) + 0] = l01; bl2[(j >> 1) + 1] = l23;
            }
        }
        __syncthreads();
#pragma unroll
        for (int k = 0; k < 8; k++) {
            const uint32_t ko = k * 32;     // 16 halfs
            uint32_t a_h[2][4], a_l[2][4], b4h[4], b4l[4];
#pragma unroll
            for (int mi = 0; mi < 2; mi++) {
                ldsm4(a_h[mi][0], a_h[mi][1], a_h[mi][2], a_h[mi][3],
                      ahB + aOff[mi] + ko);
                ldsm4(a_l[mi][0], a_l[mi][1], a_l[mi][2], a_l[mi][3],
                      alB + aOff[mi] + ko);
            }
            ldsm4(b4h[0], b4h[1], b4h[2], b4h[3], bhB + bOff + ko);
            ldsm4(b4l[0], b4l[1], b4l[2], b4l[3], blB + bOff + ko);
            uint32_t bh0[2] = {b4h[0], b4h[2]};   // s+0..7
            uint32_t bh1[2] = {b4h[1], b4h[3]};   // s+8..15
            uint32_t bl0[2] = {b4l[0], b4l[2]};
            uint32_t bl1[2] = {b4l[1], b4l[3]};
#pragma unroll
            for (int mi = 0; mi < 2; mi++) {
                mma16816(d[mi][stile * 2 + 0], a_h[mi], bh0);
                mma16816(d[mi][stile * 2 + 0], a_h[mi], bl0);
                mma16816(d[mi][stile * 2 + 0], a_l[mi], bh0);
                mma16816(d[mi][stile * 2 + 1], a_h[mi], bh1);
                mma16816(d[mi][stile * 2 + 1], a_h[mi], bl1);
                mma16816(d[mi][stile * 2 + 1], a_l[mi], bh1);
            }
        }
        __syncthreads();
    }

    // epilogue
    const int r0 = lt * 64 + wm * 32 + (lane >> 2);
    const int c0 = (lane & 3) * 2;
#pragma unroll
    for (int mi = 0; mi < 2; mi++) {
        float* out0 = g_CB + ((size_t)bc * CHUNK + r0 + mi * 16) * CHUNK;
        float* out1 = out0 + 8 * CHUNK;
#pragma unroll
        for (int st = 0; st < 4; st++)
#pragma unroll
            for (int q = 0; q < 2; q++) {
                int col = st * 64 + wn * 16 + q * 8 + c0;
                float* dd = d[mi][st * 2 + q];
                *(float2*)&out0[col] = make_float2(dd[0], dd[1]);
                *(float2*)&out1[col] = make_float2(dd[2], dd[3]);
            }
    }
}

// ---------------- fused Y = (CB.L)X + exp(acs) C Sinit (bf16 3-term) --------
#define YF_WH    0
#define YF_WL    36864               // 256*72*2
#define YF_XH    73728
#define YF_XL    82944               // + 64*72*2
#define YF_ACS   92160
#define YF_DT    93184
#define YF_SMEM  94208

__global__ __launch_bounds__(256, 2) void yfused_kernel()
{
    extern __shared__ char ysm[];
    __nv_bfloat16* Wh = (__nv_bfloat16*)(ysm + YF_WH);
    __nv_bfloat16* Wl = (__nv_bfloat16*)(ysm + YF_WL);
    __nv_bfloat16* Xh = (__nv_bfloat16*)(ysm + YF_XH);
    __nv_bfloat16* Xl = (__nv_bfloat16*)(ysm + YF_XL);
    float* sacs = (float*)(ysm + YF_ACS);
    float* sdt  = (float*)(ysm + YF_DT);

    const int bc = blockIdx.x, h = blockIdx.y;
    const int b = bc >> 4, c = bc & 15;
    const int t = threadIdx.x;
    const size_t rowB = (size_t)b * SEQLEN + c * CHUNK;

    sacs[t] = g_acs[((size_t)bc * NHEADS + h) * CHUNK + t];
    sdt[t]  = g_dt[(rowB + t) * NHEADS + h];
    __syncthreads();
    const float acs_l = sacs[t];

    const int lane = t & 31, warp = t >> 5;
    const int grp = lane >> 3, rr = lane & 7;
    const uint32_t whB = s2u(Wh), wlB = s2u(Wl), xhB = s2u(Xh), xlB = s2u(Xl);

    uint32_t aOff[2], bOff[4];
#pragma unroll
    for (int mi = 0; mi < 2; mi++)
        aOff[mi] = ((warp * 32 + mi * 16 + (grp & 1) * 8 + rr) * 72
                    + (grp >> 1) * 8) * 2;
#pragma unroll
    for (int pi = 0; pi < 4; pi++)
        bOff[pi] = (((grp & 1) * 8 + rr) * 72 + pi * 16 + (grp >> 1) * 8) * 2;

    float d[2][8][4];
#pragma unroll
    for (int mi = 0; mi < 2; mi++)
#pragma unroll
        for (int ni = 0; ni < 8; ni++)
#pragma unroll
            for (int k = 0; k < 4; k++) d[mi][ni][k] = 0.f;

#define YF_MMA() do {                                                           \
    _Pragma("unroll")                                                           \
    for (int k = 0; k < 4; k++) {                                               \
        const uint32_t ka = k * 32;                                             \
        const uint32_t kb = k * 16 * 144;                                       \
        uint32_t a_h[2][4], a_l[2][4];                                          \
        _Pragma("unroll")                                                       \
        for (int mi = 0; mi < 2; mi++) {                                        \
            ldsm4(a_h[mi][0], a_h[mi][1], a_h[mi][2], a_h[mi][3],               \
                  whB + aOff[mi] + ka);                                         \
            ldsm4(a_l[mi][0], a_l[mi][1], a_l[mi][2], a_l[mi][3],               \
                  wlB + aOff[mi] + ka);                                         \
        }                                                                       \
        _Pragma("unroll")                                                       \
        for (int pi = 0; pi < 4; pi++) {                                        \
            uint32_t bh[2][2], bl[2][2];                                        \
            ldsm4t(bh[0][0], bh[0][1], bh[1][0], bh[1][1],                      \
                   xhB + bOff[pi] + kb);                                        \
            ldsm4t(bl[0][0], bl[0][1], bl[1][0], bl[1][1],                      \
                   xlB + bOff[pi] + kb);                                        \
            _Pragma("unroll")                                                   \
            for (int mi = 0; mi < 2; mi++)                                      \
                _Pragma("unroll")                                               \
                for (int q = 0; q < 2; q++) {                                   \
                    mma16816(d[mi][2*pi+q], a_h[mi], bh[q]);                    \
                    mma16816(d[mi][2*pi+q], a_h[mi], bl[q]);                    \
                    mma16816(d[mi][2*pi+q], a_l[mi], bh[q]);                    \
                }                                                               \
        }                                                                       \
    }                                                                           \
} while (0)

    // ---- part 1: Y_diag, 4 s-tiles of 64 ----
    const float* CBrow = g_CB + ((size_t)bc * CHUNK + t) * CHUNK;
    for (int st = 0; st < 4; st++) {
        const int s0 = st * 64;
        __nv_bfloat162* wh2 = (__nv_bfloat162*)(Wh + t * 72);
        __nv_bfloat162* wl2 = (__nv_bfloat162*)(Wl + t * 72);
#pragma unroll
        for (int j = 0; j < 64; j += 4) {
            float4 cb4 = *(const float4*)(CBrow + s0 + j);
            float w[4];
            const float* cbp = (const float*)&cb4;
#pragma unroll
            for (int e = 0; e < 4; e++) {
                int s = s0 + j + e;
                float arg = fminf(acs_l - sacs[s], 0.f);
                w[e] = (s <= t) ? cbp[e] * __expf(arg) : 0.f;
            }
            __nv_bfloat162 h01, l01, h23, l23;
            split2(w[0], w[1], h01, l01);
            split2(w[2], w[3], h23, l23);
            wh2[(j >> 1) + 0] = h01; wh2[(j >> 1) + 1] = h23;
            wl2[(j >> 1) + 0] = l01; wl2[(j >> 1) + 1] = l23;
        }
        {
            const int r = t >> 2, c16 = (t & 3) * 16;
            const float dts = sdt[s0 + r];
            const float* xr = g_xBC + (rowB + s0 + r) * CONVDIM + h * HEADDIM + c16;
            __nv_bfloat162* xh2 = (__nv_bfloat162*)(Xh + r * 72 + c16);
            __nv_bfloat162* xl2 = (__nv_bfloat162*)(Xl + r * 72 + c16);
#pragma unroll
            for (int j = 0; j < 16; j += 4) {
                float4 v = *(const float4*)(xr + j);
                __nv_bfloat162 h01, l01, h23, l23;
                split2(v.x * dts, v.y * dts, h01, l01);
                split2(v.z * dts, v.w * dts, h23, l23);
                xh2[(j >> 1) + 0] = h01; xh2[(j >> 1) + 1] = h23;
                xl2[(j >> 1) + 0] = l01; xl2[(j >> 1) + 1] = l23;
            }
        }
        __syncthreads();
        YF_MMA();
        __syncthreads();
    }

    // ---- part 2: Y_off, 2 n-tiles of 64 ----
    const float el = __expf(acs_l);
    const float* Crow = g_xBC + (rowB + t) * CONVDIM + DINNER + DSTATE;
    const float* S0p = g_Sinit + ((size_t)bc * NHEADS + h) * (HEADDIM * DSTATE);
    for (int nt = 0; nt < 2; nt++) {
        const int n0 = nt * 64;
        __nv_bfloat162* wh2 = (__nv_bfloat162*)(Wh + t * 72);
        __nv_bfloat162* wl2 = (__nv_bfloat162*)(Wl + t * 72);
#pragma unroll
        for (int j = 0; j < 64; j += 4) {
            float4 c4 = *(const float4*)(Crow + n0 + j);
            __nv_bfloat162 h01, l01, h23, l23;
            split2(c4.x * el, c4.y * el, h01, l01);
            split2(c4.z * el, c4.w * el, h23, l23);
            wh2[(j >> 1) + 0] = h01; wh2[(j >> 1) + 1] = h23;
            wl2[(j >> 1) + 0] = l01; wl2[(j >> 1) + 1] = l23;
        }
        {
            const int p = t >> 2, nb = (t & 3) * 16;
            const float* sp = S0p + (size_t)p * DSTATE + n0 + nb;
#pragma unroll
            for (int j = 0; j < 16; j++) {
                float v = sp[j];
                __nv_bfloat16 hh = __float2bfloat16(v);
                Xh[(nb + j) * 72 + p] = hh;
                Xl[(nb + j) * 72 + p] = __float2bfloat16(v - __bfloat162float(hh));
            }
        }
        __syncthreads();
        YF_MMA();
        __syncthreads();
    }
#undef YF_MMA

    const int c0 = (lane & 3) * 2;
#pragma unroll
    for (int mi = 0; mi < 2; mi++) {
        const size_t gr0 = (rowB + warp * 32 + (lane >> 2) + mi * 16) * DINNER + h * HEADDIM;
#pragma unroll
        for (int ni = 0; ni < 8; ni++) {
            int col = c0 + ni * 8;
            *(float2*)&g_Y[gr0 + col] = make_float2(d[mi][ni][0], d[mi][ni][1]);
            *(float2*)&g_Y[gr0 + 8 * DINNER + col] = make_float2(d[mi][ni][2], d[mi][ni][3]);
        }
    }
}

// ---------------- state S[64p x 128n] = x^T . (w.B), bf16 3-term mma --------
#define ST_AH    0
#define ST_AL    9216                // 64*72*2
#define ST_BH    18432
#define ST_BL    35840               // + 64*136*2
#define ST_SMEM  53248

__global__ __launch_bounds__(256, 2) void state_mma_kernel()
{
    extern __shared__ char ssm[];
    __nv_bfloat16* Ah = (__nv_bfloat16*)(ssm + ST_AH);   // [p(64)][s(72 pad)]
    __nv_bfloat16* Al = (__nv_bfloat16*)(ssm + ST_AL);
    __nv_bfloat16* Bh = (__nv_bfloat16*)(ssm + ST_BH);   // [s(64)][n(136 pad)]
    __nv_bfloat16* Bl = (__nv_bfloat16*)(ssm + ST_BL);

    const int bc = blockIdx.x, h = blockIdx.y;
    const int b = bc >> 4, c = bc & 15;
    const int t = threadIdx.x;
    const size_t rowB = (size_t)b * SEQLEN + c * CHUNK;
    const float asum = g_asum[bc * NHEADS + h];
    const float* acsp = g_acs + ((size_t)bc * NHEADS + h) * CHUNK;

    const int lane = t & 31, warp = t >> 5;
    const int wm = warp >> 2, wn = warp & 3;
    const int grp = lane >> 3, rr = lane & 7;
    const uint32_t ahB = s2u(Ah), alB = s2u(Al), bhB = s2u(Bh), blB = s2u(Bl);

    uint32_t aOff[2], bOff[2];
#pragma unroll
    for (int mi = 0; mi < 2; mi++)
        aOff[mi] = ((wm * 32 + mi * 16 + (grp & 1) * 8 + rr) * 72
                    + (grp >> 1) * 8) * 2;
#pragma unroll
    for (int pi = 0; pi < 2; pi++)
        bOff[pi] = (((grp & 1) * 8 + rr) * 136
                    + wn * 32 + pi * 16 + (grp >> 1) * 8) * 2;

    float d[2][4][4];
#pragma unroll
    for (int mi = 0; mi < 2; mi++)
#pragma unroll
        for (int ni = 0; ni < 4; ni++)
#pragma unroll
            for (int k = 0; k < 4; k++) d[mi][ni][k] = 0.f;

    for (int st4 = 0; st4 < 4; st4++) {
        const int s0 = st4 * 64;
        const int r = t >> 2;
        const float w = g_dt[(rowB + s0 + r) * NHEADS + h] *
                        __expf(asum - acsp[s0 + r]);
        {
            const int q = (t & 3) * 16;
            const float* xr = g_xBC + (rowB + s0 + r) * CONVDIM + h * HEADDIM + q;
#pragma unroll
            for (int j = 0; j < 16; j += 4) {
                float4 v = *(const float4*)(xr + j);
                float vals[4] = {v.x, v.y, v.z, v.w};
#pragma unroll
                for (int e = 0; e < 4; e++) {
                    __nv_bfloat16 hh = __float2bfloat16(vals[e]);
                    Ah[(q + j + e) * 72 + r] = hh;
                    Al[(q + j + e) * 72 + r] =
                        __float2bfloat16(vals[e] - __bfloat162float(hh));
                }
            }
        }
        {
            const int nq = (t & 3) * 32;
            const float* brp = g_xBC + (rowB + s0 + r) * CONVDIM + DINNER + nq;
            __nv_bfloat162* bh2 = (__nv_bfloat162*)(Bh + r * 136 + nq);
            __nv_bfloat162* bl2 = (__nv_bfloat162*)(Bl + r * 136 + nq);
#pragma unroll
            for (int j = 0; j < 32; j += 4) {
                float4 v = *(const float4*)(brp + j);
                __nv_bfloat162 h01, l01, h23, l23;
                split2(v.x * w, v.y * w, h01, l01);
                split2(v.z * w, v.w * w, h23, l23);
                bh2[(j >> 1) + 0] = h01; bh2[(j >> 1) + 1] = h23;
                bl2[(j >> 1) + 0] = l01; bl2[(j >> 1) + 1] = l23;
            }
        }
        __syncthreads();
#pragma unroll
        for (int k = 0; k < 4; k++) {
            const uint32_t ka = k * 32;
            const uint32_t kb = (uint32_t)k * 16 * 136 * 2;
            uint32_t a_h[2][4], a_l[2][4], bhf[4][2], blf[4][2];
#pragma unroll
            for (int mi = 0; mi < 2; mi++) {
                ldsm4(a_h[mi][0], a_h[mi][1], a_h[mi][2], a_h[mi][3],
                      ahB + aOff[mi] + ka);
                ldsm4(a_l[mi][0], a_l[mi][1], a_l[mi][2], a_l[mi][3],
                      alB + aOff[mi] + ka);
            }
#pragma unroll
            for (int pi = 0; pi < 2; pi++) {
                ldsm4t(bhf[2*pi][0], bhf[2*pi][1], bhf[2*pi+1][0], bhf[2*pi+1][1],
                       bhB + bOff[pi] + kb);
                ldsm4t(blf[2*pi][0], blf[2*pi][1], blf[2*pi+1][0], blf[2*pi+1][1],
                       blB + bOff[pi] + kb);
            }
#pragma unroll
            for (int mi = 0; mi < 2; mi++)
#pragma unroll
                for (int ni = 0; ni < 4; ni++) {
                    mma16816(d[mi][ni], a_h[mi], bhf[ni]);
                    mma16816(d[mi][ni], a_h[mi], blf[ni]);
                    mma16816(d[mi][ni], a_l[mi], bhf[ni]);
                }
        }
        __syncthreads();
    }

    float* Sout = g_S + ((size_t)bc * NHEADS + h) * (HEADDIM * DSTATE);
    const int p0 = wm * 32 + (lane >> 2);
    const int n0 = wn * 32 + (lane & 3) * 2;
#pragma unroll
    for (int mi = 0; mi < 2; mi++)
#pragma unroll
        for (int ni = 0; ni < 4; ni++) {
            int col = n0 + ni * 8;
            *(float2*)&Sout[(size_t)(p0 + mi * 16) * DSTATE + col] =
                make_float2(d[mi][ni][0], d[mi][ni][1]);
            *(float2*)&Sout[(size_t)(p0 + mi * 16 + 8) * DSTATE + col] =
                make_float2(d[mi][ni][2], d[mi][ni][3]);
        }
}

// ---------------- convert kernels -------------------------------------------
__global__ void tofp16_kernel(const float* __restrict__ x, __half* __restrict__ o, size_t n)
{
    size_t i = (size_t)blockIdx.x * blockDim.x + threadIdx.x;
    if (i >= n) return;
    o[i] = __float2half(x[i]);
}

__global__ void splitf16_kernel(const float* __restrict__ x, __half* __restrict__ hi,
                                __half* __restrict__ lo, size_t n)
{
    size_t i = (size_t)blockIdx.x * blockDim.x + threadIdx.x;
    if (i >= n) return;
    float v = x[i];
    __half h = __float2half(v);
    hi[i] = h;
    lo[i] = __float2half(v - __half2float(h));
}

__global__ void splitf16_pad_kernel(const float* __restrict__ x, __half* __restrict__ hi,
                                    __half* __restrict__ lo, int K, int N, int Np)
{
    size_t i = (size_t)blockIdx.x * blockDim.x + threadIdx.x;
    if (i >= (size_t)K * Np) return;
    int r = (int)(i / Np), c = (int)(i % Np);
    float v = (c < N) ? x[(size_t)r * N + c] : 0.f;
    __half h = __float2half(v);
    hi[i] = h;
    lo[i] = __float2half(v - __half2float(h));
}

// ---------------- causal conv1d + SiLU: 4 outputs per thread ----------------
__global__ void conv_silu_kernel(const float* __restrict__ conv_w,
                                 const float* __restrict__ conv_b)
{
    int idx = blockIdx.x * blockDim.x + threadIdx.x;
    if (idx >= (ROWS / 4) * CONVDIM) return;
    int c  = idx % CONVDIM;
    int rg = idx / CONVDIM;
    int row0 = rg * 4;
    int l0 = row0 & (SEQLEN - 1);
    const float* base = g_zxbcdt + (size_t)row0 * DPROJ + DINNER + c;
    const float w0 = conv_w[c * DCONV + 0], w1 = conv_w[c * DCONV + 1];
    const float w2 = conv_w[c * DCONV + 2], w3 = conv_w[c * DCONV + 3];
    const float bias = conv_b[c];
    float v[7];
#pragma unroll
    for (int j = 0; j < 7; j++) {
        int l = l0 - 3 + j;
        v[j] = (l >= 0) ? base[(long)(j - 3) * DPROJ] : 0.f;
    }
#pragma unroll
    for (int i = 0; i < 4; i++) {
        float acc = bias + v[i] * w0 + v[i+1] * w1 + v[i+2] * w2 + v[i+3] * w3;
        g_xBC[(size_t)(row0 + i) * CONVDIM + c] = acc / (1.f + __expf(-acc));
    }
}

// ---------------- dt = softplus(dt_raw + dt_bias) --------------------------
__global__ void dt_kernel(const float* __restrict__ dt_bias)
{
    int idx = blockIdx.x * blockDim.x + threadIdx.x;
    if (idx >= ROWS * NHEADS) return;
    int h   = idx & (NHEADS - 1);
    int row = idx >> 5;
    float v = g_zxbcdt[(size_t)row * DPROJ + DT_OFF + h] + dt_bias[h];
    g_dt[idx] = (v > 20.f) ? v : log1pf(expf(v));
}

// ---------------- per-chunk inclusive cumsum of a = A*dt -------------------
__global__ void ascan_kernel(const float* __restrict__ A_log)
{
    int bc = blockIdx.x;
    int h  = blockIdx.y;
    int t  = threadIdx.x;
    int b = bc >> 4, c = bc & 15;
    __shared__ float sa[CHUNK];
    int row = b * SEQLEN + c * CHUNK + t;
    float A = -expf(A_log[h]);
    sa[t] = A * g_dt[row * NHEADS + h];
    __syncthreads();
    for (int off = 1; off < CHUNK; off <<= 1) {
        float v = (t >= off) ? sa[t - off] : 0.f;
        __syncthreads();
        sa[t] += v;
        __syncthreads();
    }
    g_acs[(bc * NHEADS + h) * CHUNK + t] = sa[t];
    if (t == CHUNK - 1) g_asum[bc * NHEADS + h] = sa[t];
}

// ---------------- sequential inter-chunk recurrence ------------------------
__global__ void chunkrec_kernel()
{
    int b = blockIdx.x, h = blockIdx.y;
    int t = threadIdx.x;
    float cur[32];
#pragma unroll
    for (int k = 0; k < 32; k++) cur[k] = 0.f;
    for (int c = 0; c < NCHUNK; c++) {
        int bc = b * NCHUNK + c;
        size_t base = ((size_t)bc * NHEADS + h) * (HEADDIM * DSTATE);
        float dd = __expf(g_asum[bc * NHEADS + h]);
#pragma unroll
        for (int k = 0; k < 32; k++) {
            size_t e = base + t + 256 * k;
            g_Sinit[e] = cur[k];
            cur[k] = cur[k] * dd + g_S[e];
        }
    }
}

// ---------------- layernorm + z-gate -> fp16 yg ----------------------------
__global__ __launch_bounds__(256) void normgate_kernel(const float* __restrict__ norm_w)
{
    int row = blockIdx.x;
    int t = threadIdx.x;
    const float* yrow = g_Y + (size_t)row * DINNER;
    const float* zrow = g_zxbcdt + (size_t)row * DPROJ;
    float v[8];
    float s = 0.f;
#pragma unroll
    for (int i = 0; i < 8; i++) { v[i] = yrow[t + 256*i]; s += v[i]; }
    __shared__ float red[256];
    red[t] = s; __syncthreads();
    for (int o = 128; o > 0; o >>= 1) { if (t < o) red[t] += red[t+o]; __syncthreads(); }
    float mu = red[0] * (1.f / DINNER);
    __syncthreads();
    float s2 = 0.f;
#pragma unroll
    for (int i = 0; i < 8; i++) { float dv = v[i] - mu; s2 += dv * dv; }
    red[t] = s2; __syncthreads();
    for (int o = 128; o > 0; o >>= 1) { if (t < o) red[t] += red[t+o]; __syncthreads(); }
    float inv = rsqrtf(red[0] * (1.f / DINNER) + 1e-5f);
    __half* orow = g_yg + (size_t)row * DINNER;
#pragma unroll
    for (int i = 0; i < 8; i++) {
        int idx = t + 256*i;
        float z = zrow[idx];
        float g = z / (1.f + __expf(-z));
        orow[idx] = __float2half((v[i] - mu) * inv * norm_w[idx] * g);
    }
}

// ---------------- launch ---------------------------------------------------
extern "C" void kernel_launch(void* const* d_in, const int* in_sizes, int n_in,
                              void* d_out, int out_size)
{
    const float* u       = (const float*)d_in[0];
    const float* W_in    = (const float*)d_in[1];
    const float* conv_w  = (const float*)d_in[2];
    const float* conv_b  = (const float*)d_in[3];
    const float* dt_bias = (const float*)d_in[4];
    const float* A_log   = (const float*)d_in[5];
    const float* norm_w  = (const float*)d_in[6];
    const float* W_out   = (const float*)d_in[7];
    float* out = (float*)d_out;

    float* p_zx = nullptr;
    __half *p_uf, *p_wih, *p_wil, *p_woh, *p_wol, *p_yg;
    cudaGetSymbolAddress((void**)&p_zx,  g_zxbcdt);
    cudaGetSymbolAddress((void**)&p_uf,  g_uf);
    cudaGetSymbolAddress((void**)&p_wih, g_wih);
    cudaGetSymbolAddress((void**)&p_wil, g_wil);
    cudaGetSymbolAddress((void**)&p_woh, g_woh);
    cudaGetSymbolAddress((void**)&p_wol, g_wol);
    cudaGetSymbolAddress((void**)&p_yg,  g_yg);

    cudaFuncSetAttribute(mma_gemm, cudaFuncAttributeMaxDynamicSharedMemorySize, GEMM_SMEM);
    cudaFuncSetAttribute(yfused_kernel, cudaFuncAttributeMaxDynamicSharedMemorySize, YF_SMEM);
    cudaFuncSetAttribute(state_mma_kernel, cudaFuncAttributeMaxDynamicSharedMemorySize, ST_SMEM);
    cudaFuncSetAttribute(cb_mma_kernel, cudaFuncAttributeMaxDynamicSharedMemorySize, CB_SMEM);

    // 0. fp16 conversions
    {
        size_t n = (size_t)ROWS * DMODEL;
        tofp16_kernel<<<(unsigned)((n + 255) / 256), 256>>>(u, p_uf, n);
    }
    splitf16_pad_kernel<<<(unsigned)(((size_t)DMODEL * NPAD1 + 255) / 256), 256>>>(
        W_in, p_wih, p_wil, DMODEL, DPROJ, NPAD1);
    {
        size_t n = (size_t)DINNER * DMODEL;
        splitf16_kernel<<<(unsigned)((n + 255) / 256), 256>>>(W_out, p_woh, p_wol, n);
    }

    // 1. zxbcdt = u @ W_in  (8192 x 4384 x 1024)
    mma_gemm<<<dim3(NPAD1 / 128, ROWS / 128), 256, GEMM_SMEM>>>(
        p_uf, p_wih, p_wil, p_zx, ROWS, DPROJ, DMODEL, NPAD1, DPROJ);
    // 2. causal conv1d + SiLU (4 l per thread)
    conv_silu_kernel<<<((ROWS / 4) * CONVDIM + 255) / 256, 256>>>(conv_w, conv_b);
    // 3. dt softplus
    dt_kernel<<<(ROWS * NHEADS + 255) / 256, 256>>>(dt_bias);
    // 4. per-chunk cumsum of A*dt
    ascan_kernel<<<dim3(NBC, NHEADS), CHUNK>>>(A_log);
    // 5. CB gram matrices (tensor cores, full 256x256)
    cb_mma_kernel<<<dim3(NBC, 4), 256, CB_SMEM>>>();
    // 6. per-chunk end states (tensor cores)
    state_mma_kernel<<<dim3(NBC, NHEADS), 256, ST_SMEM>>>();
    // 7. inter-chunk recurrence
    chunkrec_kernel<<<dim3(BATCH, NHEADS), 256>>>();
    // 8. fused Y_diag + Y_off (tensor cores)
    yfused_kernel<<<dim3(NBC, NHEADS), 256, YF_SMEM>>>();
    // 9. layernorm + silu(z) gate -> fp16
    normgate_kernel<<<ROWS, 256>>>(norm_w);
    // 10. out = yg @ W_out  (8192 x 1024 x 2048)
    mma_gemm<<<dim3(DMODEL / 128, ROWS / 128), 256, GEMM_SMEM>>>(
        p_yg, p_woh, p_wol, out, ROWS, DMODEL, DINNER, DMODEL, DMODEL);
}

// round 12
// speedup vs baseline: 1.5765x; 1.2532x over previous
#include <cuda_runtime.h>
#include <cuda_bf16.h>
#include <cuda_fp16.h>
#include <math.h>
#include <stdint.h>

#define BATCH   2
#define SEQLEN  4096
#define DMODEL  1024
#define DINNER  2048
#define HEADDIM 64
#define NHEADS  32
#define DSTATE  128
#define DCONV   4
#define CHUNK   256
#define NCHUNK  (SEQLEN / CHUNK)   // 16
#define NBC     (BATCH * NCHUNK)   // 32
#define DPROJ   4384               // 2*DINNER + 2*DSTATE + NHEADS
#define CONVDIM 2304               // DINNER + 2*DSTATE
#define DT_OFF  4352               // 2*DINNER + 2*DSTATE
#define ROWS    (BATCH * SEQLEN)   // 8192
#define NPAD1   4480               // DPROJ padded to multiple of 128

// ---------------- scratch (device globals; no allocation allowed) ----------
__device__ float g_zxbcdt[(size_t)ROWS * DPROJ];
__device__ float g_xBC[(size_t)ROWS * CONVDIM];
__device__ float g_dt[ROWS * NHEADS];
__device__ float g_acs[NBC * NHEADS * CHUNK];
__device__ float g_asum[NBC * NHEADS];
__device__ float g_CB[(size_t)NBC * CHUNK * CHUNK];
__device__ float g_Y[(size_t)ROWS * DINNER];
__device__ float g_S[(size_t)NBC * NHEADS * HEADDIM * DSTATE];
__device__ float g_Sinit[(size_t)NBC * NHEADS * HEADDIM * DSTATE];

// fp16 GEMM operands (all single precision fp16)
__device__ __half g_uf[(size_t)ROWS * DMODEL];
__device__ __half g_wif[(size_t)DMODEL * NPAD1];
__device__ __half g_wof[(size_t)DINNER * DMODEL];
__device__ __half g_yg[(size_t)ROWS * DINNER];

// ---------------- helpers ---------------------------------------------------
__device__ __forceinline__ uint32_t s2u(const void* p) {
    return (uint32_t)__cvta_generic_to_shared(p);
}
#define CP16(dst, src) \
    asm volatile("cp.async.cg.shared.global [%0], [%1], 16;\n" :: "r"(dst), "l"(src))
#define CP_COMMIT() asm volatile("cp.async.commit_group;\n")
#define CP_WAIT1()  asm volatile("cp.async.wait_group 1;\n")

__device__ __forceinline__ void ldsm4(uint32_t& r0, uint32_t& r1, uint32_t& r2,
                                      uint32_t& r3, uint32_t addr) {
    asm volatile("ldmatrix.sync.aligned.m8n8.x4.shared.b16 {%0,%1,%2,%3}, [%4];"
                 : "=r"(r0), "=r"(r1), "=r"(r2), "=r"(r3) : "r"(addr));
}
__device__ __forceinline__ void ldsm4t(uint32_t& r0, uint32_t& r1, uint32_t& r2,
                                       uint32_t& r3, uint32_t addr) {
    asm volatile("ldmatrix.sync.aligned.m8n8.x4.trans.shared.b16 {%0,%1,%2,%3}, [%4];"
                 : "=r"(r0), "=r"(r1), "=r"(r2), "=r"(r3) : "r"(addr));
}
// fp16 mma
__device__ __forceinline__ void mma16816h(float* d, const uint32_t* a, const uint32_t* b) {
    asm volatile(
        "mma.sync.aligned.m16n8k16.row.col.f32.f16.f16.f32 "
        "{%0,%1,%2,%3}, {%4,%5,%6,%7}, {%8,%9}, {%0,%1,%2,%3};"
        : "+f"(d[0]), "+f"(d[1]), "+f"(d[2]), "+f"(d[3])
        : "r"(a[0]), "r"(a[1]), "r"(a[2]), "r"(a[3]), "r"(b[0]), "r"(b[1]));
}
// bf16 mma
__device__ __forceinline__ void mma16816(float* d, const uint32_t* a, const uint32_t* b) {
    asm volatile(
        "mma.sync.aligned.m16n8k16.row.col.f32.bf16.bf16.f32 "
        "{%0,%1,%2,%3}, {%4,%5,%6,%7}, {%8,%9}, {%0,%1,%2,%3};"
        : "+f"(d[0]), "+f"(d[1]), "+f"(d[2]), "+f"(d[3])
        : "r"(a[0]), "r"(a[1]), "r"(a[2]), "r"(a[3]), "r"(b[0]), "r"(b[1]));
}
__device__ __forceinline__ void split2(float a, float b,
                                       __nv_bfloat162& h, __nv_bfloat162& l) {
    __nv_bfloat16 ha = __float2bfloat16(a), hb = __float2bfloat16(b);
    h = __halves2bfloat162(ha, hb);
    l = __halves2bfloat162(__float2bfloat16(a - __bfloat162float(ha)),
                           __float2bfloat16(b - __bfloat162float(hb)));
}

// ---------------- GEMM smem layout (bytes), tile 128x128, BK=32 -------------
// per stage: A[128][40] | B[32][136]   (fp16, single precision each)
#define A_B        10240         // 128*40*2
#define B_B        8704          // 32*136*2
#define OFF_B      A_B
#define STAGE_B    (A_B + B_B)                     // 18944
#define NSTAGE     3
#define GEMM_SMEM  (NSTAGE * STAGE_B)              // 56832

// ---------------- fp16 single-term tensor-core GEMM (2 CTAs/SM) -------------
__global__ __launch_bounds__(256, 2) void mma_gemm(
    const __half* __restrict__ A, const __half* __restrict__ B,
    float* __restrict__ C, int M, int N, int K, int ldb, int ldc)
{
    extern __shared__ __half smem[];
    const uint32_t sbase = s2u(smem);
    const int rowBase = blockIdx.y * 128;
    const int colBase = blockIdx.x * 128;
    const int t = threadIdx.x;

    const int ar = t >> 2, aq = t & 3;
    const __half* aS = A + (size_t)(rowBase + ar) * K + aq * 8;
    const uint32_t aD = sbase + (ar * 40 + aq * 8) * 2;
    const int br = t >> 4, bq = t & 15;
    const __half* bS = B + (size_t)br * ldb + colBase + bq * 8;
    const uint32_t bD = sbase + OFF_B + (br * 136 + bq * 8) * 2;

    const int lane = t & 31, warp = t >> 5;
    const int wm = warp >> 2, wn = warp & 3;
    const int grp = lane >> 3, rr = lane & 7;

    uint32_t aAddr[4], bAddr[2];
#pragma unroll
    for (int mi = 0; mi < 4; mi++)
        aAddr[mi] = sbase + ((wm * 64 + mi * 16 + (grp & 1) * 8 + rr) * 40
                             + (grp >> 1) * 8) * 2;
#pragma unroll
    for (int pi = 0; pi < 2; pi++)
        bAddr[pi] = sbase + OFF_B + (((grp & 1) * 8 + rr) * 136
                             + wn * 32 + pi * 16 + (grp >> 1) * 8) * 2;

    float d[4][4][4];
#pragma unroll
    for (int mi = 0; mi < 4; mi++)
#pragma unroll
        for (int ni = 0; ni < 4; ni++)
#pragma unroll
            for (int k = 0; k < 4; k++) d[mi][ni][k] = 0.f;

    const int nk = K / 32;

#define LOAD_SLAB(st, kt) do {                                                  \
    const uint32_t _d = (st) * STAGE_B;                                         \
    const int _k = (kt) * 32;                                                   \
    CP16(aD + _d, aS + _k);                                                     \
    CP16(aD + _d + 64 * 40 * 2, aS + (size_t)64 * K + _k);                      \
    CP16(bD + _d, bS + (size_t)_k * ldb);                                       \
    CP16(bD + _d + 16 * 136 * 2, bS + (size_t)(_k + 16) * ldb);                 \
} while (0)

#define FRAGS_MMA(sd, koff_a, koff_b) do {                                      \
    uint32_t a_f[4][4], b_f[4][2];                                              \
    _Pragma("unroll")                                                           \
    for (int mi = 0; mi < 4; mi++)                                              \
        ldsm4(a_f[mi][0], a_f[mi][1], a_f[mi][2], a_f[mi][3],                   \
              aAddr[mi] + (sd) + (koff_a));                                     \
    _Pragma("unroll")                                                           \
    for (int pi = 0; pi < 2; pi++)                                              \
        ldsm4t(b_f[2*pi][0], b_f[2*pi][1], b_f[2*pi+1][0], b_f[2*pi+1][1],      \
               bAddr[pi] + (sd) + (koff_b));                                    \
    _Pragma("unroll")                                                           \
    for (int mi = 0; mi < 4; mi++)                                              \
        _Pragma("unroll")                                                       \
        for (int ni = 0; ni < 4; ni++)                                          \
            mma16816h(d[mi][ni], a_f[mi], b_f[ni]);                             \
} while (0)

    LOAD_SLAB(0, 0); CP_COMMIT();
    LOAD_SLAB(1, 1); CP_COMMIT();
    CP_WAIT1();
    __syncthreads();

    for (int kt = 0; kt < nk; kt++) {
        const uint32_t sd = (uint32_t)(kt % 3) * STAGE_B;
        if (kt + 2 < nk) LOAD_SLAB((kt + 2) % 3, kt + 2);
        CP_COMMIT();
        FRAGS_MMA(sd, 0, 0);
        FRAGS_MMA(sd, 32, 16 * 136 * 2);
        if (kt + 1 < nk) {
            CP_WAIT1();
            __syncthreads();
        }
    }

    const int r0 = rowBase + wm * 64 + (lane >> 2);
    const int c0 = colBase + wn * 32 + (lane & 3) * 2;
#pragma unroll
    for (int mi = 0; mi < 4; mi++)
#pragma unroll
        for (int ni = 0; ni < 4; ni++) {
            int col = c0 + ni * 8;
            if (col < N) {
                float2 v0 = make_float2(d[mi][ni][0], d[mi][ni][1]);
                float2 v1 = make_float2(d[mi][ni][2], d[mi][ni][3]);
                *(float2*)&C[(size_t)(r0 + mi * 16) * ldc + col] = v0;
                *(float2*)&C[(size_t)(r0 + mi * 16 + 8) * ldc + col] = v1;
            }
        }
#undef LOAD_SLAB
#undef FRAGS_MMA
}

// ---------------- CB gram via mma: CB[l,s] = sum_n C[l,n] B[s,n] ------------
#define CB_AH    0
#define CB_AL    17408               // 64*136*2
#define CB_BH    34816
#define CB_BL    52224
#define CB_SMEM  69632

__global__ __launch_bounds__(256, 2) void cb_mma_kernel()
{
    extern __shared__ char csm[];
    __nv_bfloat16* Ah = (__nv_bfloat16*)(csm + CB_AH);
    __nv_bfloat16* Al = (__nv_bfloat16*)(csm + CB_AL);
    __nv_bfloat16* Bh = (__nv_bfloat16*)(csm + CB_BH);
    __nv_bfloat16* Bl = (__nv_bfloat16*)(csm + CB_BL);

    const int bc = blockIdx.x, lt = blockIdx.y;
    const int b = bc >> 4, c = bc & 15;
    const int t = threadIdx.x;
    const size_t rowB = (size_t)b * SEQLEN + c * CHUNK;

    const int lane = t & 31, warp = t >> 5;
    const int wm = warp >> 2, wn = warp & 3;
    const int grp = lane >> 3, rr = lane & 7;
    const uint32_t ahB = s2u(Ah), alB = s2u(Al), bhB = s2u(Bh), blB = s2u(Bl);

    {
        const int r = t >> 2, q = (t & 3) * 32;
        const float* cr = g_xBC + (rowB + lt * 64 + r) * CONVDIM
                          + (DINNER + DSTATE) + q;
        __nv_bfloat162* ah2 = (__nv_bfloat162*)(Ah + r * 136 + q);
        __nv_bfloat162* al2 = (__nv_bfloat162*)(Al + r * 136 + q);
#pragma unroll
        for (int j = 0; j < 32; j += 4) {
            float4 v = *(const float4*)(cr + j);
            __nv_bfloat162 h01, l01, h23, l23;
            split2(v.x, v.y, h01, l01);
            split2(v.z, v.w, h23, l23);
            ah2[(j >> 1) + 0] = h01; ah2[(j >> 1) + 1] = h23;
            al2[(j >> 1) + 0] = l01; al2[(j >> 1) + 1] = l23;
        }
    }

    uint32_t aOff[2];
#pragma unroll
    for (int mi = 0; mi < 2; mi++)
        aOff[mi] = ((wm * 32 + mi * 16 + (grp & 1) * 8 + rr) * 136
                    + (grp >> 1) * 8) * 2;
    const uint32_t bOff = ((wn * 16 + (grp & 1) * 8 + rr) * 136
                           + (grp >> 1) * 8) * 2;

    float d[2][8][4];
#pragma unroll
    for (int mi = 0; mi < 2; mi++)
#pragma unroll
        for (int ni = 0; ni < 8; ni++)
#pragma unroll
            for (int k = 0; k < 4; k++) d[mi][ni][k] = 0.f;

    for (int stile = 0; stile < 4; stile++) {
        {
            const int r = t >> 2, q = (t & 3) * 32;
            const float* br = g_xBC + (rowB + stile * 64 + r) * CONVDIM
                              + DINNER + q;
            __nv_bfloat162* bh2 = (__nv_bfloat162*)(Bh + r * 136 + q);
            __nv_bfloat162* bl2 = (__nv_bfloat162*)(Bl + r * 136 + q);
#pragma unroll
            for (int j = 0; j < 32; j += 4) {
                float4 v = *(const float4*)(br + j);
                __nv_bfloat162 h01, l01, h23, l23;
                split2(v.x, v.y, h01, l01);
                split2(v.z, v.w, h23, l23);
                bh2[(j >> 1) + 0] = h01; bh2[(j >> 1) + 1] = h23;
                bl2[(j >> 1) + 0] = l01; bl2[(j >> 1) + 1] = l23;
            }
        }
        __syncthreads();
#pragma unroll
        for (int k = 0; k < 8; k++) {
            const uint32_t ko = k * 32;
            uint32_t a_h[2][4], a_l[2][4], b4h[4], b4l[4];
#pragma unroll
            for (int mi = 0; mi < 2; mi++) {
                ldsm4(a_h[mi][0], a_h[mi][1], a_h[mi][2], a_h[mi][3],
                      ahB + aOff[mi] + ko);
                ldsm4(a_l[mi][0], a_l[mi][1], a_l[mi][2], a_l[mi][3],
                      alB + aOff[mi] + ko);
            }
            ldsm4(b4h[0], b4h[1], b4h[2], b4h[3], bhB + bOff + ko);
            ldsm4(b4l[0], b4l[1], b4l[2], b4l[3], blB + bOff + ko);
            uint32_t bh0[2] = {b4h[0], b4h[2]};
            uint32_t bh1[2] = {b4h[1], b4h[3]};
            uint32_t bl0[2] = {b4l[0], b4l[2]};
            uint32_t bl1[2] = {b4l[1], b4l[3]};
#pragma unroll
            for (int mi = 0; mi < 2; mi++) {
                mma16816(d[mi][stile * 2 + 0], a_h[mi], bh0);
                mma16816(d[mi][stile * 2 + 0], a_h[mi], bl0);
                mma16816(d[mi][stile * 2 + 0], a_l[mi], bh0);
                mma16816(d[mi][stile * 2 + 1], a_h[mi], bh1);
                mma16816(d[mi][stile * 2 + 1], a_h[mi], bl1);
                mma16816(d[mi][stile * 2 + 1], a_l[mi], bh1);
            }
        }
        __syncthreads();
    }

    const int r0 = lt * 64 + wm * 32 + (lane >> 2);
    const int c0 = (lane & 3) * 2;
#pragma unroll
    for (int mi = 0; mi < 2; mi++) {
        float* out0 = g_CB + ((size_t)bc * CHUNK + r0 + mi * 16) * CHUNK;
        float* out1 = out0 + 8 * CHUNK;
#pragma unroll
        for (int st = 0; st < 4; st++)
#pragma unroll
            for (int q = 0; q < 2; q++) {
                int col = st * 64 + wn * 16 + q * 8 + c0;
                float* dd = d[mi][st * 2 + q];
                *(float2*)&out0[col] = make_float2(dd[0], dd[1]);
                *(float2*)&out1[col] = make_float2(dd[2], dd[3]);
            }
    }
}

// ---------------- fused Y = (CB.L)X + exp(acs) C Sinit (bf16 3-term) --------
#define YF_WH    0
#define YF_WL    36864
#define YF_XH    73728
#define YF_XL    82944
#define YF_ACS   92160
#define YF_DT    93184
#define YF_SMEM  94208

__global__ __launch_bounds__(256, 2) void yfused_kernel()
{
    extern __shared__ char ysm[];
    __nv_bfloat16* Wh = (__nv_bfloat16*)(ysm + YF_WH);
    __nv_bfloat16* Wl = (__nv_bfloat16*)(ysm + YF_WL);
    __nv_bfloat16* Xh = (__nv_bfloat16*)(ysm + YF_XH);
    __nv_bfloat16* Xl = (__nv_bfloat16*)(ysm + YF_XL);
    float* sacs = (float*)(ysm + YF_ACS);
    float* sdt  = (float*)(ysm + YF_DT);

    const int bc = blockIdx.x, h = blockIdx.y;
    const int b = bc >> 4, c = bc & 15;
    const int t = threadIdx.x;
    const size_t rowB = (size_t)b * SEQLEN + c * CHUNK;

    sacs[t] = g_acs[((size_t)bc * NHEADS + h) * CHUNK + t];
    sdt[t]  = g_dt[(rowB + t) * NHEADS + h];
    __syncthreads();
    const float acs_l = sacs[t];

    const int lane = t & 31, warp = t >> 5;
    const int grp = lane >> 3, rr = lane & 7;
    const uint32_t whB = s2u(Wh), wlB = s2u(Wl), xhB = s2u(Xh), xlB = s2u(Xl);

    uint32_t aOff[2], bOff[4];
#pragma unroll
    for (int mi = 0; mi < 2; mi++)
        aOff[mi] = ((warp * 32 + mi * 16 + (grp & 1) * 8 + rr) * 72
                    + (grp >> 1) * 8) * 2;
#pragma unroll
    for (int pi = 0; pi < 4; pi++)
        bOff[pi] = (((grp & 1) * 8 + rr) * 72 + pi * 16 + (grp >> 1) * 8) * 2;

    float d[2][8][4];
#pragma unroll
    for (int mi = 0; mi < 2; mi++)
#pragma unroll
        for (int ni = 0; ni < 8; ni++)
#pragma unroll
            for (int k = 0; k < 4; k++) d[mi][ni][k] = 0.f;

#define YF_MMA() do {                                                           \
    _Pragma("unroll")                                                           \
    for (int k = 0; k < 4; k++) {                                               \
        const uint32_t ka = k * 32;                                             \
        const uint32_t kb = k * 16 * 144;                                       \
        uint32_t a_h[2][4], a_l[2][4];                                          \
        _Pragma("unroll")                                                       \
        for (int mi = 0; mi < 2; mi++) {                                        \
            ldsm4(a_h[mi][0], a_h[mi][1], a_h[mi][2], a_h[mi][3],               \
                  whB + aOff[mi] + ka);                                         \
            ldsm4(a_l[mi][0], a_l[mi][1], a_l[mi][2], a_l[mi][3],               \
                  wlB + aOff[mi] + ka);                                         \
        }                                                                       \
        _Pragma("unroll")                                                       \
        for (int pi = 0; pi < 4; pi++) {                                        \
            uint32_t bh[2][2], bl[2][2];                                        \
            ldsm4t(bh[0][0], bh[0][1], bh[1][0], bh[1][1],                      \
                   xhB + bOff[pi] + kb);                                        \
            ldsm4t(bl[0][0], bl[0][1], bl[1][0], bl[1][1],                      \
                   xlB + bOff[pi] + kb);                                        \
            _Pragma("unroll")                                                   \
            for (int mi = 0; mi < 2; mi++)                                      \
                _Pragma("unroll")                                               \
                for (int q = 0; q < 2; q++) {                                   \
                    mma16816(d[mi][2*pi+q], a_h[mi], bh[q]);                    \
                    mma16816(d[mi][2*pi+q], a_h[mi], bl[q]);                    \
                    mma16816(d[mi][2*pi+q], a_l[mi], bh[q]);                    \
                }                                                               \
        }                                                                       \
    }                                                                           \
} while (0)

    const float* CBrow = g_CB + ((size_t)bc * CHUNK + t) * CHUNK;
    for (int st = 0; st < 4; st++) {
        const int s0 = st * 64;
        __nv_bfloat162* wh2 = (__nv_bfloat162*)(Wh + t * 72);
        __nv_bfloat162* wl2 = (__nv_bfloat162*)(Wl + t * 72);
#pragma unroll
        for (int j = 0; j < 64; j += 4) {
            float4 cb4 = *(const float4*)(CBrow + s0 + j);
            float w[4];
            const float* cbp = (const float*)&cb4;
#pragma unroll
            for (int e = 0; e < 4; e++) {
                int s = s0 + j + e;
                float arg = fminf(acs_l - sacs[s], 0.f);
                w[e] = (s <= t) ? cbp[e] * __expf(arg) : 0.f;
            }
            __nv_bfloat162 h01, l01, h23, l23;
            split2(w[0], w[1], h01, l01);
            split2(w[2], w[3], h23, l23);
            wh2[(j >> 1) + 0] = h01; wh2[(j >> 1) + 1] = h23;
            wl2[(j >> 1) + 0] = l01; wl2[(j >> 1) + 1] = l23;
        }
        {
            const int r = t >> 2, c16 = (t & 3) * 16;
            const float dts = sdt[s0 + r];
            const float* xr = g_xBC + (rowB + s0 + r) * CONVDIM + h * HEADDIM + c16;
            __nv_bfloat162* xh2 = (__nv_bfloat162*)(Xh + r * 72 + c16);
            __nv_bfloat162* xl2 = (__nv_bfloat162*)(Xl + r * 72 + c16);
#pragma unroll
            for (int j = 0; j < 16; j += 4) {
                float4 v = *(const float4*)(xr + j);
                __nv_bfloat162 h01, l01, h23, l23;
                split2(v.x * dts, v.y * dts, h01, l01);
                split2(v.z * dts, v.w * dts, h23, l23);
                xh2[(j >> 1) + 0] = h01; xh2[(j >> 1) + 1] = h23;
                xl2[(j >> 1) + 0] = l01; xl2[(j >> 1) + 1] = l23;
            }
        }
        __syncthreads();
        YF_MMA();
        __syncthreads();
    }

    const float el = __expf(acs_l);
    const float* Crow = g_xBC + (rowB + t) * CONVDIM + DINNER + DSTATE;
    const float* S0p = g_Sinit + ((size_t)bc * NHEADS + h) * (HEADDIM * DSTATE);
    for (int nt = 0; nt < 2; nt++) {
        const int n0 = nt * 64;
        __nv_bfloat162* wh2 = (__nv_bfloat162*)(Wh + t * 72);
        __nv_bfloat162* wl2 = (__nv_bfloat162*)(Wl + t * 72);
#pragma unroll
        for (int j = 0; j < 64; j += 4) {
            float4 c4 = *(const float4*)(Crow + n0 + j);
            __nv_bfloat162 h01, l01, h23, l23;
            split2(c4.x * el, c4.y * el, h01, l01);
            split2(c4.z * el, c4.w * el, h23, l23);
            wh2[(j >> 1) + 0] = h01; wh2[(j >> 1) + 1] = h23;
            wl2[(j >> 1) + 0] = l01; wl2[(j >> 1) + 1] = l23;
        }
        {
            const int p = t >> 2, nb = (t & 3) * 16;
            const float* sp = S0p + (size_t)p * DSTATE + n0 + nb;
#pragma unroll
            for (int j = 0; j < 16; j++) {
                float v = sp[j];
                __nv_bfloat16 hh = __float2bfloat16(v);
                Xh[(nb + j) * 72 + p] = hh;
                Xl[(nb + j) * 72 + p] = __float2bfloat16(v - __bfloat162float(hh));
            }
        }
        __syncthreads();
        YF_MMA();
        __syncthreads();
    }
#undef YF_MMA

    const int c0 = (lane & 3) * 2;
#pragma unroll
    for (int mi = 0; mi < 2; mi++) {
        const size_t gr0 = (rowB + warp * 32 + (lane >> 2) + mi * 16) * DINNER + h * HEADDIM;
#pragma unroll
        for (int ni = 0; ni < 8; ni++) {
            int col = c0 + ni * 8;
            *(float2*)&g_Y[gr0 + col] = make_float2(d[mi][ni][0], d[mi][ni][1]);
            *(float2*)&g_Y[gr0 + 8 * DINNER + col] = make_float2(d[mi][ni][2], d[mi][ni][3]);
        }
    }
}

// ---------------- state S[64p x 128n] = x^T . (w.B), bf16 3-term mma --------
#define ST_AH    0
#define ST_AL    9216
#define ST_BH    18432
#define ST_BL    35840
#define ST_SMEM  53248

__global__ __launch_bounds__(256, 2) void state_mma_kernel()
{
    extern __shared__ char ssm[];
    __nv_bfloat16* Ah = (__nv_bfloat16*)(ssm + ST_AH);
    __nv_bfloat16* Al = (__nv_bfloat16*)(ssm + ST_AL);
    __nv_bfloat16* Bh = (__nv_bfloat16*)(ssm + ST_BH);
    __nv_bfloat16* Bl = (__nv_bfloat16*)(ssm + ST_BL);

    const int bc = blockIdx.x, h = blockIdx.y;
    const int b = bc >> 4, c = bc & 15;
    const int t = threadIdx.x;
    const size_t rowB = (size_t)b * SEQLEN + c * CHUNK;
    const float asum = g_asum[bc * NHEADS + h];
    const float* acsp = g_acs + ((size_t)bc * NHEADS + h) * CHUNK;

    const int lane = t & 31, warp = t >> 5;
    const int wm = warp >> 2, wn = warp & 3;
    const int grp = lane >> 3, rr = lane & 7;
    const uint32_t ahB = s2u(Ah), alB = s2u(Al), bhB = s2u(Bh), blB = s2u(Bl);

    uint32_t aOff[2], bOff[2];
#pragma unroll
    for (int mi = 0; mi < 2; mi++)
        aOff[mi] = ((wm * 32 + mi * 16 + (grp & 1) * 8 + rr) * 72
                    + (grp >> 1) * 8) * 2;
#pragma unroll
    for (int pi = 0; pi < 2; pi++)
        bOff[pi] = (((grp & 1) * 8 + rr) * 136
                    + wn * 32 + pi * 16 + (grp >> 1) * 8) * 2;

    float d[2][4][4];
#pragma unroll
    for (int mi = 0; mi < 2; mi++)
#pragma unroll
        for (int ni = 0; ni < 4; ni++)
#pragma unroll
            for (int k = 0; k < 4; k++) d[mi][ni][k] = 0.f;

    for (int st4 = 0; st4 < 4; st4++) {
        const int s0 = st4 * 64;
        const int r = t >> 2;
        const float w = g_dt[(rowB + s0 + r) * NHEADS + h] *
                        __expf(asum - acsp[s0 + r]);
        {
            const int q = (t & 3) * 16;
            const float* xr = g_xBC + (rowB + s0 + r) * CONVDIM + h * HEADDIM + q;
#pragma unroll
            for (int j = 0; j < 16; j += 4) {
                float4 v = *(const float4*)(xr + j);
                float vals[4] = {v.x, v.y, v.z, v.w};
#pragma unroll
                for (int e = 0; e < 4; e++) {
                    __nv_bfloat16 hh = __float2bfloat16(vals[e]);
                    Ah[(q + j + e) * 72 + r] = hh;
                    Al[(q + j + e) * 72 + r] =
                        __float2bfloat16(vals[e] - __bfloat162float(hh));
                }
            }
        }
        {
            const int nq = (t & 3) * 32;
            const float* brp = g_xBC + (rowB + s0 + r) * CONVDIM + DINNER + nq;
            __nv_bfloat162* bh2 = (__nv_bfloat162*)(Bh + r * 136 + nq);
            __nv_bfloat162* bl2 = (__nv_bfloat162*)(Bl + r * 136 + nq);
#pragma unroll
            for (int j = 0; j < 32; j += 4) {
                float4 v = *(const float4*)(brp + j);
                __nv_bfloat162 h01, l01, h23, l23;
                split2(v.x * w, v.y * w, h01, l01);
                split2(v.z * w, v.w * w, h23, l23);
                bh2[(j >> 1) + 0] = h01; bh2[(j >> 1) + 1] = h23;
                bl2[(j >> 1) + 0] = l01; bl2[(j >> 1) + 1] = l23;
            }
        }
        __syncthreads();
#pragma unroll
        for (int k = 0; k < 4; k++) {
            const uint32_t ka = k * 32;
            const uint32_t kb = (uint32_t)k * 16 * 136 * 2;
            uint32_t a_h[2][4], a_l[2][4], bhf[4][2], blf[4][2];
#pragma unroll
            for (int mi = 0; mi < 2; mi++) {
                ldsm4(a_h[mi][0], a_h[mi][1], a_h[mi][2], a_h[mi][3],
                      ahB + aOff[mi] + ka);
                ldsm4(a_l[mi][0], a_l[mi][1], a_l[mi][2], a_l[mi][3],
                      alB + aOff[mi] + ka);
            }
#pragma unroll
            for (int pi = 0; pi < 2; pi++) {
                ldsm4t(bhf[2*pi][0], bhf[2*pi][1], bhf[2*pi+1][0], bhf[2*pi+1][1],
                       bhB + bOff[pi] + kb);
                ldsm4t(blf[2*pi][0], blf[2*pi][1], blf[2*pi+1][0], blf[2*pi+1][1],
                       blB + bOff[pi] + kb);
            }
#pragma unroll
            for (int mi = 0; mi < 2; mi++)
#pragma unroll
                for (int ni = 0; ni < 4; ni++) {
                    mma16816(d[mi][ni], a_h[mi], bhf[ni]);
                    mma16816(d[mi][ni], a_h[mi], blf[ni]);
                    mma16816(d[mi][ni], a_l[mi], bhf[ni]);
                }
        }
        __syncthreads();
    }

    float* Sout = g_S + ((size_t)bc * NHEADS + h) * (HEADDIM * DSTATE);
    const int p0 = wm * 32 + (lane >> 2);
    const int n0 = wn * 32 + (lane & 3) * 2;
#pragma unroll
    for (int mi = 0; mi < 2; mi++)
#pragma unroll
        for (int ni = 0; ni < 4; ni++) {
            int col = n0 + ni * 8;
            *(float2*)&Sout[(size_t)(p0 + mi * 16) * DSTATE + col] =
                make_float2(d[mi][ni][0], d[mi][ni][1]);
            *(float2*)&Sout[(size_t)(p0 + mi * 16 + 8) * DSTATE + col] =
                make_float2(d[mi][ni][2], d[mi][ni][3]);
        }
}

// ---------------- convert kernels -------------------------------------------
__global__ void tofp16_kernel(const float* __restrict__ x, __half* __restrict__ o, size_t n)
{
    size_t i = (size_t)blockIdx.x * blockDim.x + threadIdx.x;
    if (i >= n) return;
    o[i] = __float2half(x[i]);
}

__global__ void tofp16_pad_kernel(const float* __restrict__ x, __half* __restrict__ o,
                                  int K, int N, int Np)
{
    size_t i = (size_t)blockIdx.x * blockDim.x + threadIdx.x;
    if (i >= (size_t)K * Np) return;
    int r = (int)(i / Np), c = (int)(i % Np);
    o[i] = __float2half((c < N) ? x[(size_t)r * N + c] : 0.f);
}

// ---------------- causal conv1d + SiLU: 4 outputs per thread ----------------
__global__ void conv_silu_kernel(const float* __restrict__ conv_w,
                                 const float* __restrict__ conv_b)
{
    int idx = blockIdx.x * blockDim.x + threadIdx.x;
    if (idx >= (ROWS / 4) * CONVDIM) return;
    int c  = idx % CONVDIM;
    int rg = idx / CONVDIM;
    int row0 = rg * 4;
    int l0 = row0 & (SEQLEN - 1);
    const float* base = g_zxbcdt + (size_t)row0 * DPROJ + DINNER + c;
    const float w0 = conv_w[c * DCONV + 0], w1 = conv_w[c * DCONV + 1];
    const float w2 = conv_w[c * DCONV + 2], w3 = conv_w[c * DCONV + 3];
    const float bias = conv_b[c];
    float v[7];
#pragma unroll
    for (int j = 0; j < 7; j++) {
        int l = l0 - 3 + j;
        v[j] = (l >= 0) ? base[(long)(j - 3) * DPROJ] : 0.f;
    }
#pragma unroll
    for (int i = 0; i < 4; i++) {
        float acc = bias + v[i] * w0 + v[i+1] * w1 + v[i+2] * w2 + v[i+3] * w3;
        g_xBC[(size_t)(row0 + i) * CONVDIM + c] = acc / (1.f + __expf(-acc));
    }
}

// ---------------- dt = softplus(dt_raw + dt_bias) --------------------------
__global__ void dt_kernel(const float* __restrict__ dt_bias)
{
    int idx = blockIdx.x * blockDim.x + threadIdx.x;
    if (idx >= ROWS * NHEADS) return;
    int h   = idx & (NHEADS - 1);
    int row = idx >> 5;
    float v = g_zxbcdt[(size_t)row * DPROJ + DT_OFF + h] + dt_bias[h];
    g_dt[idx] = (v > 20.f) ? v : log1pf(expf(v));
}

// ---------------- per-chunk inclusive cumsum of a = A*dt -------------------
__global__ void ascan_kernel(const float* __restrict__ A_log)
{
    int bc = blockIdx.x;
    int h  = blockIdx.y;
    int t  = threadIdx.x;
    int b = bc >> 4, c = bc & 15;
    __shared__ float sa[CHUNK];
    int row = b * SEQLEN + c * CHUNK + t;
    float A = -expf(A_log[h]);
    sa[t] = A * g_dt[row * NHEADS + h];
    __syncthreads();
    for (int off = 1; off < CHUNK; off <<= 1) {
        float v = (t >= off) ? sa[t - off] : 0.f;
        __syncthreads();
        sa[t] += v;
        __syncthreads();
    }
    g_acs[(bc * NHEADS + h) * CHUNK + t] = sa[t];
    if (t == CHUNK - 1) g_asum[bc * NHEADS + h] = sa[t];
}

// ---------------- sequential inter-chunk recurrence ------------------------
__global__ void chunkrec_kernel()
{
    int b = blockIdx.x, h = blockIdx.y;
    int t = threadIdx.x;
    float cur[32];
#pragma unroll
    for (int k = 0; k < 32; k++) cur[k] = 0.f;
    for (int c = 0; c < NCHUNK; c++) {
        int bc = b * NCHUNK + c;
        size_t base = ((size_t)bc * NHEADS + h) * (HEADDIM * DSTATE);
        float dd = __expf(g_asum[bc * NHEADS + h]);
#pragma unroll
        for (int k = 0; k < 32; k++) {
            size_t e = base + t + 256 * k;
            g_Sinit[e] = cur[k];
            cur[k] = cur[k] * dd + g_S[e];
        }
    }
}

// ---------------- layernorm + z-gate -> fp16 yg ----------------------------
__global__ __launch_bounds__(256) void normgate_kernel(const float* __restrict__ norm_w)
{
    int row = blockIdx.x;
    int t = threadIdx.x;
    const float* yrow = g_Y + (size_t)row * DINNER;
    const float* zrow = g_zxbcdt + (size_t)row * DPROJ;
    float v[8];
    float s = 0.f;
#pragma unroll
    for (int i = 0; i < 8; i++) { v[i] = yrow[t + 256*i]; s += v[i]; }
    __shared__ float red[256];
    red[t] = s; __syncthreads();
    for (int o = 128; o > 0; o >>= 1) { if (t < o) red[t] += red[t+o]; __syncthreads(); }
    float mu = red[0] * (1.f / DINNER);
    __syncthreads();
    float s2 = 0.f;
#pragma unroll
    for (int i = 0; i < 8; i++) { float dv = v[i] - mu; s2 += dv * dv; }
    red[t] = s2; __syncthreads();
    for (int o = 128; o > 0; o >>= 1) { if (t < o) red[t] += red[t+o]; __syncthreads(); }
    float inv = rsqrtf(red[0] * (1.f / DINNER) + 1e-5f);
    __half* orow = g_yg + (size_t)row * DINNER;
#pragma unroll
    for (int i = 0; i < 8; i++) {
        int idx = t + 256*i;
        float z = zrow[idx];
        float g = z / (1.f + __expf(-z));
        orow[idx] = __float2half((v[i] - mu) * inv * norm_w[idx] * g);
    }
}

// ---------------- launch ---------------------------------------------------
extern "C" void kernel_launch(void* const* d_in, const int* in_sizes, int n_in,
                              void* d_out, int out_size)
{
    const float* u       = (const float*)d_in[0];
    const float* W_in    = (const float*)d_in[1];
    const float* conv_w  = (const float*)d_in[2];
    const float* conv_b  = (const float*)d_in[3];
    const float* dt_bias = (const float*)d_in[4];
    const float* A_log   = (const float*)d_in[5];
    const float* norm_w  = (const float*)d_in[6];
    const float* W_out   = (const float*)d_in[7];
    float* out = (float*)d_out;

    float* p_zx = nullptr;
    __half *p_uf, *p_wif, *p_wof, *p_yg;
    cudaGetSymbolAddress((void**)&p_zx,  g_zxbcdt);
    cudaGetSymbolAddress((void**)&p_uf,  g_uf);
    cudaGetSymbolAddress((void**)&p_wif, g_wif);
    cudaGetSymbolAddress((void**)&p_wof, g_wof);
    cudaGetSymbolAddress((void**)&p_yg,  g_yg);

    cudaFuncSetAttribute(mma_gemm, cudaFuncAttributeMaxDynamicSharedMemorySize, GEMM_SMEM);
    cudaFuncSetAttribute(yfused_kernel, cudaFuncAttributeMaxDynamicSharedMemorySize, YF_SMEM);
    cudaFuncSetAttribute(state_mma_kernel, cudaFuncAttributeMaxDynamicSharedMemorySize, ST_SMEM);
    cudaFuncSetAttribute(cb_mma_kernel, cudaFuncAttributeMaxDynamicSharedMemorySize, CB_SMEM);

    // 0. fp16 conversions
    {
        size_t n = (size_t)ROWS * DMODEL;
        tofp16_kernel<<<(unsigned)((n + 255) / 256), 256>>>(u, p_uf, n);
    }
    tofp16_pad_kernel<<<(unsigned)(((size_t)DMODEL * NPAD1 + 255) / 256), 256>>>(
        W_in, p_wif, DMODEL, DPROJ, NPAD1);
    {
        size_t n = (size_t)DINNER * DMODEL;
        tofp16_kernel<<<(unsigned)((n + 255) / 256), 256>>>(W_out, p_wof, n);
    }

    // 1. zxbcdt = u @ W_in  (8192 x 4384 x 1024)
    mma_gemm<<<dim3(NPAD1 / 128, ROWS / 128), 256, GEMM_SMEM>>>(
        p_uf, p_wif, p_zx, ROWS, DPROJ, DMODEL, NPAD1, DPROJ);
    // 2. causal conv1d + SiLU (4 l per thread)
    conv_silu_kernel<<<((ROWS / 4) * CONVDIM + 255) / 256, 256>>>(conv_w, conv_b);
    // 3. dt softplus
    dt_kernel<<<(ROWS * NHEADS + 255) / 256, 256>>>(dt_bias);
    // 4. per-chunk cumsum of A*dt
    ascan_kernel<<<dim3(NBC, NHEADS), CHUNK>>>(A_log);
    // 5. CB gram matrices (tensor cores)
    cb_mma_kernel<<<dim3(NBC, 4), 256, CB_SMEM>>>();
    // 6. per-chunk end states (tensor cores)
    state_mma_kernel<<<dim3(NBC, NHEADS), 256, ST_SMEM>>>();
    // 7. inter-chunk recurrence
    chunkrec_kernel<<<dim3(BATCH, NHEADS), 256>>>();
    // 8. fused Y_diag + Y_off (tensor cores)
    yfused_kernel<<<dim3(NBC, NHEADS), 256, YF_SMEM>>>();
    // 9. layernorm + silu(z) gate -> fp16
    normgate_kernel<<<ROWS, 256>>>(norm_w);
    // 10. out = yg @ W_out  (8192 x 1024 x 2048)
    mma_gemm<<<dim3(DMODEL / 128, ROWS / 128), 256, GEMM_SMEM>>>(
        p_yg, p_wof, out, ROWS, DMODEL, DINNER, DMODEL, DMODEL);
}

// round 13
// speedup vs baseline: 1.7134x; 1.0868x over previous
#include <cuda_runtime.h>
#include <cuda_bf16.h>
#include <cuda_fp16.h>
#include <math.h>
#include <stdint.h>

#define BATCH   2
#define SEQLEN  4096
#define DMODEL  1024
#define DINNER  2048
#define HEADDIM 64
#define NHEADS  32
#define DSTATE  128
#define DCONV   4
#define CHUNK   256
#define NCHUNK  (SEQLEN / CHUNK)   // 16
#define NBC     (BATCH * NCHUNK)   // 32
#define DPROJ   4384               // 2*DINNER + 2*DSTATE + NHEADS
#define CONVDIM 2304               // DINNER + 2*DSTATE
#define DT_OFF  4352               // 2*DINNER + 2*DSTATE
#define ROWS    (BATCH * SEQLEN)   // 8192
#define NPAD1   4480               // DPROJ padded to multiple of 128

// ---------------- scratch (device globals; no allocation allowed) ----------
__device__ float g_zxbcdt[(size_t)ROWS * DPROJ];
__device__ float g_xBC[(size_t)ROWS * CONVDIM];
__device__ float g_dt[ROWS * NHEADS];
__device__ float g_acs[NBC * NHEADS * CHUNK];
__device__ float g_asum[NBC * NHEADS];
__device__ float g_CB[(size_t)NBC * CHUNK * CHUNK];
__device__ float g_Y[(size_t)ROWS * DINNER];
__device__ float g_S[(size_t)NBC * NHEADS * HEADDIM * DSTATE];
__device__ float g_Sinit[(size_t)NBC * NHEADS * HEADDIM * DSTATE];

// fp16 GEMM operands (all single precision fp16)
__device__ __half g_uf[(size_t)ROWS * DMODEL];
__device__ __half g_wif[(size_t)DMODEL * NPAD1];
__device__ __half g_wof[(size_t)DINNER * DMODEL];
__device__ __half g_yg[(size_t)ROWS * DINNER];

// ---------------- helpers ---------------------------------------------------
__device__ __forceinline__ uint32_t s2u(const void* p) {
    return (uint32_t)__cvta_generic_to_shared(p);
}
#define CP16(dst, src) \
    asm volatile("cp.async.cg.shared.global [%0], [%1], 16;\n" :: "r"(dst), "l"(src))
#define CP_COMMIT() asm volatile("cp.async.commit_group;\n")
#define CP_WAIT1()  asm volatile("cp.async.wait_group 1;\n")

__device__ __forceinline__ void ldsm4(uint32_t& r0, uint32_t& r1, uint32_t& r2,
                                      uint32_t& r3, uint32_t addr) {
    asm volatile("ldmatrix.sync.aligned.m8n8.x4.shared.b16 {%0,%1,%2,%3}, [%4];"
                 : "=r"(r0), "=r"(r1), "=r"(r2), "=r"(r3) : "r"(addr));
}
__device__ __forceinline__ void ldsm4t(uint32_t& r0, uint32_t& r1, uint32_t& r2,
                                       uint32_t& r3, uint32_t addr) {
    asm volatile("ldmatrix.sync.aligned.m8n8.x4.trans.shared.b16 {%0,%1,%2,%3}, [%4];"
                 : "=r"(r0), "=r"(r1), "=r"(r2), "=r"(r3) : "r"(addr));
}
// fp16 mma
__device__ __forceinline__ void mma16816h(float* d, const uint32_t* a, const uint32_t* b) {
    asm volatile(
        "mma.sync.aligned.m16n8k16.row.col.f32.f16.f16.f32 "
        "{%0,%1,%2,%3}, {%4,%5,%6,%7}, {%8,%9}, {%0,%1,%2,%3};"
        : "+f"(d[0]), "+f"(d[1]), "+f"(d[2]), "+f"(d[3])
        : "r"(a[0]), "r"(a[1]), "r"(a[2]), "r"(a[3]), "r"(b[0]), "r"(b[1]));
}
// bf16 mma (cb)
__device__ __forceinline__ void mma16816(float* d, const uint32_t* a, const uint32_t* b) {
    asm volatile(
        "mma.sync.aligned.m16n8k16.row.col.f32.bf16.bf16.f32 "
        "{%0,%1,%2,%3}, {%4,%5,%6,%7}, {%8,%9}, {%0,%1,%2,%3};"
        : "+f"(d[0]), "+f"(d[1]), "+f"(d[2]), "+f"(d[3])
        : "r"(a[0]), "r"(a[1]), "r"(a[2]), "r"(a[3]), "r"(b[0]), "r"(b[1]));
}
__device__ __forceinline__ void split2(float a, float b,
                                       __nv_bfloat162& h, __nv_bfloat162& l) {
    __nv_bfloat16 ha = __float2bfloat16(a), hb = __float2bfloat16(b);
    h = __halves2bfloat162(ha, hb);
    l = __halves2bfloat162(__float2bfloat16(a - __bfloat162float(ha)),
                           __float2bfloat16(b - __bfloat162float(hb)));
}
__device__ __forceinline__ void split2h(float a, float b, __half2& h, __half2& l) {
    __half ha = __float2half(a), hb = __float2half(b);
    h = __halves2half2(ha, hb);
    l = __halves2half2(__float2half(a - __half2float(ha)),
                       __float2half(b - __half2float(hb)));
}

// ---------------- GEMM smem layout (bytes), tile 128x128, BK=32 -------------
#define A_B        10240         // 128*40*2
#define B_B        8704          // 32*136*2
#define OFF_B      A_B
#define STAGE_B    (A_B + B_B)                     // 18944
#define NSTAGE     3
#define GEMM_SMEM  (NSTAGE * STAGE_B)              // 56832

// ---------------- fp16 single-term tensor-core GEMM (2 CTAs/SM) -------------
__global__ __launch_bounds__(256, 2) void mma_gemm(
    const __half* __restrict__ A, const __half* __restrict__ B,
    float* __restrict__ C, int M, int N, int K, int ldb, int ldc)
{
    extern __shared__ __half smem[];
    const uint32_t sbase = s2u(smem);
    const int rowBase = blockIdx.y * 128;
    const int colBase = blockIdx.x * 128;
    const int t = threadIdx.x;

    const int ar = t >> 2, aq = t & 3;
    const __half* aS = A + (size_t)(rowBase + ar) * K + aq * 8;
    const uint32_t aD = sbase + (ar * 40 + aq * 8) * 2;
    const int br = t >> 4, bq = t & 15;
    const __half* bS = B + (size_t)br * ldb + colBase + bq * 8;
    const uint32_t bD = sbase + OFF_B + (br * 136 + bq * 8) * 2;

    const int lane = t & 31, warp = t >> 5;
    const int wm = warp >> 2, wn = warp & 3;
    const int grp = lane >> 3, rr = lane & 7;

    uint32_t aAddr[4], bAddr[2];
#pragma unroll
    for (int mi = 0; mi < 4; mi++)
        aAddr[mi] = sbase + ((wm * 64 + mi * 16 + (grp & 1) * 8 + rr) * 40
                             + (grp >> 1) * 8) * 2;
#pragma unroll
    for (int pi = 0; pi < 2; pi++)
        bAddr[pi] = sbase + OFF_B + (((grp & 1) * 8 + rr) * 136
                             + wn * 32 + pi * 16 + (grp >> 1) * 8) * 2;

    float d[4][4][4];
#pragma unroll
    for (int mi = 0; mi < 4; mi++)
#pragma unroll
        for (int ni = 0; ni < 4; ni++)
#pragma unroll
            for (int k = 0; k < 4; k++) d[mi][ni][k] = 0.f;

    const int nk = K / 32;

#define LOAD_SLAB(st, kt) do {                                                  \
    const uint32_t _d = (st) * STAGE_B;                                         \
    const int _k = (kt) * 32;                                                   \
    CP16(aD + _d, aS + _k);                                                     \
    CP16(aD + _d + 64 * 40 * 2, aS + (size_t)64 * K + _k);                      \
    CP16(bD + _d, bS + (size_t)_k * ldb);                                       \
    CP16(bD + _d + 16 * 136 * 2, bS + (size_t)(_k + 16) * ldb);                 \
} while (0)

#define FRAGS_MMA(sd, koff_a, koff_b) do {                                      \
    uint32_t a_f[4][4], b_f[4][2];                                              \
    _Pragma("unroll")                                                           \
    for (int mi = 0; mi < 4; mi++)                                              \
        ldsm4(a_f[mi][0], a_f[mi][1], a_f[mi][2], a_f[mi][3],                   \
              aAddr[mi] + (sd) + (koff_a));                                     \
    _Pragma("unroll")                                                           \
    for (int pi = 0; pi < 2; pi++)                                              \
        ldsm4t(b_f[2*pi][0], b_f[2*pi][1], b_f[2*pi+1][0], b_f[2*pi+1][1],      \
               bAddr[pi] + (sd) + (koff_b));                                    \
    _Pragma("unroll")                                                           \
    for (int mi = 0; mi < 4; mi++)                                              \
        _Pragma("unroll")                                                       \
        for (int ni = 0; ni < 4; ni++)                                          \
            mma16816h(d[mi][ni], a_f[mi], b_f[ni]);                             \
} while (0)

    LOAD_SLAB(0, 0); CP_COMMIT();
    LOAD_SLAB(1, 1); CP_COMMIT();
    CP_WAIT1();
    __syncthreads();

    for (int kt = 0; kt < nk; kt++) {
        const uint32_t sd = (uint32_t)(kt % 3) * STAGE_B;
        if (kt + 2 < nk) LOAD_SLAB((kt + 2) % 3, kt + 2);
        CP_COMMIT();
        FRAGS_MMA(sd, 0, 0);
        FRAGS_MMA(sd, 32, 16 * 136 * 2);
        if (kt + 1 < nk) {
            CP_WAIT1();
            __syncthreads();
        }
    }

    const int r0 = rowBase + wm * 64 + (lane >> 2);
    const int c0 = colBase + wn * 32 + (lane & 3) * 2;
#pragma unroll
    for (int mi = 0; mi < 4; mi++)
#pragma unroll
        for (int ni = 0; ni < 4; ni++) {
            int col = c0 + ni * 8;
            if (col < N) {
                float2 v0 = make_float2(d[mi][ni][0], d[mi][ni][1]);
                float2 v1 = make_float2(d[mi][ni][2], d[mi][ni][3]);
                *(float2*)&C[(size_t)(r0 + mi * 16) * ldc + col] = v0;
                *(float2*)&C[(size_t)(r0 + mi * 16 + 8) * ldc + col] = v1;
            }
        }
#undef LOAD_SLAB
#undef FRAGS_MMA
}

// ---------------- CB gram via mma (bf16 3-term, unchanged) ------------------
#define CB_AH    0
#define CB_AL    17408               // 64*136*2
#define CB_BH    34816
#define CB_BL    52224
#define CB_SMEM  69632

__global__ __launch_bounds__(256, 2) void cb_mma_kernel()
{
    extern __shared__ char csm[];
    __nv_bfloat16* Ah = (__nv_bfloat16*)(csm + CB_AH);
    __nv_bfloat16* Al = (__nv_bfloat16*)(csm + CB_AL);
    __nv_bfloat16* Bh = (__nv_bfloat16*)(csm + CB_BH);
    __nv_bfloat16* Bl = (__nv_bfloat16*)(csm + CB_BL);

    const int bc = blockIdx.x, lt = blockIdx.y;
    const int b = bc >> 4, c = bc & 15;
    const int t = threadIdx.x;
    const size_t rowB = (size_t)b * SEQLEN + c * CHUNK;

    const int lane = t & 31, warp = t >> 5;
    const int wm = warp >> 2, wn = warp & 3;
    const int grp = lane >> 3, rr = lane & 7;
    const uint32_t ahB = s2u(Ah), alB = s2u(Al), bhB = s2u(Bh), blB = s2u(Bl);

    {
        const int r = t >> 2, q = (t & 3) * 32;
        const float* cr = g_xBC + (rowB + lt * 64 + r) * CONVDIM
                          + (DINNER + DSTATE) + q;
        __nv_bfloat162* ah2 = (__nv_bfloat162*)(Ah + r * 136 + q);
        __nv_bfloat162* al2 = (__nv_bfloat162*)(Al + r * 136 + q);
#pragma unroll
        for (int j = 0; j < 32; j += 4) {
            float4 v = *(const float4*)(cr + j);
            __nv_bfloat162 h01, l01, h23, l23;
            split2(v.x, v.y, h01, l01);
            split2(v.z, v.w, h23, l23);
            ah2[(j >> 1) + 0] = h01; ah2[(j >> 1) + 1] = h23;
            al2[(j >> 1) + 0] = l01; al2[(j >> 1) + 1] = l23;
        }
    }

    uint32_t aOff[2];
#pragma unroll
    for (int mi = 0; mi < 2; mi++)
        aOff[mi] = ((wm * 32 + mi * 16 + (grp & 1) * 8 + rr) * 136
                    + (grp >> 1) * 8) * 2;
    const uint32_t bOff = ((wn * 16 + (grp & 1) * 8 + rr) * 136
                           + (grp >> 1) * 8) * 2;

    float d[2][8][4];
#pragma unroll
    for (int mi = 0; mi < 2; mi++)
#pragma unroll
        for (int ni = 0; ni < 8; ni++)
#pragma unroll
            for (int k = 0; k < 4; k++) d[mi][ni][k] = 0.f;

    for (int stile = 0; stile < 4; stile++) {
        {
            const int r = t >> 2, q = (t & 3) * 32;
            const float* br = g_xBC + (rowB + stile * 64 + r) * CONVDIM
                              + DINNER + q;
            __nv_bfloat162* bh2 = (__nv_bfloat162*)(Bh + r * 136 + q);
            __nv_bfloat162* bl2 = (__nv_bfloat162*)(Bl + r * 136 + q);
#pragma unroll
            for (int j = 0; j < 32; j += 4) {
                float4 v = *(const float4*)(br + j);
                __nv_bfloat162 h01, l01, h23, l23;
                split2(v.x, v.y, h01, l01);
                split2(v.z, v.w, h23, l23);
                bh2[(j >> 1) + 0] = h01; bh2[(j >> 1) + 1] = h23;
                bl2[(j >> 1) + 0] = l01; bl2[(j >> 1) + 1] = l23;
            }
        }
        __syncthreads();
#pragma unroll
        for (int k = 0; k < 8; k++) {
            const uint32_t ko = k * 32;
            uint32_t a_h[2][4], a_l[2][4], b4h[4], b4l[4];
#pragma unroll
            for (int mi = 0; mi < 2; mi++) {
                ldsm4(a_h[mi][0], a_h[mi][1], a_h[mi][2], a_h[mi][3],
                      ahB + aOff[mi] + ko);
                ldsm4(a_l[mi][0], a_l[mi][1], a_l[mi][2], a_l[mi][3],
                      alB + aOff[mi] + ko);
            }
            ldsm4(b4h[0], b4h[1], b4h[2], b4h[3], bhB + bOff + ko);
            ldsm4(b4l[0], b4l[1], b4l[2], b4l[3], blB + bOff + ko);
            uint32_t bh0[2] = {b4h[0], b4h[2]};
            uint32_t bh1[2] = {b4h[1], b4h[3]};
            uint32_t bl0[2] = {b4l[0], b4l[2]};
            uint32_t bl1[2] = {b4l[1], b4l[3]};
#pragma unroll
            for (int mi = 0; mi < 2; mi++) {
                mma16816(d[mi][stile * 2 + 0], a_h[mi], bh0);
                mma16816(d[mi][stile * 2 + 0], a_h[mi], bl0);
                mma16816(d[mi][stile * 2 + 0], a_l[mi], bh0);
                mma16816(d[mi][stile * 2 + 1], a_h[mi], bh1);
                mma16816(d[mi][stile * 2 + 1], a_h[mi], bl1);
                mma16816(d[mi][stile * 2 + 1], a_l[mi], bh1);
            }
        }
        __syncthreads();
    }

    const int r0 = lt * 64 + wm * 32 + (lane >> 2);
    const int c0 = (lane & 3) * 2;
#pragma unroll
    for (int mi = 0; mi < 2; mi++) {
        float* out0 = g_CB + ((size_t)bc * CHUNK + r0 + mi * 16) * CHUNK;
        float* out1 = out0 + 8 * CHUNK;
#pragma unroll
        for (int st = 0; st < 4; st++)
#pragma unroll
            for (int q = 0; q < 2; q++) {
                int col = st * 64 + wn * 16 + q * 8 + c0;
                float* dd = d[mi][st * 2 + q];
                *(float2*)&out0[col] = make_float2(dd[0], dd[1]);
                *(float2*)&out1[col] = make_float2(dd[2], dd[3]);
            }
    }
}

// ---------------- fused Y (fp16: W split hi/lo, X single) -------------------
#define YF_WH    0
#define YF_WL    36864               // 256*72*2
#define YF_XH    73728               // 64*72*2 = 9216
#define YF_ACS   82944
#define YF_DT    83968
#define YF_SMEM  84992

__global__ __launch_bounds__(256, 2) void yfused_kernel()
{
    extern __shared__ char ysm[];
    __half* Wh = (__half*)(ysm + YF_WH);
    __half* Wl = (__half*)(ysm + YF_WL);
    __half* Xh = (__half*)(ysm + YF_XH);
    float* sacs = (float*)(ysm + YF_ACS);
    float* sdt  = (float*)(ysm + YF_DT);

    const int bc = blockIdx.x, h = blockIdx.y;
    const int b = bc >> 4, c = bc & 15;
    const int t = threadIdx.x;
    const size_t rowB = (size_t)b * SEQLEN + c * CHUNK;

    sacs[t] = g_acs[((size_t)bc * NHEADS + h) * CHUNK + t];
    sdt[t]  = g_dt[(rowB + t) * NHEADS + h];
    __syncthreads();
    const float acs_l = sacs[t];

    const int lane = t & 31, warp = t >> 5;
    const int grp = lane >> 3, rr = lane & 7;
    const uint32_t whB = s2u(Wh), wlB = s2u(Wl), xhB = s2u(Xh);

    uint32_t aOff[2], bOff[4];
#pragma unroll
    for (int mi = 0; mi < 2; mi++)
        aOff[mi] = ((warp * 32 + mi * 16 + (grp & 1) * 8 + rr) * 72
                    + (grp >> 1) * 8) * 2;
#pragma unroll
    for (int pi = 0; pi < 4; pi++)
        bOff[pi] = (((grp & 1) * 8 + rr) * 72 + pi * 16 + (grp >> 1) * 8) * 2;

    float d[2][8][4];
#pragma unroll
    for (int mi = 0; mi < 2; mi++)
#pragma unroll
        for (int ni = 0; ni < 8; ni++)
#pragma unroll
            for (int k = 0; k < 4; k++) d[mi][ni][k] = 0.f;

#define YF_MMA() do {                                                           \
    _Pragma("unroll")                                                           \
    for (int k = 0; k < 4; k++) {                                               \
        const uint32_t ka = k * 32;                                             \
        const uint32_t kb = k * 16 * 144;                                       \
        uint32_t a_h[2][4], a_l[2][4];                                          \
        _Pragma("unroll")                                                       \
        for (int mi = 0; mi < 2; mi++) {                                        \
            ldsm4(a_h[mi][0], a_h[mi][1], a_h[mi][2], a_h[mi][3],               \
                  whB + aOff[mi] + ka);                                         \
            ldsm4(a_l[mi][0], a_l[mi][1], a_l[mi][2], a_l[mi][3],               \
                  wlB + aOff[mi] + ka);                                         \
        }                                                                       \
        _Pragma("unroll")                                                       \
        for (int pi = 0; pi < 4; pi++) {                                        \
            uint32_t bh[2][2];                                                  \
            ldsm4t(bh[0][0], bh[0][1], bh[1][0], bh[1][1],                      \
                   xhB + bOff[pi] + kb);                                        \
            _Pragma("unroll")                                                   \
            for (int mi = 0; mi < 2; mi++)                                      \
                _Pragma("unroll")                                               \
                for (int q = 0; q < 2; q++) {                                   \
                    mma16816h(d[mi][2*pi+q], a_h[mi], bh[q]);                   \
                    mma16816h(d[mi][2*pi+q], a_l[mi], bh[q]);                   \
                }                                                               \
        }                                                                       \
    }                                                                           \
} while (0)

    // ---- part 1: Y_diag, 4 s-tiles of 64 ----
    const float* CBrow = g_CB + ((size_t)bc * CHUNK + t) * CHUNK;
    for (int st = 0; st < 4; st++) {
        const int s0 = st * 64;
        __half2* wh2 = (__half2*)(Wh + t * 72);
        __half2* wl2 = (__half2*)(Wl + t * 72);
#pragma unroll
        for (int j = 0; j < 64; j += 4) {
            float4 cb4 = *(const float4*)(CBrow + s0 + j);
            float w[4];
            const float* cbp = (const float*)&cb4;
#pragma unroll
            for (int e = 0; e < 4; e++) {
                int s = s0 + j + e;
                float arg = fminf(acs_l - sacs[s], 0.f);
                w[e] = (s <= t) ? cbp[e] * __expf(arg) : 0.f;
            }
            __half2 h01, l01, h23, l23;
            split2h(w[0], w[1], h01, l01);
            split2h(w[2], w[3], h23, l23);
            wh2[(j >> 1) + 0] = h01; wh2[(j >> 1) + 1] = h23;
            wl2[(j >> 1) + 0] = l01; wl2[(j >> 1) + 1] = l23;
        }
        {
            const int r = t >> 2, c16 = (t & 3) * 16;
            const float dts = sdt[s0 + r];
            const float* xr = g_xBC + (rowB + s0 + r) * CONVDIM + h * HEADDIM + c16;
            __half2* xh2 = (__half2*)(Xh + r * 72 + c16);
#pragma unroll
            for (int j = 0; j < 16; j += 4) {
                float4 v = *(const float4*)(xr + j);
                xh2[(j >> 1) + 0] = __floats2half2_rn(v.x * dts, v.y * dts);
                xh2[(j >> 1) + 1] = __floats2half2_rn(v.z * dts, v.w * dts);
            }
        }
        __syncthreads();
        YF_MMA();
        __syncthreads();
    }

    // ---- part 2: Y_off, 2 n-tiles of 64 ----
    const float el = __expf(acs_l);
    const float* Crow = g_xBC + (rowB + t) * CONVDIM + DINNER + DSTATE;
    const float* S0p = g_Sinit + ((size_t)bc * NHEADS + h) * (HEADDIM * DSTATE);
    for (int nt = 0; nt < 2; nt++) {
        const int n0 = nt * 64;
        __half2* wh2 = (__half2*)(Wh + t * 72);
        __half2* wl2 = (__half2*)(Wl + t * 72);
#pragma unroll
        for (int j = 0; j < 64; j += 4) {
            float4 c4 = *(const float4*)(Crow + n0 + j);
            __half2 h01, l01, h23, l23;
            split2h(c4.x * el, c4.y * el, h01, l01);
            split2h(c4.z * el, c4.w * el, h23, l23);
            wh2[(j >> 1) + 0] = h01; wh2[(j >> 1) + 1] = h23;
            wl2[(j >> 1) + 0] = l01; wl2[(j >> 1) + 1] = l23;
        }
        {
            const int p = t >> 2, nb = (t & 3) * 16;
            const float* sp = S0p + (size_t)p * DSTATE + n0 + nb;
#pragma unroll
            for (int j = 0; j < 16; j++)
                Xh[(nb + j) * 72 + p] = __float2half(sp[j]);
        }
        __syncthreads();
        YF_MMA();
        __syncthreads();
    }
#undef YF_MMA

    const int c0 = (lane & 3) * 2;
#pragma unroll
    for (int mi = 0; mi < 2; mi++) {
        const size_t gr0 = (rowB + warp * 32 + (lane >> 2) + mi * 16) * DINNER + h * HEADDIM;
#pragma unroll
        for (int ni = 0; ni < 8; ni++) {
            int col = c0 + ni * 8;
            *(float2*)&g_Y[gr0 + col] = make_float2(d[mi][ni][0], d[mi][ni][1]);
            *(float2*)&g_Y[gr0 + 8 * DINNER + col] = make_float2(d[mi][ni][2], d[mi][ni][3]);
        }
    }
}

// ---------------- state S = x^T . (w.B)  (fp16: x single, w.B split) --------
#define ST_A     0
#define ST_BH    9216                // 64*72*2
#define ST_BL    26624               // + 64*136*2
#define ST_SMEM  44032

__global__ __launch_bounds__(256, 2) void state_mma_kernel()
{
    extern __shared__ char ssm[];
    __half* Ax = (__half*)(ssm + ST_A);    // [p(64)][s(72 pad)]
    __half* Bh = (__half*)(ssm + ST_BH);   // [s(64)][n(136 pad)]
    __half* Bl = (__half*)(ssm + ST_BL);

    const int bc = blockIdx.x, h = blockIdx.y;
    const int b = bc >> 4, c = bc & 15;
    const int t = threadIdx.x;
    const size_t rowB = (size_t)b * SEQLEN + c * CHUNK;
    const float asum = g_asum[bc * NHEADS + h];
    const float* acsp = g_acs + ((size_t)bc * NHEADS + h) * CHUNK;

    const int lane = t & 31, warp = t >> 5;
    const int wm = warp >> 2, wn = warp & 3;
    const int grp = lane >> 3, rr = lane & 7;
    const uint32_t axB = s2u(Ax), bhB = s2u(Bh), blB = s2u(Bl);

    uint32_t aOff[2], bOff[2];
#pragma unroll
    for (int mi = 0; mi < 2; mi++)
        aOff[mi] = ((wm * 32 + mi * 16 + (grp & 1) * 8 + rr) * 72
                    + (grp >> 1) * 8) * 2;
#pragma unroll
    for (int pi = 0; pi < 2; pi++)
        bOff[pi] = (((grp & 1) * 8 + rr) * 136
                    + wn * 32 + pi * 16 + (grp >> 1) * 8) * 2;

    float d[2][4][4];
#pragma unroll
    for (int mi = 0; mi < 2; mi++)
#pragma unroll
        for (int ni = 0; ni < 4; ni++)
#pragma unroll
            for (int k = 0; k < 4; k++) d[mi][ni][k] = 0.f;

    for (int st4 = 0; st4 < 4; st4++) {
        const int s0 = st4 * 64;
        const int r = t >> 2;
        const float w = g_dt[(rowB + s0 + r) * NHEADS + h] *
                        __expf(asum - acsp[s0 + r]);
        {
            const int q = (t & 3) * 16;
            const float* xr = g_xBC + (rowB + s0 + r) * CONVDIM + h * HEADDIM + q;
#pragma unroll
            for (int j = 0; j < 16; j += 4) {
                float4 v = *(const float4*)(xr + j);
                Ax[(q + j + 0) * 72 + r] = __float2half(v.x);
                Ax[(q + j + 1) * 72 + r] = __float2half(v.y);
                Ax[(q + j + 2) * 72 + r] = __float2half(v.z);
                Ax[(q + j + 3) * 72 + r] = __float2half(v.w);
            }
        }
        {
            const int nq = (t & 3) * 32;
            const float* brp = g_xBC + (rowB + s0 + r) * CONVDIM + DINNER + nq;
            __half2* bh2 = (__half2*)(Bh + r * 136 + nq);
            __half2* bl2 = (__half2*)(Bl + r * 136 + nq);
#pragma unroll
            for (int j = 0; j < 32; j += 4) {
                float4 v = *(const float4*)(brp + j);
                __half2 h01, l01, h23, l23;
                split2h(v.x * w, v.y * w, h01, l01);
                split2h(v.z * w, v.w * w, h23, l23);
                bh2[(j >> 1) + 0] = h01; bh2[(j >> 1) + 1] = h23;
                bl2[(j >> 1) + 0] = l01; bl2[(j >> 1) + 1] = l23;
            }
        }
        __syncthreads();
#pragma unroll
        for (int k = 0; k < 4; k++) {
            const uint32_t ka = k * 32;
            const uint32_t kb = (uint32_t)k * 16 * 136 * 2;
            uint32_t a_f[2][4], bhf[4][2], blf[4][2];
#pragma unroll
            for (int mi = 0; mi < 2; mi++)
                ldsm4(a_f[mi][0], a_f[mi][1], a_f[mi][2], a_f[mi][3],
                      axB + aOff[mi] + ka);
#pragma unroll
            for (int pi = 0; pi < 2; pi++) {
                ldsm4t(bhf[2*pi][0], bhf[2*pi][1], bhf[2*pi+1][0], bhf[2*pi+1][1],
                       bhB + bOff[pi] + kb);
                ldsm4t(blf[2*pi][0], blf[2*pi][1], blf[2*pi+1][0], blf[2*pi+1][1],
                       blB + bOff[pi] + kb);
            }
#pragma unroll
            for (int mi = 0; mi < 2; mi++)
#pragma unroll
                for (int ni = 0; ni < 4; ni++) {
                    mma16816h(d[mi][ni], a_f[mi], bhf[ni]);
                    mma16816h(d[mi][ni], a_f[mi], blf[ni]);
                }
        }
        __syncthreads();
    }

    float* Sout = g_S + ((size_t)bc * NHEADS + h) * (HEADDIM * DSTATE);
    const int p0 = wm * 32 + (lane >> 2);
    const int n0 = wn * 32 + (lane & 3) * 2;
#pragma unroll
    for (int mi = 0; mi < 2; mi++)
#pragma unroll
        for (int ni = 0; ni < 4; ni++) {
            int col = n0 + ni * 8;
            *(float2*)&Sout[(size_t)(p0 + mi * 16) * DSTATE + col] =
                make_float2(d[mi][ni][0], d[mi][ni][1]);
            *(float2*)&Sout[(size_t)(p0 + mi * 16 + 8) * DSTATE + col] =
                make_float2(d[mi][ni][2], d[mi][ni][3]);
        }
}

// ---------------- convert kernels -------------------------------------------
__global__ void tofp16_kernel(const float* __restrict__ x, __half* __restrict__ o, size_t n)
{
    size_t i = (size_t)blockIdx.x * blockDim.x + threadIdx.x;
    if (i >= n) return;
    o[i] = __float2half(x[i]);
}

__global__ void tofp16_pad_kernel(const float* __restrict__ x, __half* __restrict__ o,
                                  int K, int N, int Np)
{
    size_t i = (size_t)blockIdx.x * blockDim.x + threadIdx.x;
    if (i >= (size_t)K * Np) return;
    int r = (int)(i / Np), c = (int)(i % Np);
    o[i] = __float2half((c < N) ? x[(size_t)r * N + c] : 0.f);
}

// ---------------- causal conv1d + SiLU: 4 outputs per thread ----------------
__global__ void conv_silu_kernel(const float* __restrict__ conv_w,
                                 const float* __restrict__ conv_b)
{
    int idx = blockIdx.x * blockDim.x + threadIdx.x;
    if (idx >= (ROWS / 4) * CONVDIM) return;
    int c  = idx % CONVDIM;
    int rg = idx / CONVDIM;
    int row0 = rg * 4;
    int l0 = row0 & (SEQLEN - 1);
    const float* base = g_zxbcdt + (size_t)row0 * DPROJ + DINNER + c;
    const float w0 = conv_w[c * DCONV + 0], w1 = conv_w[c * DCONV + 1];
    const float w2 = conv_w[c * DCONV + 2], w3 = conv_w[c * DCONV + 3];
    const float bias = conv_b[c];
    float v[7];
#pragma unroll
    for (int j = 0; j < 7; j++) {
        int l = l0 - 3 + j;
        v[j] = (l >= 0) ? base[(long)(j - 3) * DPROJ] : 0.f;
    }
#pragma unroll
    for (int i = 0; i < 4; i++) {
        float acc = bias + v[i] * w0 + v[i+1] * w1 + v[i+2] * w2 + v[i+3] * w3;
        g_xBC[(size_t)(row0 + i) * CONVDIM + c] = acc / (1.f + __expf(-acc));
    }
}

// ---------------- dt = softplus(dt_raw + dt_bias) --------------------------
__global__ void dt_kernel(const float* __restrict__ dt_bias)
{
    int idx = blockIdx.x * blockDim.x + threadIdx.x;
    if (idx >= ROWS * NHEADS) return;
    int h   = idx & (NHEADS - 1);
    int row = idx >> 5;
    float v = g_zxbcdt[(size_t)row * DPROJ + DT_OFF + h] + dt_bias[h];
    g_dt[idx] = (v > 20.f) ? v : log1pf(expf(v));
}

// ---------------- per-chunk inclusive cumsum of a = A*dt -------------------
__global__ void ascan_kernel(const float* __restrict__ A_log)
{
    int bc = blockIdx.x;
    int h  = blockIdx.y;
    int t  = threadIdx.x;
    int b = bc >> 4, c = bc & 15;
    __shared__ float sa[CHUNK];
    int row = b * SEQLEN + c * CHUNK + t;
    float A = -expf(A_log[h]);
    sa[t] = A * g_dt[row * NHEADS + h];
    __syncthreads();
    for (int off = 1; off < CHUNK; off <<= 1) {
        float v = (t >= off) ? sa[t - off] : 0.f;
        __syncthreads();
        sa[t] += v;
        __syncthreads();
    }
    g_acs[(bc * NHEADS + h) * CHUNK + t] = sa[t];
    if (t == CHUNK - 1) g_asum[bc * NHEADS + h] = sa[t];
}

// ---------------- sequential inter-chunk recurrence (4-way split) -----------
__global__ void chunkrec_kernel()
{
    int b = blockIdx.x, h = blockIdx.y, z = blockIdx.z;
    int t = threadIdx.x;
    float cur[8];
#pragma unroll
    for (int k = 0; k < 8; k++) cur[k] = 0.f;
    for (int c = 0; c < NCHUNK; c++) {
        int bc = b * NCHUNK + c;
        size_t base = ((size_t)bc * NHEADS + h) * (HEADDIM * DSTATE) + z * 2048;
        float dd = __expf(g_asum[bc * NHEADS + h]);
#pragma unroll
        for (int k = 0; k < 8; k++) {
            size_t e = base + t + 256 * k;
            g_Sinit[e] = cur[k];
            cur[k] = cur[k] * dd + g_S[e];
        }
    }
}

// ---------------- layernorm + z-gate -> fp16 yg ----------------------------
__global__ __launch_bounds__(256) void normgate_kernel(const float* __restrict__ norm_w)
{
    int row = blockIdx.x;
    int t = threadIdx.x;
    const float* yrow = g_Y + (size_t)row * DINNER;
    const float* zrow = g_zxbcdt + (size_t)row * DPROJ;
    float v[8];
    float s = 0.f;
#pragma unroll
    for (int i = 0; i < 8; i++) { v[i] = yrow[t + 256*i]; s += v[i]; }
    __shared__ float red[256];
    red[t] = s; __syncthreads();
    for (int o = 128; o > 0; o >>= 1) { if (t < o) red[t] += red[t+o]; __syncthreads(); }
    float mu = red[0] * (1.f / DINNER);
    __syncthreads();
    float s2 = 0.f;
#pragma unroll
    for (int i = 0; i < 8; i++) { float dv = v[i] - mu; s2 += dv * dv; }
    red[t] = s2; __syncthreads();
    for (int o = 128; o > 0; o >>= 1) { if (t < o) red[t] += red[t+o]; __syncthreads(); }
    float inv = rsqrtf(red[0] * (1.f / DINNER) + 1e-5f);
    __half* orow = g_yg + (size_t)row * DINNER;
#pragma unroll
    for (int i = 0; i < 8; i++) {
        int idx = t + 256*i;
        float z = zrow[idx];
        float g = z / (1.f + __expf(-z));
        orow[idx] = __float2half((v[i] - mu) * inv * norm_w[idx] * g);
    }
}

// ---------------- launch ---------------------------------------------------
extern "C" void kernel_launch(void* const* d_in, const int* in_sizes, int n_in,
                              void* d_out, int out_size)
{
    const float* u       = (const float*)d_in[0];
    const float* W_in    = (const float*)d_in[1];
    const float* conv_w  = (const float*)d_in[2];
    const float* conv_b  = (const float*)d_in[3];
    const float* dt_bias = (const float*)d_in[4];
    const float* A_log   = (const float*)d_in[5];
    const float* norm_w  = (const float*)d_in[6];
    const float* W_out   = (const float*)d_in[7];
    float* out = (float*)d_out;

    float* p_zx = nullptr;
    __half *p_uf, *p_wif, *p_wof, *p_yg;
    cudaGetSymbolAddress((void**)&p_zx,  g_zxbcdt);
    cudaGetSymbolAddress((void**)&p_uf,  g_uf);
    cudaGetSymbolAddress((void**)&p_wif, g_wif);
    cudaGetSymbolAddress((void**)&p_wof, g_wof);
    cudaGetSymbolAddress((void**)&p_yg,  g_yg);

    cudaFuncSetAttribute(mma_gemm, cudaFuncAttributeMaxDynamicSharedMemorySize, GEMM_SMEM);
    cudaFuncSetAttribute(yfused_kernel, cudaFuncAttributeMaxDynamicSharedMemorySize, YF_SMEM);
    cudaFuncSetAttribute(state_mma_kernel, cudaFuncAttributeMaxDynamicSharedMemorySize, ST_SMEM);
    cudaFuncSetAttribute(cb_mma_kernel, cudaFuncAttributeMaxDynamicSharedMemorySize, CB_SMEM);

    // 0. fp16 conversions
    {
        size_t n = (size_t)ROWS * DMODEL;
        tofp16_kernel<<<(unsigned)((n + 255) / 256), 256>>>(u, p_uf, n);
    }
    tofp16_pad_kernel<<<(unsigned)(((size_t)DMODEL * NPAD1 + 255) / 256), 256>>>(
        W_in, p_wif, DMODEL, DPROJ, NPAD1);
    {
        size_t n = (size_t)DINNER * DMODEL;
        tofp16_kernel<<<(unsigned)((n + 255) / 256), 256>>>(W_out, p_wof, n);
    }

    // 1. zxbcdt = u @ W_in  (8192 x 4384 x 1024)
    mma_gemm<<<dim3(NPAD1 / 128, ROWS / 128), 256, GEMM_SMEM>>>(
        p_uf, p_wif, p_zx, ROWS, DPROJ, DMODEL, NPAD1, DPROJ);
    // 2. causal conv1d + SiLU (4 l per thread)
    conv_silu_kernel<<<((ROWS / 4) * CONVDIM + 255) / 256, 256>>>(conv_w, conv_b);
    // 3. dt softplus
    dt_kernel<<<(ROWS * NHEADS + 255) / 256, 256>>>(dt_bias);
    // 4. per-chunk cumsum of A*dt
    ascan_kernel<<<dim3(NBC, NHEADS), CHUNK>>>(A_log);
    // 5. CB gram matrices (tensor cores, bf16 3-term)
    cb_mma_kernel<<<dim3(NBC, 4), 256, CB_SMEM>>>();
    // 6. per-chunk end states (tensor cores, fp16 2-term)
    state_mma_kernel<<<dim3(NBC, NHEADS), 256, ST_SMEM>>>();
    // 7. inter-chunk recurrence (4-way parallel over state elems)
    chunkrec_kernel<<<dim3(BATCH, NHEADS, 4), 256>>>();
    // 8. fused Y_diag + Y_off (tensor cores, fp16 2-term)
    yfused_kernel<<<dim3(NBC, NHEADS), 256, YF_SMEM>>>();
    // 9. layernorm + silu(z) gate -> fp16
    normgate_kernel<<<ROWS, 256>>>(norm_w);
    // 10. out = yg @ W_out  (8192 x 1024 x 2048)
    mma_gemm<<<dim3(DMODEL / 128, ROWS / 128), 256, GEMM_SMEM>>>(
        p_yg, p_wof, out, ROWS, DMODEL, DINNER, DMODEL, DMODEL);
}

// round 14
// speedup vs baseline: 1.9135x; 1.1167x over previous
#include <cuda_runtime.h>
#include <cuda_bf16.h>
#include <cuda_fp16.h>
#include <math.h>
#include <stdint.h>

#define BATCH   2
#define SEQLEN  4096
#define DMODEL  1024
#define DINNER  2048
#define HEADDIM 64
#define NHEADS  32
#define DSTATE  128
#define DCONV   4
#define CHUNK   256
#define NCHUNK  (SEQLEN / CHUNK)   // 16
#define NBC     (BATCH * NCHUNK)   // 32
#define DPROJ   4384               // 2*DINNER + 2*DSTATE + NHEADS
#define CONVDIM 2304               // DINNER + 2*DSTATE
#define DT_OFF  4352               // 2*DINNER + 2*DSTATE
#define ROWS    (BATCH * SEQLEN)   // 8192
#define NPAD1   4480               // DPROJ padded to multiple of 128

// ---------------- scratch (device globals; no allocation allowed) ----------
__device__ float g_zxbcdt[(size_t)ROWS * DPROJ];
__device__ float g_xBC[(size_t)ROWS * CONVDIM];
__device__ float g_dt[ROWS * NHEADS];
__device__ float g_acs[NBC * NHEADS * CHUNK];
__device__ float g_asum[NBC * NHEADS];
__device__ float g_CB[(size_t)NBC * CHUNK * CHUNK];
__device__ float g_Y[(size_t)ROWS * DINNER];
__device__ float g_S[(size_t)NBC * NHEADS * HEADDIM * DSTATE];
__device__ float g_Sinit[(size_t)NBC * NHEADS * HEADDIM * DSTATE];

// fp16 GEMM operands (all single precision fp16)
__device__ __half g_uf[(size_t)ROWS * DMODEL];
__device__ __half g_wif[(size_t)DMODEL * NPAD1];
__device__ __half g_wof[(size_t)DINNER * DMODEL];
__device__ __half g_yg[(size_t)ROWS * DINNER];

// ---------------- helpers ---------------------------------------------------
__device__ __forceinline__ uint32_t s2u(const void* p) {
    return (uint32_t)__cvta_generic_to_shared(p);
}
#define CP16(dst, src) \
    asm volatile("cp.async.cg.shared.global [%0], [%1], 16;\n" :: "r"(dst), "l"(src))
#define CP_COMMIT() asm volatile("cp.async.commit_group;\n")
#define CP_WAIT1()  asm volatile("cp.async.wait_group 1;\n")

__device__ __forceinline__ void ldsm4(uint32_t& r0, uint32_t& r1, uint32_t& r2,
                                      uint32_t& r3, uint32_t addr) {
    asm volatile("ldmatrix.sync.aligned.m8n8.x4.shared.b16 {%0,%1,%2,%3}, [%4];"
                 : "=r"(r0), "=r"(r1), "=r"(r2), "=r"(r3) : "r"(addr));
}
__device__ __forceinline__ void ldsm4t(uint32_t& r0, uint32_t& r1, uint32_t& r2,
                                       uint32_t& r3, uint32_t addr) {
    asm volatile("ldmatrix.sync.aligned.m8n8.x4.trans.shared.b16 {%0,%1,%2,%3}, [%4];"
                 : "=r"(r0), "=r"(r1), "=r"(r2), "=r"(r3) : "r"(addr));
}
// fp16 mma
__device__ __forceinline__ void mma16816h(float* d, const uint32_t* a, const uint32_t* b) {
    asm volatile(
        "mma.sync.aligned.m16n8k16.row.col.f32.f16.f16.f32 "
        "{%0,%1,%2,%3}, {%4,%5,%6,%7}, {%8,%9}, {%0,%1,%2,%3};"
        : "+f"(d[0]), "+f"(d[1]), "+f"(d[2]), "+f"(d[3])
        : "r"(a[0]), "r"(a[1]), "r"(a[2]), "r"(a[3]), "r"(b[0]), "r"(b[1]));
}
// bf16 mma (cb)
__device__ __forceinline__ void mma16816(float* d, const uint32_t* a, const uint32_t* b) {
    asm volatile(
        "mma.sync.aligned.m16n8k16.row.col.f32.bf16.bf16.f32 "
        "{%0,%1,%2,%3}, {%4,%5,%6,%7}, {%8,%9}, {%0,%1,%2,%3};"
        : "+f"(d[0]), "+f"(d[1]), "+f"(d[2]), "+f"(d[3])
        : "r"(a[0]), "r"(a[1]), "r"(a[2]), "r"(a[3]), "r"(b[0]), "r"(b[1]));
}
__device__ __forceinline__ void split2(float a, float b,
                                       __nv_bfloat162& h, __nv_bfloat162& l) {
    __nv_bfloat16 ha = __float2bfloat16(a), hb = __float2bfloat16(b);
    h = __halves2bfloat162(ha, hb);
    l = __halves2bfloat162(__float2bfloat16(a - __bfloat162float(ha)),
                           __float2bfloat16(b - __bfloat162float(hb)));
}
__device__ __forceinline__ void split2h(float a, float b, __half2& h, __half2& l) {
    __half ha = __float2half(a), hb = __float2half(b);
    h = __halves2half2(ha, hb);
    l = __halves2half2(__float2half(a - __half2float(ha)),
                       __float2half(b - __half2float(hb)));
}

// ---------------- GEMM smem layout (bytes), tile 128x128, BK=32 -------------
#define A_B        10240         // 128*40*2
#define B_B        8704          // 32*136*2
#define OFF_B      A_B
#define STAGE_B    (A_B + B_B)                     // 18944
#define NSTAGE     3
#define GEMM_SMEM  (NSTAGE * STAGE_B)              // 56832

// ---------------- fp16 single-term tensor-core GEMM (2 CTAs/SM) -------------
__global__ __launch_bounds__(256, 2) void mma_gemm(
    const __half* __restrict__ A, const __half* __restrict__ B,
    float* __restrict__ C, int M, int N, int K, int ldb, int ldc)
{
    extern __shared__ __half smem[];
    const uint32_t sbase = s2u(smem);
    const int rowBase = blockIdx.y * 128;
    const int colBase = blockIdx.x * 128;
    const int t = threadIdx.x;

    const int ar = t >> 2, aq = t & 3;
    const __half* aS = A + (size_t)(rowBase + ar) * K + aq * 8;
    const uint32_t aD = sbase + (ar * 40 + aq * 8) * 2;
    const int br = t >> 4, bq = t & 15;
    const __half* bS = B + (size_t)br * ldb + colBase + bq * 8;
    const uint32_t bD = sbase + OFF_B + (br * 136 + bq * 8) * 2;

    const int lane = t & 31, warp = t >> 5;
    const int wm = warp >> 2, wn = warp & 3;
    const int grp = lane >> 3, rr = lane & 7;

    uint32_t aAddr[4], bAddr[2];
#pragma unroll
    for (int mi = 0; mi < 4; mi++)
        aAddr[mi] = sbase + ((wm * 64 + mi * 16 + (grp & 1) * 8 + rr) * 40
                             + (grp >> 1) * 8) * 2;
#pragma unroll
    for (int pi = 0; pi < 2; pi++)
        bAddr[pi] = sbase + OFF_B + (((grp & 1) * 8 + rr) * 136
                             + wn * 32 + pi * 16 + (grp >> 1) * 8) * 2;

    float d[4][4][4];
#pragma unroll
    for (int mi = 0; mi < 4; mi++)
#pragma unroll
        for (int ni = 0; ni < 4; ni++)
#pragma unroll
            for (int k = 0; k < 4; k++) d[mi][ni][k] = 0.f;

    const int nk = K / 32;

#define LOAD_SLAB(st, kt) do {                                                  \
    const uint32_t _d = (st) * STAGE_B;                                         \
    const int _k = (kt) * 32;                                                   \
    CP16(aD + _d, aS + _k);                                                     \
    CP16(aD + _d + 64 * 40 * 2, aS + (size_t)64 * K + _k);                      \
    CP16(bD + _d, bS + (size_t)_k * ldb);                                       \
    CP16(bD + _d + 16 * 136 * 2, bS + (size_t)(_k + 16) * ldb);                 \
} while (0)

#define FRAGS_MMA(sd, koff_a, koff_b) do {                                      \
    uint32_t a_f[4][4], b_f[4][2];                                              \
    _Pragma("unroll")                                                           \
    for (int mi = 0; mi < 4; mi++)                                              \
        ldsm4(a_f[mi][0], a_f[mi][1], a_f[mi][2], a_f[mi][3],                   \
              aAddr[mi] + (sd) + (koff_a));                                     \
    _Pragma("unroll")                                                           \
    for (int pi = 0; pi < 2; pi++)                                              \
        ldsm4t(b_f[2*pi][0], b_f[2*pi][1], b_f[2*pi+1][0], b_f[2*pi+1][1],      \
               bAddr[pi] + (sd) + (koff_b));                                    \
    _Pragma("unroll")                                                           \
    for (int mi = 0; mi < 4; mi++)                                              \
        _Pragma("unroll")                                                       \
        for (int ni = 0; ni < 4; ni++)                                          \
            mma16816h(d[mi][ni], a_f[mi], b_f[ni]);                             \
} while (0)

    LOAD_SLAB(0, 0); CP_COMMIT();
    LOAD_SLAB(1, 1); CP_COMMIT();
    CP_WAIT1();
    __syncthreads();

    for (int kt = 0; kt < nk; kt++) {
        const uint32_t sd = (uint32_t)(kt % 3) * STAGE_B;
        if (kt + 2 < nk) LOAD_SLAB((kt + 2) % 3, kt + 2);
        CP_COMMIT();
        FRAGS_MMA(sd, 0, 0);
        FRAGS_MMA(sd, 32, 16 * 136 * 2);
        if (kt + 1 < nk) {
            CP_WAIT1();
            __syncthreads();
        }
    }

    const int r0 = rowBase + wm * 64 + (lane >> 2);
    const int c0 = colBase + wn * 32 + (lane & 3) * 2;
#pragma unroll
    for (int mi = 0; mi < 4; mi++)
#pragma unroll
        for (int ni = 0; ni < 4; ni++) {
            int col = c0 + ni * 8;
            if (col < N) {
                float2 v0 = make_float2(d[mi][ni][0], d[mi][ni][1]);
                float2 v1 = make_float2(d[mi][ni][2], d[mi][ni][3]);
                *(float2*)&C[(size_t)(r0 + mi * 16) * ldc + col] = v0;
                *(float2*)&C[(size_t)(r0 + mi * 16 + 8) * ldc + col] = v1;
            }
        }
#undef LOAD_SLAB
#undef FRAGS_MMA
}

// ---------------- CB gram via mma (bf16 3-term) -----------------------------
#define CB_AH    0
#define CB_AL    17408               // 64*136*2
#define CB_BH    34816
#define CB_BL    52224
#define CB_SMEM  69632

__global__ __launch_bounds__(256, 2) void cb_mma_kernel()
{
    extern __shared__ char csm[];
    __nv_bfloat16* Ah = (__nv_bfloat16*)(csm + CB_AH);
    __nv_bfloat16* Al = (__nv_bfloat16*)(csm + CB_AL);
    __nv_bfloat16* Bh = (__nv_bfloat16*)(csm + CB_BH);
    __nv_bfloat16* Bl = (__nv_bfloat16*)(csm + CB_BL);

    const int bc = blockIdx.x, lt = blockIdx.y;
    const int b = bc >> 4, c = bc & 15;
    const int t = threadIdx.x;
    const size_t rowB = (size_t)b * SEQLEN + c * CHUNK;

    const int lane = t & 31, warp = t >> 5;
    const int wm = warp >> 2, wn = warp & 3;
    const int grp = lane >> 3, rr = lane & 7;
    const uint32_t ahB = s2u(Ah), alB = s2u(Al), bhB = s2u(Bh), blB = s2u(Bl);

    {
        const int r = t >> 2, q = (t & 3) * 32;
        const float* cr = g_xBC + (rowB + lt * 64 + r) * CONVDIM
                          + (DINNER + DSTATE) + q;
        __nv_bfloat162* ah2 = (__nv_bfloat162*)(Ah + r * 136 + q);
        __nv_bfloat162* al2 = (__nv_bfloat162*)(Al + r * 136 + q);
#pragma unroll
        for (int j = 0; j < 32; j += 4) {
            float4 v = *(const float4*)(cr + j);
            __nv_bfloat162 h01, l01, h23, l23;
            split2(v.x, v.y, h01, l01);
            split2(v.z, v.w, h23, l23);
            ah2[(j >> 1) + 0] = h01; ah2[(j >> 1) + 1] = h23;
            al2[(j >> 1) + 0] = l01; al2[(j >> 1) + 1] = l23;
        }
    }

    uint32_t aOff[2];
#pragma unroll
    for (int mi = 0; mi < 2; mi++)
        aOff[mi] = ((wm * 32 + mi * 16 + (grp & 1) * 8 + rr) * 136
                    + (grp >> 1) * 8) * 2;
    const uint32_t bOff = ((wn * 16 + (grp & 1) * 8 + rr) * 136
                           + (grp >> 1) * 8) * 2;

    float d[2][8][4];
#pragma unroll
    for (int mi = 0; mi < 2; mi++)
#pragma unroll
        for (int ni = 0; ni < 8; ni++)
#pragma unroll
            for (int k = 0; k < 4; k++) d[mi][ni][k] = 0.f;

    for (int stile = 0; stile < 4; stile++) {
        {
            const int r = t >> 2, q = (t & 3) * 32;
            const float* br = g_xBC + (rowB + stile * 64 + r) * CONVDIM
                              + DINNER + q;
            __nv_bfloat162* bh2 = (__nv_bfloat162*)(Bh + r * 136 + q);
            __nv_bfloat162* bl2 = (__nv_bfloat162*)(Bl + r * 136 + q);
#pragma unroll
            for (int j = 0; j < 32; j += 4) {
                float4 v = *(const float4*)(br + j);
                __nv_bfloat162 h01, l01, h23, l23;
                split2(v.x, v.y, h01, l01);
                split2(v.z, v.w, h23, l23);
                bh2[(j >> 1) + 0] = h01; bh2[(j >> 1) + 1] = h23;
                bl2[(j >> 1) + 0] = l01; bl2[(j >> 1) + 1] = l23;
            }
        }
        __syncthreads();
#pragma unroll
        for (int k = 0; k < 8; k++) {
            const uint32_t ko = k * 32;
            uint32_t a_h[2][4], a_l[2][4], b4h[4], b4l[4];
#pragma unroll
            for (int mi = 0; mi < 2; mi++) {
                ldsm4(a_h[mi][0], a_h[mi][1], a_h[mi][2], a_h[mi][3],
                      ahB + aOff[mi] + ko);
                ldsm4(a_l[mi][0], a_l[mi][1], a_l[mi][2], a_l[mi][3],
                      alB + aOff[mi] + ko);
            }
            ldsm4(b4h[0], b4h[1], b4h[2], b4h[3], bhB + bOff + ko);
            ldsm4(b4l[0], b4l[1], b4l[2], b4l[3], blB + bOff + ko);
            uint32_t bh0[2] = {b4h[0], b4h[2]};
            uint32_t bh1[2] = {b4h[1], b4h[3]};
            uint32_t bl0[2] = {b4l[0], b4l[2]};
            uint32_t bl1[2] = {b4l[1], b4l[3]};
#pragma unroll
            for (int mi = 0; mi < 2; mi++) {
                mma16816(d[mi][stile * 2 + 0], a_h[mi], bh0);
                mma16816(d[mi][stile * 2 + 0], a_h[mi], bl0);
                mma16816(d[mi][stile * 2 + 0], a_l[mi], bh0);
                mma16816(d[mi][stile * 2 + 1], a_h[mi], bh1);
                mma16816(d[mi][stile * 2 + 1], a_h[mi], bl1);
                mma16816(d[mi][stile * 2 + 1], a_l[mi], bh1);
            }
        }
        __syncthreads();
    }

    const int r0 = lt * 64 + wm * 32 + (lane >> 2);
    const int c0 = (lane & 3) * 2;
#pragma unroll
    for (int mi = 0; mi < 2; mi++) {
        float* out0 = g_CB + ((size_t)bc * CHUNK + r0 + mi * 16) * CHUNK;
        float* out1 = out0 + 8 * CHUNK;
#pragma unroll
        for (int st = 0; st < 4; st++)
#pragma unroll
            for (int q = 0; q < 2; q++) {
                int col = st * 64 + wn * 16 + q * 8 + c0;
                float* dd = d[mi][st * 2 + q];
                *(float2*)&out0[col] = make_float2(dd[0], dd[1]);
                *(float2*)&out1[col] = make_float2(dd[2], dd[3]);
            }
    }
}

// ---------------- fused Y (fp16, factored decay + triangular skip) ----------
#define YF_WH    0
#define YF_WL    36864               // 256*72*2
#define YF_XH    73728               // 64*72*2 = 9216
#define YF_ACS   82944
#define YF_DT    83968
#define YF_SCOL  84992
#define YF_SMEM  86016

__global__ __launch_bounds__(256, 2) void yfused_kernel()
{
    extern __shared__ char ysm[];
    __half* Wh = (__half*)(ysm + YF_WH);
    __half* Wl = (__half*)(ysm + YF_WL);
    __half* Xh = (__half*)(ysm + YF_XH);
    float* sacs = (float*)(ysm + YF_ACS);
    float* sdt  = (float*)(ysm + YF_DT);
    float* scol = (float*)(ysm + YF_SCOL);

    const int bc = blockIdx.x, h = blockIdx.y;
    const int b = bc >> 4, c = bc & 15;
    const int t = threadIdx.x;
    const size_t rowB = (size_t)b * SEQLEN + c * CHUNK;

    sacs[t] = g_acs[((size_t)bc * NHEADS + h) * CHUNK + t];
    sdt[t]  = g_dt[(rowB + t) * NHEADS + h];
    __syncthreads();
    const float acs_l = sacs[t];
    // column decay factor: exp(acs[tile_end] - acs[t]) for t's own tile (<=0 exp)
    scol[t] = __expf(sacs[t | 63] - acs_l);
    __syncthreads();

    const int lane = t & 31, warp = t >> 5;
    const int grp = lane >> 3, rr = lane & 7;
    const uint32_t whB = s2u(Wh), wlB = s2u(Wl), xhB = s2u(Xh);

    uint32_t aOff[2], bOff[4];
#pragma unroll
    for (int mi = 0; mi < 2; mi++)
        aOff[mi] = ((warp * 32 + mi * 16 + (grp & 1) * 8 + rr) * 72
                    + (grp >> 1) * 8) * 2;
#pragma unroll
    for (int pi = 0; pi < 4; pi++)
        bOff[pi] = (((grp & 1) * 8 + rr) * 72 + pi * 16 + (grp >> 1) * 8) * 2;

    float d[2][8][4];
#pragma unroll
    for (int mi = 0; mi < 2; mi++)
#pragma unroll
        for (int ni = 0; ni < 8; ni++)
#pragma unroll
            for (int k = 0; k < 4; k++) d[mi][ni][k] = 0.f;

#define YF_MMA() do {                                                           \
    _Pragma("unroll")                                                           \
    for (int k = 0; k < 4; k++) {                                               \
        const uint32_t ka = k * 32;                                             \
        const uint32_t kb = k * 16 * 144;                                       \
        uint32_t a_h[2][4], a_l[2][4];                                          \
        _Pragma("unroll")                                                       \
        for (int mi = 0; mi < 2; mi++) {                                        \
            ldsm4(a_h[mi][0], a_h[mi][1], a_h[mi][2], a_h[mi][3],               \
                  whB + aOff[mi] + ka);                                         \
            ldsm4(a_l[mi][0], a_l[mi][1], a_l[mi][2], a_l[mi][3],               \
                  wlB + aOff[mi] + ka);                                         \
        }                                                                       \
        _Pragma("unroll")                                                       \
        for (int pi = 0; pi < 4; pi++) {                                        \
            uint32_t bh[2][2];                                                  \
            ldsm4t(bh[0][0], bh[0][1], bh[1][0], bh[1][1],                      \
                   xhB + bOff[pi] + kb);                                        \
            _Pragma("unroll")                                                   \
            for (int mi = 0; mi < 2; mi++)                                      \
                _Pragma("unroll")                                               \
                for (int q = 0; q < 2; q++) {                                   \
                    mma16816h(d[mi][2*pi+q], a_h[mi], bh[q]);                   \
                    mma16816h(d[mi][2*pi+q], a_l[mi], bh[q]);                   \
                }                                                               \
        }                                                                       \
    }                                                                           \
} while (0)

    // ---- part 1: Y_diag, 4 s-tiles of 64, triangular ----
    const float* CBrow = g_CB + ((size_t)bc * CHUNK + t) * CHUNK;
    for (int st = 0; st < 4; st++) {
        const int s0 = st * 64;
        if (t >= s0) {
            __half2* wh2 = (__half2*)(Wh + t * 72);
            __half2* wl2 = (__half2*)(Wl + t * 72);
            if (t < s0 + 64) {
                // diagonal tile: per-pair exp with causal mask
#pragma unroll
                for (int j = 0; j < 64; j += 4) {
                    float4 cb4 = *(const float4*)(CBrow + s0 + j);
                    float w[4];
                    const float* cbp = (const float*)&cb4;
#pragma unroll
                    for (int e = 0; e < 4; e++) {
                        int s = s0 + j + e;
                        float arg = fminf(acs_l - sacs[s], 0.f);
                        w[e] = (s <= t) ? cbp[e] * __expf(arg) : 0.f;
                    }
                    __half2 h01, l01, h23, l23;
                    split2h(w[0], w[1], h01, l01);
                    split2h(w[2], w[3], h23, l23);
                    wh2[(j >> 1) + 0] = h01; wh2[(j >> 1) + 1] = h23;
                    wl2[(j >> 1) + 0] = l01; wl2[(j >> 1) + 1] = l23;
                }
            } else {
                // strictly-lower tile: exp(acs_l-acs_s) = rowf * scol[s]
                const float rowf = __expf(sacs[s0 + 63] >= acs_l ?
                                          acs_l - sacs[s0 + 63] : 0.f);
#pragma unroll
                for (int j = 0; j < 64; j += 4) {
                    float4 cb4 = *(const float4*)(CBrow + s0 + j);
                    float w[4];
                    const float* cbp = (const float*)&cb4;
#pragma unroll
                    for (int e = 0; e < 4; e++)
                        w[e] = cbp[e] * rowf * scol[s0 + j + e];
                    __half2 h01, l01, h23, l23;
                    split2h(w[0], w[1], h01, l01);
                    split2h(w[2], w[3], h23, l23);
                    wh2[(j >> 1) + 0] = h01; wh2[(j >> 1) + 1] = h23;
                    wl2[(j >> 1) + 0] = l01; wl2[(j >> 1) + 1] = l23;
                }
            }
        }
        // X tile (all threads)
        {
            const int r = t >> 2, c16 = (t & 3) * 16;
            const float dts = sdt[s0 + r];
            const float* xr = g_xBC + (rowB + s0 + r) * CONVDIM + h * HEADDIM + c16;
            __half2* xh2 = (__half2*)(Xh + r * 72 + c16);
#pragma unroll
            for (int j = 0; j < 16; j += 4) {
                float4 v = *(const float4*)(xr + j);
                xh2[(j >> 1) + 0] = __floats2half2_rn(v.x * dts, v.y * dts);
                xh2[(j >> 1) + 1] = __floats2half2_rn(v.z * dts, v.w * dts);
            }
        }
        __syncthreads();
        if (warp >= st * 2) {           // warps fully above diagonal skip
            YF_MMA();
        }
        __syncthreads();
    }

    // ---- part 2: Y_off, 2 n-tiles of 64 ----
    const float el = __expf(acs_l);
    const float* Crow = g_xBC + (rowB + t) * CONVDIM + DINNER + DSTATE;
    const float* S0p = g_Sinit + ((size_t)bc * NHEADS + h) * (HEADDIM * DSTATE);
    for (int nt = 0; nt < 2; nt++) {
        const int n0 = nt * 64;
        __half2* wh2 = (__half2*)(Wh + t * 72);
        __half2* wl2 = (__half2*)(Wl + t * 72);
#pragma unroll
        for (int j = 0; j < 64; j += 4) {
            float4 c4 = *(const float4*)(Crow + n0 + j);
            __half2 h01, l01, h23, l23;
            split2h(c4.x * el, c4.y * el, h01, l01);
            split2h(c4.z * el, c4.w * el, h23, l23);
            wh2[(j >> 1) + 0] = h01; wh2[(j >> 1) + 1] = h23;
            wl2[(j >> 1) + 0] = l01; wl2[(j >> 1) + 1] = l23;
        }
        {
            const int p = t >> 2, nb = (t & 3) * 16;
            const float* sp = S0p + (size_t)p * DSTATE + n0 + nb;
#pragma unroll
            for (int j = 0; j < 16; j++)
                Xh[(nb + j) * 72 + p] = __float2half(sp[j]);
        }
        __syncthreads();
        YF_MMA();
        __syncthreads();
    }
#undef YF_MMA

    const int c0 = (lane & 3) * 2;
#pragma unroll
    for (int mi = 0; mi < 2; mi++) {
        const size_t gr0 = (rowB + warp * 32 + (lane >> 2) + mi * 16) * DINNER + h * HEADDIM;
#pragma unroll
        for (int ni = 0; ni < 8; ni++) {
            int col = c0 + ni * 8;
            *(float2*)&g_Y[gr0 + col] = make_float2(d[mi][ni][0], d[mi][ni][1]);
            *(float2*)&g_Y[gr0 + 8 * DINNER + col] = make_float2(d[mi][ni][2], d[mi][ni][3]);
        }
    }
}

// ---------------- state S = x^T . (w.B)  (fp16: x single, w.B split) --------
#define ST_A     0
#define ST_BH    9216                // 64*72*2
#define ST_BL    26624               // + 64*136*2
#define ST_SMEM  44032

__global__ __launch_bounds__(256, 2) void state_mma_kernel()
{
    extern __shared__ char ssm[];
    __half* Ax = (__half*)(ssm + ST_A);    // [p(64)][s(72 pad)]
    __half* Bh = (__half*)(ssm + ST_BH);   // [s(64)][n(136 pad)]
    __half* Bl = (__half*)(ssm + ST_BL);

    const int bc = blockIdx.x, h = blockIdx.y;
    const int b = bc >> 4, c = bc & 15;
    const int t = threadIdx.x;
    const size_t rowB = (size_t)b * SEQLEN + c * CHUNK;
    const float asum = g_asum[bc * NHEADS + h];
    const float* acsp = g_acs + ((size_t)bc * NHEADS + h) * CHUNK;

    const int lane = t & 31, warp = t >> 5;
    const int wm = warp >> 2, wn = warp & 3;
    const int grp = lane >> 3, rr = lane & 7;
    const uint32_t axB = s2u(Ax), bhB = s2u(Bh), blB = s2u(Bl);

    uint32_t aOff[2], bOff[2];
#pragma unroll
    for (int mi = 0; mi < 2; mi++)
        aOff[mi] = ((wm * 32 + mi * 16 + (grp & 1) * 8 + rr) * 72
                    + (grp >> 1) * 8) * 2;
#pragma unroll
    for (int pi = 0; pi < 2; pi++)
        bOff[pi] = (((grp & 1) * 8 + rr) * 136
                    + wn * 32 + pi * 16 + (grp >> 1) * 8) * 2;

    float d[2][4][4];
#pragma unroll
    for (int mi = 0; mi < 2; mi++)
#pragma unroll
        for (int ni = 0; ni < 4; ni++)
#pragma unroll
            for (int k = 0; k < 4; k++) d[mi][ni][k] = 0.f;

    for (int st4 = 0; st4 < 4; st4++) {
        const int s0 = st4 * 64;
        const int r = t >> 2;
        const float w = g_dt[(rowB + s0 + r) * NHEADS + h] *
                        __expf(asum - acsp[s0 + r]);
        {
            const int q = (t & 3) * 16;
            const float* xr = g_xBC + (rowB + s0 + r) * CONVDIM + h * HEADDIM + q;
#pragma unroll
            for (int j = 0; j < 16; j += 4) {
                float4 v = *(const float4*)(xr + j);
                Ax[(q + j + 0) * 72 + r] = __float2half(v.x);
                Ax[(q + j + 1) * 72 + r] = __float2half(v.y);
                Ax[(q + j + 2) * 72 + r] = __float2half(v.z);
                Ax[(q + j + 3) * 72 + r] = __float2half(v.w);
            }
        }
        {
            const int nq = (t & 3) * 32;
            const float* brp = g_xBC + (rowB + s0 + r) * CONVDIM + DINNER + nq;
            __half2* bh2 = (__half2*)(Bh + r * 136 + nq);
            __half2* bl2 = (__half2*)(Bl + r * 136 + nq);
#pragma unroll
            for (int j = 0; j < 32; j += 4) {
                float4 v = *(const float4*)(brp + j);
                __half2 h01, l01, h23, l23;
                split2h(v.x * w, v.y * w, h01, l01);
                split2h(v.z * w, v.w * w, h23, l23);
                bh2[(j >> 1) + 0] = h01; bh2[(j >> 1) + 1] = h23;
                bl2[(j >> 1) + 0] = l01; bl2[(j >> 1) + 1] = l23;
            }
        }
        __syncthreads();
#pragma unroll
        for (int k = 0; k < 4; k++) {
            const uint32_t ka = k * 32;
            const uint32_t kb = (uint32_t)k * 16 * 136 * 2;
            uint32_t a_f[2][4], bhf[4][2], blf[4][2];
#pragma unroll
            for (int mi = 0; mi < 2; mi++)
                ldsm4(a_f[mi][0], a_f[mi][1], a_f[mi][2], a_f[mi][3],
                      axB + aOff[mi] + ka);
#pragma unroll
            for (int pi = 0; pi < 2; pi++) {
                ldsm4t(bhf[2*pi][0], bhf[2*pi][1], bhf[2*pi+1][0], bhf[2*pi+1][1],
                       bhB + bOff[pi] + kb);
                ldsm4t(blf[2*pi][0], blf[2*pi][1], blf[2*pi+1][0], blf[2*pi+1][1],
                       blB + bOff[pi] + kb);
            }
#pragma unroll
            for (int mi = 0; mi < 2; mi++)
#pragma unroll
                for (int ni = 0; ni < 4; ni++) {
                    mma16816h(d[mi][ni], a_f[mi], bhf[ni]);
                    mma16816h(d[mi][ni], a_f[mi], blf[ni]);
                }
        }
        __syncthreads();
    }

    float* Sout = g_S + ((size_t)bc * NHEADS + h) * (HEADDIM * DSTATE);
    const int p0 = wm * 32 + (lane >> 2);
    const int n0 = wn * 32 + (lane & 3) * 2;
#pragma unroll
    for (int mi = 0; mi < 2; mi++)
#pragma unroll
        for (int ni = 0; ni < 4; ni++) {
            int col = n0 + ni * 8;
            *(float2*)&Sout[(size_t)(p0 + mi * 16) * DSTATE + col] =
                make_float2(d[mi][ni][0], d[mi][ni][1]);
            *(float2*)&Sout[(size_t)(p0 + mi * 16 + 8) * DSTATE + col] =
                make_float2(d[mi][ni][2], d[mi][ni][3]);
        }
}

// ---------------- convert kernels -------------------------------------------
__global__ void tofp16_kernel(const float* __restrict__ x, __half* __restrict__ o, size_t n)
{
    size_t i = (size_t)blockIdx.x * blockDim.x + threadIdx.x;
    if (i >= n) return;
    o[i] = __float2half(x[i]);
}

__global__ void tofp16_pad_kernel(const float* __restrict__ x, __half* __restrict__ o,
                                  int K, int N, int Np)
{
    size_t i = (size_t)blockIdx.x * blockDim.x + threadIdx.x;
    if (i >= (size_t)K * Np) return;
    int r = (int)(i / Np), c = (int)(i % Np);
    o[i] = __float2half((c < N) ? x[(size_t)r * N + c] : 0.f);
}

// ---------------- causal conv1d + SiLU: 4 outputs per thread ----------------
__global__ void conv_silu_kernel(const float* __restrict__ conv_w,
                                 const float* __restrict__ conv_b)
{
    int idx = blockIdx.x * blockDim.x + threadIdx.x;
    if (idx >= (ROWS / 4) * CONVDIM) return;
    int c  = idx % CONVDIM;
    int rg = idx / CONVDIM;
    int row0 = rg * 4;
    int l0 = row0 & (SEQLEN - 1);
    const float* base = g_zxbcdt + (size_t)row0 * DPROJ + DINNER + c;
    const float w0 = conv_w[c * DCONV + 0], w1 = conv_w[c * DCONV + 1];
    const float w2 = conv_w[c * DCONV + 2], w3 = conv_w[c * DCONV + 3];
    const float bias = conv_b[c];
    float v[7];
#pragma unroll
    for (int j = 0; j < 7; j++) {
        int l = l0 - 3 + j;
        v[j] = (l >= 0) ? base[(long)(j - 3) * DPROJ] : 0.f;
    }
#pragma unroll
    for (int i = 0; i < 4; i++) {
        float acc = bias + v[i] * w0 + v[i+1] * w1 + v[i+2] * w2 + v[i+3] * w3;
        g_xBC[(size_t)(row0 + i) * CONVDIM + c] = acc / (1.f + __expf(-acc));
    }
}

// ---------------- fused dt softplus + per-chunk cumsum ----------------------
__global__ void ascan_kernel(const float* __restrict__ A_log,
                             const float* __restrict__ dt_bias)
{
    int bc = blockIdx.x;
    int h  = blockIdx.y;
    int t  = threadIdx.x;
    int b = bc >> 4, c = bc & 15;
    __shared__ float sa[CHUNK];
    int row = b * SEQLEN + c * CHUNK + t;
    float v = g_zxbcdt[(size_t)row * DPROJ + DT_OFF + h] + dt_bias[h];
    float dtv = (v > 20.f) ? v : log1pf(expf(v));
    g_dt[row * NHEADS + h] = dtv;
    float A = -expf(A_log[h]);
    sa[t] = A * dtv;
    __syncthreads();
    for (int off = 1; off < CHUNK; off <<= 1) {
        float vv = (t >= off) ? sa[t - off] : 0.f;
        __syncthreads();
        sa[t] += vv;
        __syncthreads();
    }
    g_acs[(bc * NHEADS + h) * CHUNK + t] = sa[t];
    if (t == CHUNK - 1) g_asum[bc * NHEADS + h] = sa[t];
}

// ---------------- sequential inter-chunk recurrence (4-way split) -----------
__global__ void chunkrec_kernel()
{
    int b = blockIdx.x, h = blockIdx.y, z = blockIdx.z;
    int t = threadIdx.x;
    float cur[8];
#pragma unroll
    for (int k = 0; k < 8; k++) cur[k] = 0.f;
    for (int c = 0; c < NCHUNK; c++) {
        int bc = b * NCHUNK + c;
        size_t base = ((size_t)bc * NHEADS + h) * (HEADDIM * DSTATE) + z * 2048;
        float dd = __expf(g_asum[bc * NHEADS + h]);
#pragma unroll
        for (int k = 0; k < 8; k++) {
            size_t e = base + t + 256 * k;
            g_Sinit[e] = cur[k];
            cur[k] = cur[k] * dd + g_S[e];
        }
    }
}

// ---------------- layernorm + z-gate -> fp16 yg ----------------------------
__global__ __launch_bounds__(256) void normgate_kernel(const float* __restrict__ norm_w)
{
    int row = blockIdx.x;
    int t = threadIdx.x;
    const float* yrow = g_Y + (size_t)row * DINNER;
    const float* zrow = g_zxbcdt + (size_t)row * DPROJ;
    float v[8];
    float s = 0.f;
#pragma unroll
    for (int i = 0; i < 8; i++) { v[i] = yrow[t + 256*i]; s += v[i]; }
    __shared__ float red[256];
    red[t] = s; __syncthreads();
    for (int o = 128; o > 0; o >>= 1) { if (t < o) red[t] += red[t+o]; __syncthreads(); }
    float mu = red[0] * (1.f / DINNER);
    __syncthreads();
    float s2 = 0.f;
#pragma unroll
    for (int i = 0; i < 8; i++) { float dv = v[i] - mu; s2 += dv * dv; }
    red[t] = s2; __syncthreads();
    for (int o = 128; o > 0; o >>= 1) { if (t < o) red[t] += red[t+o]; __syncthreads(); }
    float inv = rsqrtf(red[0] * (1.f / DINNER) + 1e-5f);
    __half* orow = g_yg + (size_t)row * DINNER;
#pragma unroll
    for (int i = 0; i < 8; i++) {
        int idx = t + 256*i;
        float z = zrow[idx];
        float g = z / (1.f + __expf(-z));
        orow[idx] = __float2half((v[i] - mu) * inv * norm_w[idx] * g);
    }
}

// ---------------- launch ---------------------------------------------------
extern "C" void kernel_launch(void* const* d_in, const int* in_sizes, int n_in,
                              void* d_out, int out_size)
{
    const float* u       = (const float*)d_in[0];
    const float* W_in    = (const float*)d_in[1];
    const float* conv_w  = (const float*)d_in[2];
    const float* conv_b  = (const float*)d_in[3];
    const float* dt_bias = (const float*)d_in[4];
    const float* A_log   = (const float*)d_in[5];
    const float* norm_w  = (const float*)d_in[6];
    const float* W_out   = (const float*)d_in[7];
    float* out = (float*)d_out;

    float* p_zx = nullptr;
    __half *p_uf, *p_wif, *p_wof, *p_yg;
    cudaGetSymbolAddress((void**)&p_zx,  g_zxbcdt);
    cudaGetSymbolAddress((void**)&p_uf,  g_uf);
    cudaGetSymbolAddress((void**)&p_wif, g_wif);
    cudaGetSymbolAddress((void**)&p_wof, g_wof);
    cudaGetSymbolAddress((void**)&p_yg,  g_yg);

    cudaFuncSetAttribute(mma_gemm, cudaFuncAttributeMaxDynamicSharedMemorySize, GEMM_SMEM);
    cudaFuncSetAttribute(yfused_kernel, cudaFuncAttributeMaxDynamicSharedMemorySize, YF_SMEM);
    cudaFuncSetAttribute(state_mma_kernel, cudaFuncAttributeMaxDynamicSharedMemorySize, ST_SMEM);
    cudaFuncSetAttribute(cb_mma_kernel, cudaFuncAttributeMaxDynamicSharedMemorySize, CB_SMEM);

    // 0. fp16 conversions
    {
        size_t n = (size_t)ROWS * DMODEL;
        tofp16_kernel<<<(unsigned)((n + 255) / 256), 256>>>(u, p_uf, n);
    }
    tofp16_pad_kernel<<<(unsigned)(((size_t)DMODEL * NPAD1 + 255) / 256), 256>>>(
        W_in, p_wif, DMODEL, DPROJ, NPAD1);
    {
        size_t n = (size_t)DINNER * DMODEL;
        tofp16_kernel<<<(unsigned)((n + 255) / 256), 256>>>(W_out, p_wof, n);
    }

    // 1. zxbcdt = u @ W_in  (8192 x 4384 x 1024)
    mma_gemm<<<dim3(NPAD1 / 128, ROWS / 128), 256, GEMM_SMEM>>>(
        p_uf, p_wif, p_zx, ROWS, DPROJ, DMODEL, NPAD1, DPROJ);
    // 2. causal conv1d + SiLU (4 l per thread)
    conv_silu_kernel<<<((ROWS / 4) * CONVDIM + 255) / 256, 256>>>(conv_w, conv_b);
    // 3. fused dt softplus + per-chunk cumsum
    ascan_kernel<<<dim3(NBC, NHEADS), CHUNK>>>(A_log, dt_bias);
    // 4. CB gram matrices (tensor cores, bf16 3-term)
    cb_mma_kernel<<<dim3(NBC, 4), 256, CB_SMEM>>>();
    // 5. per-chunk end states (tensor cores, fp16 2-term)
    state_mma_kernel<<<dim3(NBC, NHEADS), 256, ST_SMEM>>>();
    // 6. inter-chunk recurrence (4-way parallel over state elems)
    chunkrec_kernel<<<dim3(BATCH, NHEADS, 4), 256>>>();
    // 7. fused Y_diag + Y_off (tensor cores, factored decay + tri skip)
    yfused_kernel<<<dim3(NBC, NHEADS), 256, YF_SMEM>>>();
    // 8. layernorm + silu(z) gate -> fp16
    normgate_kernel<<<ROWS, 256>>>(norm_w);
    // 9. out = yg @ W_out  (8192 x 1024 x 2048)
    mma_gemm<<<dim3(DMODEL / 128, ROWS / 128), 256, GEMM_SMEM>>>(
        p_yg, p_wof, out, ROWS, DMODEL, DINNER, DMODEL, DMODEL);
}

// round 15
// speedup vs baseline: 1.9786x; 1.0340x over previous
#include <cuda_runtime.h>
#include <cuda_bf16.h>
#include <cuda_fp16.h>
#include <math.h>
#include <stdint.h>

#define BATCH   2
#define SEQLEN  4096
#define DMODEL  1024
#define DINNER  2048
#define HEADDIM 64
#define NHEADS  32
#define DSTATE  128
#define DCONV   4
#define CHUNK   256
#define NCHUNK  (SEQLEN / CHUNK)   // 16
#define NBC     (BATCH * NCHUNK)   // 32
#define DPROJ   4384               // 2*DINNER + 2*DSTATE + NHEADS
#define CONVDIM 2304               // DINNER + 2*DSTATE
#define DT_OFF  4352               // 2*DINNER + 2*DSTATE
#define ROWS    (BATCH * SEQLEN)   // 8192
#define NPAD1   4480               // DPROJ padded to multiple of 128

// ---------------- scratch (device globals; no allocation allowed) ----------
__device__ float g_zxbcdt[(size_t)ROWS * DPROJ];
__device__ float g_xBC[(size_t)ROWS * CONVDIM];
__device__ float g_dt[ROWS * NHEADS];
__device__ float g_acs[NBC * NHEADS * CHUNK];
__device__ float g_asum[NBC * NHEADS];
__device__ float g_CB[(size_t)NBC * CHUNK * CHUNK];
__device__ float g_Y[(size_t)ROWS * DINNER];
__device__ float g_S[(size_t)NBC * NHEADS * HEADDIM * DSTATE];
__device__ float g_Sinit[(size_t)NBC * NHEADS * HEADDIM * DSTATE];

// fp16 GEMM operands
__device__ __half g_uf[(size_t)ROWS * DMODEL];
__device__ __half g_wif[(size_t)DMODEL * NPAD1];
__device__ __half g_wof[(size_t)DINNER * DMODEL];
__device__ __half g_yg[(size_t)ROWS * DINNER];

// ---------------- helpers ---------------------------------------------------
__device__ __forceinline__ uint32_t s2u(const void* p) {
    return (uint32_t)__cvta_generic_to_shared(p);
}
#define CP16(dst, src) \
    asm volatile("cp.async.cg.shared.global [%0], [%1], 16;\n" :: "r"(dst), "l"(src))
#define CP_COMMIT() asm volatile("cp.async.commit_group;\n")
#define CP_WAIT1()  asm volatile("cp.async.wait_group 1;\n")

__device__ __forceinline__ void ldsm4(uint32_t& r0, uint32_t& r1, uint32_t& r2,
                                      uint32_t& r3, uint32_t addr) {
    asm volatile("ldmatrix.sync.aligned.m8n8.x4.shared.b16 {%0,%1,%2,%3}, [%4];"
                 : "=r"(r0), "=r"(r1), "=r"(r2), "=r"(r3) : "r"(addr));
}
__device__ __forceinline__ void ldsm4t(uint32_t& r0, uint32_t& r1, uint32_t& r2,
                                       uint32_t& r3, uint32_t addr) {
    asm volatile("ldmatrix.sync.aligned.m8n8.x4.trans.shared.b16 {%0,%1,%2,%3}, [%4];"
                 : "=r"(r0), "=r"(r1), "=r"(r2), "=r"(r3) : "r"(addr));
}
// fp16 mma
__device__ __forceinline__ void mma16816h(float* d, const uint32_t* a, const uint32_t* b) {
    asm volatile(
        "mma.sync.aligned.m16n8k16.row.col.f32.f16.f16.f32 "
        "{%0,%1,%2,%3}, {%4,%5,%6,%7}, {%8,%9}, {%0,%1,%2,%3};"
        : "+f"(d[0]), "+f"(d[1]), "+f"(d[2]), "+f"(d[3])
        : "r"(a[0]), "r"(a[1]), "r"(a[2]), "r"(a[3]), "r"(b[0]), "r"(b[1]));
}
// bf16 mma (cb)
__device__ __forceinline__ void mma16816(float* d, const uint32_t* a, const uint32_t* b) {
    asm volatile(
        "mma.sync.aligned.m16n8k16.row.col.f32.bf16.bf16.f32 "
        "{%0,%1,%2,%3}, {%4,%5,%6,%7}, {%8,%9}, {%0,%1,%2,%3};"
        : "+f"(d[0]), "+f"(d[1]), "+f"(d[2]), "+f"(d[3])
        : "r"(a[0]), "r"(a[1]), "r"(a[2]), "r"(a[3]), "r"(b[0]), "r"(b[1]));
}
__device__ __forceinline__ void split2(float a, float b,
                                       __nv_bfloat162& h, __nv_bfloat162& l) {
    __nv_bfloat16 ha = __float2bfloat16(a), hb = __float2bfloat16(b);
    h = __halves2bfloat162(ha, hb);
    l = __halves2bfloat162(__float2bfloat16(a - __bfloat162float(ha)),
                           __float2bfloat16(b - __bfloat162float(hb)));
}
__device__ __forceinline__ void split2h(float a, float b, __half2& h, __half2& l) {
    __half ha = __float2half(a), hb = __float2half(b);
    h = __halves2half2(ha, hb);
    l = __halves2half2(__float2half(a - __half2float(ha)),
                       __float2half(b - __half2float(hb)));
}

// ---------------- GEMM smem layout (bytes), tile 128x128, BK=64 -------------
// per stage: A[128][72] | B[64][136]   (fp16)
#define A_B        18432         // 128*72*2
#define B_B        17408         // 64*136*2
#define OFF_B      A_B
#define STAGE_B    (A_B + B_B)                     // 35840
#define NSTAGE     3
#define GEMM_SMEM  (NSTAGE * STAGE_B)              // 107520

// ---------------- fp16 tensor-core GEMM, BK=64, 2 CTAs/SM -------------------
__global__ __launch_bounds__(256, 2) void mma_gemm(
    const __half* __restrict__ A, const __half* __restrict__ B,
    float* __restrict__ C, int M, int N, int K, int ldb, int ldc)
{
    extern __shared__ __half smem[];
    const uint32_t sbase = s2u(smem);
    const int rowBase = blockIdx.y * 128;
    const int colBase = blockIdx.x * 128;
    const int t = threadIdx.x;

    // A: 1024 chunks/slab; thread t owns t, t+256, t+512, t+768 (rows +32 each)
    const int ar = t >> 3, aq = t & 7;
    const __half* aS = A + (size_t)(rowBase + ar) * K + aq * 8;
    const uint32_t aD = sbase + (ar * 72 + aq * 8) * 2;
    // B: 1024 chunks/slab; thread t owns t, +256... (k-rows +16 each)
    const int br = t >> 4, bq = t & 15;
    const __half* bS = B + (size_t)br * ldb + colBase + bq * 8;
    const uint32_t bD = sbase + OFF_B + (br * 136 + bq * 8) * 2;

    const int lane = t & 31, warp = t >> 5;
    const int wm = warp >> 2, wn = warp & 3;
    const int grp = lane >> 3, rr = lane & 7;

    uint32_t aAddr[4], bAddr[2];
#pragma unroll
    for (int mi = 0; mi < 4; mi++)
        aAddr[mi] = sbase + ((wm * 64 + mi * 16 + (grp & 1) * 8 + rr) * 72
                             + (grp >> 1) * 8) * 2;
#pragma unroll
    for (int pi = 0; pi < 2; pi++)
        bAddr[pi] = sbase + OFF_B + (((grp & 1) * 8 + rr) * 136
                             + wn * 32 + pi * 16 + (grp >> 1) * 8) * 2;

    float d[4][4][4];
#pragma unroll
    for (int mi = 0; mi < 4; mi++)
#pragma unroll
        for (int ni = 0; ni < 4; ni++)
#pragma unroll
            for (int k = 0; k < 4; k++) d[mi][ni][k] = 0.f;

    const int nk = K / 64;

#define LOAD_SLAB(st, kt) do {                                                  \
    const uint32_t _d = (st) * STAGE_B;                                         \
    const int _k = (kt) * 64;                                                   \
    _Pragma("unroll")                                                           \
    for (int i = 0; i < 4; i++)                                                 \
        CP16(aD + _d + (uint32_t)i * 32 * 72 * 2,                               \
             aS + (size_t)(i * 32) * K + _k);                                   \
    _Pragma("unroll")                                                           \
    for (int i = 0; i < 4; i++)                                                 \
        CP16(bD + _d + (uint32_t)i * 16 * 136 * 2,                              \
             bS + (size_t)(_k + i * 16) * ldb);                                 \
} while (0)

#define FRAGS_MMA(sd, ks) do {                                                  \
    const uint32_t _ka = (ks) * 32;                                             \
    const uint32_t _kb = (uint32_t)(ks) * 16 * 136 * 2;                         \
    uint32_t a_f[4][4], b_f[4][2];                                              \
    _Pragma("unroll")                                                           \
    for (int mi = 0; mi < 4; mi++)                                              \
        ldsm4(a_f[mi][0], a_f[mi][1], a_f[mi][2], a_f[mi][3],                   \
              aAddr[mi] + (sd) + _ka);                                          \
    _Pragma("unroll")                                                           \
    for (int pi = 0; pi < 2; pi++)                                              \
        ldsm4t(b_f[2*pi][0], b_f[2*pi][1], b_f[2*pi+1][0], b_f[2*pi+1][1],      \
               bAddr[pi] + (sd) + _kb);                                         \
    _Pragma("unroll")                                                           \
    for (int mi = 0; mi < 4; mi++)                                              \
        _Pragma("unroll")                                                       \
        for (int ni = 0; ni < 4; ni++)                                          \
            mma16816h(d[mi][ni], a_f[mi], b_f[ni]);                             \
} while (0)

    LOAD_SLAB(0, 0); CP_COMMIT();
    LOAD_SLAB(1, 1); CP_COMMIT();
    CP_WAIT1();
    __syncthreads();

    for (int kt = 0; kt < nk; kt++) {
        const uint32_t sd = (uint32_t)(kt % 3) * STAGE_B;
        if (kt + 2 < nk) LOAD_SLAB((kt + 2) % 3, kt + 2);
        CP_COMMIT();
        FRAGS_MMA(sd, 0);
        FRAGS_MMA(sd, 1);
        FRAGS_MMA(sd, 2);
        FRAGS_MMA(sd, 3);
        if (kt + 1 < nk) {
            CP_WAIT1();
            __syncthreads();
        }
    }

    const int r0 = rowBase + wm * 64 + (lane >> 2);
    const int c0 = colBase + wn * 32 + (lane & 3) * 2;
#pragma unroll
    for (int mi = 0; mi < 4; mi++)
#pragma unroll
        for (int ni = 0; ni < 4; ni++) {
            int col = c0 + ni * 8;
            if (col < N) {
                float2 v0 = make_float2(d[mi][ni][0], d[mi][ni][1]);
                float2 v1 = make_float2(d[mi][ni][2], d[mi][ni][3]);
                *(float2*)&C[(size_t)(r0 + mi * 16) * ldc + col] = v0;
                *(float2*)&C[(size_t)(r0 + mi * 16 + 8) * ldc + col] = v1;
            }
        }
#undef LOAD_SLAB
#undef FRAGS_MMA
}

// ---------------- CB gram via mma (bf16 3-term) -----------------------------
#define CB_AH    0
#define CB_AL    17408               // 64*136*2
#define CB_BH    34816
#define CB_BL    52224
#define CB_SMEM  69632

__global__ __launch_bounds__(256, 2) void cb_mma_kernel()
{
    extern __shared__ char csm[];
    __nv_bfloat16* Ah = (__nv_bfloat16*)(csm + CB_AH);
    __nv_bfloat16* Al = (__nv_bfloat16*)(csm + CB_AL);
    __nv_bfloat16* Bh = (__nv_bfloat16*)(csm + CB_BH);
    __nv_bfloat16* Bl = (__nv_bfloat16*)(csm + CB_BL);

    const int bc = blockIdx.x, lt = blockIdx.y;
    const int b = bc >> 4, c = bc & 15;
    const int t = threadIdx.x;
    const size_t rowB = (size_t)b * SEQLEN + c * CHUNK;

    const int lane = t & 31, warp = t >> 5;
    const int wm = warp >> 2, wn = warp & 3;
    const int grp = lane >> 3, rr = lane & 7;
    const uint32_t ahB = s2u(Ah), alB = s2u(Al), bhB = s2u(Bh), blB = s2u(Bl);

    {
        const int r = t >> 2, q = (t & 3) * 32;
        const float* cr = g_xBC + (rowB + lt * 64 + r) * CONVDIM
                          + (DINNER + DSTATE) + q;
        __nv_bfloat162* ah2 = (__nv_bfloat162*)(Ah + r * 136 + q);
        __nv_bfloat162* al2 = (__nv_bfloat162*)(Al + r * 136 + q);
#pragma unroll
        for (int j = 0; j < 32; j += 4) {
            float4 v = *(const float4*)(cr + j);
            __nv_bfloat162 h01, l01, h23, l23;
            split2(v.x, v.y, h01, l01);
            split2(v.z, v.w, h23, l23);
            ah2[(j >> 1) + 0] = h01; ah2[(j >> 1) + 1] = h23;
            al2[(j >> 1) + 0] = l01; al2[(j >> 1) + 1] = l23;
        }
    }

    uint32_t aOff[2];
#pragma unroll
    for (int mi = 0; mi < 2; mi++)
        aOff[mi] = ((wm * 32 + mi * 16 + (grp & 1) * 8 + rr) * 136
                    + (grp >> 1) * 8) * 2;
    const uint32_t bOff = ((wn * 16 + (grp & 1) * 8 + rr) * 136
                           + (grp >> 1) * 8) * 2;

    float d[2][8][4];
#pragma unroll
    for (int mi = 0; mi < 2; mi++)
#pragma unroll
        for (int ni = 0; ni < 8; ni++)
#pragma unroll
            for (int k = 0; k < 4; k++) d[mi][ni][k] = 0.f;

    for (int stile = 0; stile < 4; stile++) {
        {
            const int r = t >> 2, q = (t & 3) * 32;
            const float* br = g_xBC + (rowB + stile * 64 + r) * CONVDIM
                              + DINNER + q;
            __nv_bfloat162* bh2 = (__nv_bfloat162*)(Bh + r * 136 + q);
            __nv_bfloat162* bl2 = (__nv_bfloat162*)(Bl + r * 136 + q);
#pragma unroll
            for (int j = 0; j < 32; j += 4) {
                float4 v = *(const float4*)(br + j);
                __nv_bfloat162 h01, l01, h23, l23;
                split2(v.x, v.y, h01, l01);
                split2(v.z, v.w, h23, l23);
                bh2[(j >> 1) + 0] = h01; bh2[(j >> 1) + 1] = h23;
                bl2[(j >> 1) + 0] = l01; bl2[(j >> 1) + 1] = l23;
            }
        }
        __syncthreads();
#pragma unroll
        for (int k = 0; k < 8; k++) {
            const uint32_t ko = k * 32;
            uint32_t a_h[2][4], a_l[2][4], b4h[4], b4l[4];
#pragma unroll
            for (int mi = 0; mi < 2; mi++) {
                ldsm4(a_h[mi][0], a_h[mi][1], a_h[mi][2], a_h[mi][3],
                      ahB + aOff[mi] + ko);
                ldsm4(a_l[mi][0], a_l[mi][1], a_l[mi][2], a_l[mi][3],
                      alB + aOff[mi] + ko);
            }
            ldsm4(b4h[0], b4h[1], b4h[2], b4h[3], bhB + bOff + ko);
            ldsm4(b4l[0], b4l[1], b4l[2], b4l[3], blB + bOff + ko);
            uint32_t bh0[2] = {b4h[0], b4h[2]};
            uint32_t bh1[2] = {b4h[1], b4h[3]};
            uint32_t bl0[2] = {b4l[0], b4l[2]};
            uint32_t bl1[2] = {b4l[1], b4l[3]};
#pragma unroll
            for (int mi = 0; mi < 2; mi++) {
                mma16816(d[mi][stile * 2 + 0], a_h[mi], bh0);
                mma16816(d[mi][stile * 2 + 0], a_h[mi], bl0);
                mma16816(d[mi][stile * 2 + 0], a_l[mi], bh0);
                mma16816(d[mi][stile * 2 + 1], a_h[mi], bh1);
                mma16816(d[mi][stile * 2 + 1], a_h[mi], bl1);
                mma16816(d[mi][stile * 2 + 1], a_l[mi], bh1);
            }
        }
        __syncthreads();
    }

    const int r0 = lt * 64 + wm * 32 + (lane >> 2);
    const int c0 = (lane & 3) * 2;
#pragma unroll
    for (int mi = 0; mi < 2; mi++) {
        float* out0 = g_CB + ((size_t)bc * CHUNK + r0 + mi * 16) * CHUNK;
        float* out1 = out0 + 8 * CHUNK;
#pragma unroll
        for (int st = 0; st < 4; st++)
#pragma unroll
            for (int q = 0; q < 2; q++) {
                int col = st * 64 + wn * 16 + q * 8 + c0;
                float* dd = d[mi][st * 2 + q];
                *(float2*)&out0[col] = make_float2(dd[0], dd[1]);
                *(float2*)&out1[col] = make_float2(dd[2], dd[3]);
            }
    }
}

// ---------------- fused Y (fp16, factored decay + triangular skip) ----------
#define YF_WH    0
#define YF_WL    36864               // 256*72*2
#define YF_XH    73728               // 64*72*2 = 9216
#define YF_ACS   82944
#define YF_DT    83968
#define YF_SCOL  84992
#define YF_SMEM  86016

__global__ __launch_bounds__(256, 2) void yfused_kernel()
{
    extern __shared__ char ysm[];
    __half* Wh = (__half*)(ysm + YF_WH);
    __half* Wl = (__half*)(ysm + YF_WL);
    __half* Xh = (__half*)(ysm + YF_XH);
    float* sacs = (float*)(ysm + YF_ACS);
    float* sdt  = (float*)(ysm + YF_DT);
    float* scol = (float*)(ysm + YF_SCOL);

    const int bc = blockIdx.x, h = blockIdx.y;
    const int b = bc >> 4, c = bc & 15;
    const int t = threadIdx.x;
    const size_t rowB = (size_t)b * SEQLEN + c * CHUNK;

    sacs[t] = g_acs[((size_t)bc * NHEADS + h) * CHUNK + t];
    sdt[t]  = g_dt[(rowB + t) * NHEADS + h];
    __syncthreads();
    const float acs_l = sacs[t];
    scol[t] = __expf(sacs[t | 63] - acs_l);
    __syncthreads();

    const int lane = t & 31, warp = t >> 5;
    const int grp = lane >> 3, rr = lane & 7;
    const uint32_t whB = s2u(Wh), wlB = s2u(Wl), xhB = s2u(Xh);

    uint32_t aOff[2], bOff[4];
#pragma unroll
    for (int mi = 0; mi < 2; mi++)
        aOff[mi] = ((warp * 32 + mi * 16 + (grp & 1) * 8 + rr) * 72
                    + (grp >> 1) * 8) * 2;
#pragma unroll
    for (int pi = 0; pi < 4; pi++)
        bOff[pi] = (((grp & 1) * 8 + rr) * 72 + pi * 16 + (grp >> 1) * 8) * 2;

    float d[2][8][4];
#pragma unroll
    for (int mi = 0; mi < 2; mi++)
#pragma unroll
        for (int ni = 0; ni < 8; ni++)
#pragma unroll
            for (int k = 0; k < 4; k++) d[mi][ni][k] = 0.f;

#define YF_MMA() do {                                                           \
    _Pragma("unroll")                                                           \
    for (int k = 0; k < 4; k++) {                                               \
        const uint32_t ka = k * 32;                                             \
        const uint32_t kb = k * 16 * 144;                                       \
        uint32_t a_h[2][4], a_l[2][4];                                          \
        _Pragma("unroll")                                                       \
        for (int mi = 0; mi < 2; mi++) {                                        \
            ldsm4(a_h[mi][0], a_h[mi][1], a_h[mi][2], a_h[mi][3],               \
                  whB + aOff[mi] + ka);                                         \
            ldsm4(a_l[mi][0], a_l[mi][1], a_l[mi][2], a_l[mi][3],               \
                  wlB + aOff[mi] + ka);                                         \
        }                                                                       \
        _Pragma("unroll")                                                       \
        for (int pi = 0; pi < 4; pi++) {                                        \
            uint32_t bh[2][2];                                                  \
            ldsm4t(bh[0][0], bh[0][1], bh[1][0], bh[1][1],                      \
                   xhB + bOff[pi] + kb);                                        \
            _Pragma("unroll")                                                   \
            for (int mi = 0; mi < 2; mi++)                                      \
                _Pragma("unroll")                                               \
                for (int q = 0; q < 2; q++) {                                   \
                    mma16816h(d[mi][2*pi+q], a_h[mi], bh[q]);                   \
                    mma16816h(d[mi][2*pi+q], a_l[mi], bh[q]);                   \
                }                                                               \
        }                                                                       \
    }                                                                           \
} while (0)

    // ---- part 1: Y_diag, 4 s-tiles of 64, triangular ----
    const float* CBrow = g_CB + ((size_t)bc * CHUNK + t) * CHUNK;
    for (int st = 0; st < 4; st++) {
        const int s0 = st * 64;
        if (t >= s0) {
            __half2* wh2 = (__half2*)(Wh + t * 72);
            __half2* wl2 = (__half2*)(Wl + t * 72);
            if (t < s0 + 64) {
#pragma unroll
                for (int j = 0; j < 64; j += 4) {
                    float4 cb4 = *(const float4*)(CBrow + s0 + j);
                    float w[4];
                    const float* cbp = (const float*)&cb4;
#pragma unroll
                    for (int e = 0; e < 4; e++) {
                        int s = s0 + j + e;
                        float arg = fminf(acs_l - sacs[s], 0.f);
                        w[e] = (s <= t) ? cbp[e] * __expf(arg) : 0.f;
                    }
                    __half2 h01, l01, h23, l23;
                    split2h(w[0], w[1], h01, l01);
                    split2h(w[2], w[3], h23, l23);
                    wh2[(j >> 1) + 0] = h01; wh2[(j >> 1) + 1] = h23;
                    wl2[(j >> 1) + 0] = l01; wl2[(j >> 1) + 1] = l23;
                }
            } else {
                const float rowf = __expf(sacs[s0 + 63] >= acs_l ?
                                          acs_l - sacs[s0 + 63] : 0.f);
#pragma unroll
                for (int j = 0; j < 64; j += 4) {
                    float4 cb4 = *(const float4*)(CBrow + s0 + j);
                    float w[4];
                    const float* cbp = (const float*)&cb4;
#pragma unroll
                    for (int e = 0; e < 4; e++)
                        w[e] = cbp[e] * rowf * scol[s0 + j + e];
                    __half2 h01, l01, h23, l23;
                    split2h(w[0], w[1], h01, l01);
                    split2h(w[2], w[3], h23, l23);
                    wh2[(j >> 1) + 0] = h01; wh2[(j >> 1) + 1] = h23;
                    wl2[(j >> 1) + 0] = l01; wl2[(j >> 1) + 1] = l23;
                }
            }
        }
        {
            const int r = t >> 2, c16 = (t & 3) * 16;
            const float dts = sdt[s0 + r];
            const float* xr = g_xBC + (rowB + s0 + r) * CONVDIM + h * HEADDIM + c16;
            __half2* xh2 = (__half2*)(Xh + r * 72 + c16);
#pragma unroll
            for (int j = 0; j < 16; j += 4) {
                float4 v = *(const float4*)(xr + j);
                xh2[(j >> 1) + 0] = __floats2half2_rn(v.x * dts, v.y * dts);
                xh2[(j >> 1) + 1] = __floats2half2_rn(v.z * dts, v.w * dts);
            }
        }
        __syncthreads();
        if (warp >= st * 2) {
            YF_MMA();
        }
        __syncthreads();
    }

    // ---- part 2: Y_off, 2 n-tiles of 64 ----
    const float el = __expf(acs_l);
    const float* Crow = g_xBC + (rowB + t) * CONVDIM + DINNER + DSTATE;
    const float* S0p = g_Sinit + ((size_t)bc * NHEADS + h) * (HEADDIM * DSTATE);
    for (int nt = 0; nt < 2; nt++) {
        const int n0 = nt * 64;
        __half2* wh2 = (__half2*)(Wh + t * 72);
        __half2* wl2 = (__half2*)(Wl + t * 72);
#pragma unroll
        for (int j = 0; j < 64; j += 4) {
            float4 c4 = *(const float4*)(Crow + n0 + j);
            __half2 h01, l01, h23, l23;
            split2h(c4.x * el, c4.y * el, h01, l01);
            split2h(c4.z * el, c4.w * el, h23, l23);
            wh2[(j >> 1) + 0] = h01; wh2[(j >> 1) + 1] = h23;
            wl2[(j >> 1) + 0] = l01; wl2[(j >> 1) + 1] = l23;
        }
        {
            const int p = t >> 2, nb = (t & 3) * 16;
            const float* sp = S0p + (size_t)p * DSTATE + n0 + nb;
#pragma unroll
            for (int j = 0; j < 16; j++)
                Xh[(nb + j) * 72 + p] = __float2half(sp[j]);
        }
        __syncthreads();
        YF_MMA();
        __syncthreads();
    }
#undef YF_MMA

    const int c0 = (lane & 3) * 2;
#pragma unroll
    for (int mi = 0; mi < 2; mi++) {
        const size_t gr0 = (rowB + warp * 32 + (lane >> 2) + mi * 16) * DINNER + h * HEADDIM;
#pragma unroll
        for (int ni = 0; ni < 8; ni++) {
            int col = c0 + ni * 8;
            *(float2*)&g_Y[gr0 + col] = make_float2(d[mi][ni][0], d[mi][ni][1]);
            *(float2*)&g_Y[gr0 + 8 * DINNER + col] = make_float2(d[mi][ni][2], d[mi][ni][3]);
        }
    }
}

// ---------------- state S = x^T . (w.B)  (fp16: x single, w.B split) --------
#define ST_A     0
#define ST_BH    9216                // 64*72*2
#define ST_BL    26624               // + 64*136*2
#define ST_SMEM  44032

__global__ __launch_bounds__(256, 2) void state_mma_kernel()
{
    extern __shared__ char ssm[];
    __half* Ax = (__half*)(ssm + ST_A);
    __half* Bh = (__half*)(ssm + ST_BH);
    __half* Bl = (__half*)(ssm + ST_BL);

    const int bc = blockIdx.x, h = blockIdx.y;
    const int b = bc >> 4, c = bc & 15;
    const int t = threadIdx.x;
    const size_t rowB = (size_t)b * SEQLEN + c * CHUNK;
    const float asum = g_asum[bc * NHEADS + h];
    const float* acsp = g_acs + ((size_t)bc * NHEADS + h) * CHUNK;

    const int lane = t & 31, warp = t >> 5;
    const int wm = warp >> 2, wn = warp & 3;
    const int grp = lane >> 3, rr = lane & 7;
    const uint32_t axB = s2u(Ax), bhB = s2u(Bh), blB = s2u(Bl);

    uint32_t aOff[2], bOff[2];
#pragma unroll
    for (int mi = 0; mi < 2; mi++)
        aOff[mi] = ((wm * 32 + mi * 16 + (grp & 1) * 8 + rr) * 72
                    + (grp >> 1) * 8) * 2;
#pragma unroll
    for (int pi = 0; pi < 2; pi++)
        bOff[pi] = (((grp & 1) * 8 + rr) * 136
                    + wn * 32 + pi * 16 + (grp >> 1) * 8) * 2;

    float d[2][4][4];
#pragma unroll
    for (int mi = 0; mi < 2; mi++)
#pragma unroll
        for (int ni = 0; ni < 4; ni++)
#pragma unroll
            for (int k = 0; k < 4; k++) d[mi][ni][k] = 0.f;

    for (int st4 = 0; st4 < 4; st4++) {
        const int s0 = st4 * 64;
        const int r = t >> 2;
        const float w = g_dt[(rowB + s0 + r) * NHEADS + h] *
                        __expf(asum - acsp[s0 + r]);
        {
            const int q = (t & 3) * 16;
            const float* xr = g_xBC + (rowB + s0 + r) * CONVDIM + h * HEADDIM + q;
#pragma unroll
            for (int j = 0; j < 16; j += 4) {
                float4 v = *(const float4*)(xr + j);
                Ax[(q + j + 0) * 72 + r] = __float2half(v.x);
                Ax[(q + j + 1) * 72 + r] = __float2half(v.y);
                Ax[(q + j + 2) * 72 + r] = __float2half(v.z);
                Ax[(q + j + 3) * 72 + r] = __float2half(v.w);
            }
        }
        {
            const int nq = (t & 3) * 32;
            const float* brp = g_xBC + (rowB + s0 + r) * CONVDIM + DINNER + nq;
            __half2* bh2 = (__half2*)(Bh + r * 136 + nq);
            __half2* bl2 = (__half2*)(Bl + r * 136 + nq);
#pragma unroll
            for (int j = 0; j < 32; j += 4) {
                float4 v = *(const float4*)(brp + j);
                __half2 h01, l01, h23, l23;
                split2h(v.x * w, v.y * w, h01, l01);
                split2h(v.z * w, v.w * w, h23, l23);
                bh2[(j >> 1) + 0] = h01; bh2[(j >> 1) + 1] = h23;
                bl2[(j >> 1) + 0] = l01; bl2[(j >> 1) + 1] = l23;
            }
        }
        __syncthreads();
#pragma unroll
        for (int k = 0; k < 4; k++) {
            const uint32_t ka = k * 32;
            const uint32_t kb = (uint32_t)k * 16 * 136 * 2;
            uint32_t a_f[2][4], bhf[4][2], blf[4][2];
#pragma unroll
            for (int mi = 0; mi < 2; mi++)
                ldsm4(a_f[mi][0], a_f[mi][1], a_f[mi][2], a_f[mi][3],
                      axB + aOff[mi] + ka);
#pragma unroll
            for (int pi = 0; pi < 2; pi++) {
                ldsm4t(bhf[2*pi][0], bhf[2*pi][1], bhf[2*pi+1][0], bhf[2*pi+1][1],
                       bhB + bOff[pi] + kb);
                ldsm4t(blf[2*pi][0], blf[2*pi][1], blf[2*pi+1][0], blf[2*pi+1][1],
                       blB + bOff[pi] + kb);
            }
#pragma unroll
            for (int mi = 0; mi < 2; mi++)
#pragma unroll
                for (int ni = 0; ni < 4; ni++) {
                    mma16816h(d[mi][ni], a_f[mi], bhf[ni]);
                    mma16816h(d[mi][ni], a_f[mi], blf[ni]);
                }
        }
        __syncthreads();
    }

    float* Sout = g_S + ((size_t)bc * NHEADS + h) * (HEADDIM * DSTATE);
    const int p0 = wm * 32 + (lane >> 2);
    const int n0 = wn * 32 + (lane & 3) * 2;
#pragma unroll
    for (int mi = 0; mi < 2; mi++)
#pragma unroll
        for (int ni = 0; ni < 4; ni++) {
            int col = n0 + ni * 8;
            *(float2*)&Sout[(size_t)(p0 + mi * 16) * DSTATE + col] =
                make_float2(d[mi][ni][0], d[mi][ni][1]);
            *(float2*)&Sout[(size_t)(p0 + mi * 16 + 8) * DSTATE + col] =
                make_float2(d[mi][ni][2], d[mi][ni][3]);
        }
}

// ---------------- convert kernels -------------------------------------------
__global__ void tofp16_kernel(const float* __restrict__ x, __half* __restrict__ o, size_t n)
{
    size_t i = (size_t)blockIdx.x * blockDim.x + threadIdx.x;
    if (i >= n) return;
    o[i] = __float2half(x[i]);
}

__global__ void tofp16_pad_kernel(const float* __restrict__ x, __half* __restrict__ o,
                                  int K, int N, int Np)
{
    size_t i = (size_t)blockIdx.x * blockDim.x + threadIdx.x;
    if (i >= (size_t)K * Np) return;
    int r = (int)(i / Np), c = (int)(i % Np);
    o[i] = __float2half((c < N) ? x[(size_t)r * N + c] : 0.f);
}

// ---------------- causal conv1d + SiLU: 4 outputs per thread ----------------
__global__ void conv_silu_kernel(const float* __restrict__ conv_w,
                                 const float* __restrict__ conv_b)
{
    int idx = blockIdx.x * blockDim.x + threadIdx.x;
    if (idx >= (ROWS / 4) * CONVDIM) return;
    int c  = idx % CONVDIM;
    int rg = idx / CONVDIM;
    int row0 = rg * 4;
    int l0 = row0 & (SEQLEN - 1);
    const float* base = g_zxbcdt + (size_t)row0 * DPROJ + DINNER + c;
    const float w0 = conv_w[c * DCONV + 0], w1 = conv_w[c * DCONV + 1];
    const float w2 = conv_w[c * DCONV + 2], w3 = conv_w[c * DCONV + 3];
    const float bias = conv_b[c];
    float v[7];
#pragma unroll
    for (int j = 0; j < 7; j++) {
        int l = l0 - 3 + j;
        v[j] = (l >= 0) ? base[(long)(j - 3) * DPROJ] : 0.f;
    }
#pragma unroll
    for (int i = 0; i < 4; i++) {
        float acc = bias + v[i] * w0 + v[i+1] * w1 + v[i+2] * w2 + v[i+3] * w3;
        g_xBC[(size_t)(row0 + i) * CONVDIM + c] = acc / (1.f + __expf(-acc));
    }
}

// ---------------- fused dt softplus + per-chunk cumsum ----------------------
__global__ void ascan_kernel(const float* __restrict__ A_log,
                             const float* __restrict__ dt_bias)
{
    int bc = blockIdx.x;
    int h  = blockIdx.y;
    int t  = threadIdx.x;
    int b = bc >> 4, c = bc & 15;
    __shared__ float sa[CHUNK];
    int row = b * SEQLEN + c * CHUNK + t;
    float v = g_zxbcdt[(size_t)row * DPROJ + DT_OFF + h] + dt_bias[h];
    float dtv = (v > 20.f) ? v : log1pf(expf(v));
    g_dt[row * NHEADS + h] = dtv;
    float A = -expf(A_log[h]);
    sa[t] = A * dtv;
    __syncthreads();
    for (int off = 1; off < CHUNK; off <<= 1) {
        float vv = (t >= off) ? sa[t - off] : 0.f;
        __syncthreads();
        sa[t] += vv;
        __syncthreads();
    }
    g_acs[(bc * NHEADS + h) * CHUNK + t] = sa[t];
    if (t == CHUNK - 1) g_asum[bc * NHEADS + h] = sa[t];
}

// ---------------- sequential inter-chunk recurrence (4-way split) -----------
__global__ void chunkrec_kernel()
{
    int b = blockIdx.x, h = blockIdx.y, z = blockIdx.z;
    int t = threadIdx.x;
    float cur[8];
#pragma unroll
    for (int k = 0; k < 8; k++) cur[k] = 0.f;
    for (int c = 0; c < NCHUNK; c++) {
        int bc = b * NCHUNK + c;
        size_t base = ((size_t)bc * NHEADS + h) * (HEADDIM * DSTATE) + z * 2048;
        float dd = __expf(g_asum[bc * NHEADS + h]);
#pragma unroll
        for (int k = 0; k < 8; k++) {
            size_t e = base + t + 256 * k;
            g_Sinit[e] = cur[k];
            cur[k] = cur[k] * dd + g_S[e];
        }
    }
}

// ---------------- layernorm + z-gate (shuffle reduction) -> fp16 yg ---------
__global__ __launch_bounds__(256) void normgate_kernel(const float* __restrict__ norm_w)
{
    int row = blockIdx.x;
    int t = threadIdx.x;
    const int lane = t & 31, warp = t >> 5;
    const float* yrow = g_Y + (size_t)row * DINNER;
    const float* zrow = g_zxbcdt + (size_t)row * DPROJ;
    __shared__ float red[8];
    __shared__ float bres[2];
    float v[8];
    float s = 0.f;
#pragma unroll
    for (int i = 0; i < 8; i++) { v[i] = yrow[t + 256*i]; s += v[i]; }
#pragma unroll
    for (int o = 16; o > 0; o >>= 1) s += __shfl_xor_sync(0xffffffffu, s, o);
    if (lane == 0) red[warp] = s;
    __syncthreads();
    if (t == 0) {
        float tot = 0.f;
#pragma unroll
        for (int i = 0; i < 8; i++) tot += red[i];
        bres[0] = tot * (1.f / DINNER);
    }
    __syncthreads();
    const float mu = bres[0];
    float s2 = 0.f;
#pragma unroll
    for (int i = 0; i < 8; i++) { float dv = v[i] - mu; s2 += dv * dv; }
#pragma unroll
    for (int o = 16; o > 0; o >>= 1) s2 += __shfl_xor_sync(0xffffffffu, s2, o);
    if (lane == 0) red[warp] = s2;
    __syncthreads();
    if (t == 0) {
        float tot = 0.f;
#pragma unroll
        for (int i = 0; i < 8; i++) tot += red[i];
        bres[1] = rsqrtf(tot * (1.f / DINNER) + 1e-5f);
    }
    __syncthreads();
    const float inv = bres[1];
    __half* orow = g_yg + (size_t)row * DINNER;
#pragma unroll
    for (int i = 0; i < 8; i++) {
        int idx = t + 256*i;
        float z = zrow[idx];
        float g = z / (1.f + __expf(-z));
        orow[idx] = __float2half((v[i] - mu) * inv * norm_w[idx] * g);
    }
}

// ---------------- launch ---------------------------------------------------
extern "C" void kernel_launch(void* const* d_in, const int* in_sizes, int n_in,
                              void* d_out, int out_size)
{
    const float* u       = (const float*)d_in[0];
    const float* W_in    = (const float*)d_in[1];
    const float* conv_w  = (const float*)d_in[2];
    const float* conv_b  = (const float*)d_in[3];
    const float* dt_bias = (const float*)d_in[4];
    const float* A_log   = (const float*)d_in[5];
    const float* norm_w  = (const float*)d_in[6];
    const float* W_out   = (const float*)d_in[7];
    float* out = (float*)d_out;

    float* p_zx = nullptr;
    __half *p_uf, *p_wif, *p_wof, *p_yg;
    cudaGetSymbolAddress((void**)&p_zx,  g_zxbcdt);
    cudaGetSymbolAddress((void**)&p_uf,  g_uf);
    cudaGetSymbolAddress((void**)&p_wif, g_wif);
    cudaGetSymbolAddress((void**)&p_wof, g_wof);
    cudaGetSymbolAddress((void**)&p_yg,  g_yg);

    cudaFuncSetAttribute(mma_gemm, cudaFuncAttributeMaxDynamicSharedMemorySize, GEMM_SMEM);
    cudaFuncSetAttribute(yfused_kernel, cudaFuncAttributeMaxDynamicSharedMemorySize, YF_SMEM);
    cudaFuncSetAttribute(state_mma_kernel, cudaFuncAttributeMaxDynamicSharedMemorySize, ST_SMEM);
    cudaFuncSetAttribute(cb_mma_kernel, cudaFuncAttributeMaxDynamicSharedMemorySize, CB_SMEM);

    // 0. fp16 conversions
    {
        size_t n = (size_t)ROWS * DMODEL;
        tofp16_kernel<<<(unsigned)((n + 255) / 256), 256>>>(u, p_uf, n);
    }
    tofp16_pad_kernel<<<(unsigned)(((size_t)DMODEL * NPAD1 + 255) / 256), 256>>>(
        W_in, p_wif, DMODEL, DPROJ, NPAD1);
    {
        size_t n = (size_t)DINNER * DMODEL;
        tofp16_kernel<<<(unsigned)((n + 255) / 256), 256>>>(W_out, p_wof, n);
    }

    // 1. zxbcdt = u @ W_in  (8192 x 4384 x 1024), BK=64
    mma_gemm<<<dim3(NPAD1 / 128, ROWS / 128), 256, GEMM_SMEM>>>(
        p_uf, p_wif, p_zx, ROWS, DPROJ, DMODEL, NPAD1, DPROJ);
    // 2. causal conv1d + SiLU (4 l per thread)
    conv_silu_kernel<<<((ROWS / 4) * CONVDIM + 255) / 256, 256>>>(conv_w, conv_b);
    // 3. fused dt softplus + per-chunk cumsum
    ascan_kernel<<<dim3(NBC, NHEADS), CHUNK>>>(A_log, dt_bias);
    // 4. CB gram matrices (tensor cores, bf16 3-term)
    cb_mma_kernel<<<dim3(NBC, 4), 256, CB_SMEM>>>();
    // 5. per-chunk end states (tensor cores, fp16 2-term)
    state_mma_kernel<<<dim3(NBC, NHEADS), 256, ST_SMEM>>>();
    // 6. inter-chunk recurrence (4-way parallel over state elems)
    chunkrec_kernel<<<dim3(BATCH, NHEADS, 4), 256>>>();
    // 7. fused Y_diag + Y_off (tensor cores, factored decay + tri skip)
    yfused_kernel<<<dim3(NBC, NHEADS), 256, YF_SMEM>>>();
    // 8. layernorm + silu(z) gate (shuffle reduce) -> fp16
    normgate_kernel<<<ROWS, 256>>>(norm_w);
    // 9. out = yg @ W_out  (8192 x 1024 x 2048), BK=64
    mma_gemm<<<dim3(DMODEL / 128, ROWS / 128), 256, GEMM_SMEM>>>(
        p_yg, p_wof, out, ROWS, DMODEL, DINNER, DMODEL, DMODEL);
}

// round 16
// speedup vs baseline: 2.0226x; 1.0222x over previous
#include <cuda_runtime.h>
#include <cuda_bf16.h>
#include <cuda_fp16.h>
#include <math.h>
#include <stdint.h>

#define BATCH   2
#define SEQLEN  4096
#define DMODEL  1024
#define DINNER  2048
#define HEADDIM 64
#define NHEADS  32
#define DSTATE  128
#define DCONV   4
#define CHUNK   256
#define NCHUNK  (SEQLEN / CHUNK)   // 16
#define NBC     (BATCH * NCHUNK)   // 32
#define DPROJ   4384               // 2*DINNER + 2*DSTATE + NHEADS
#define CONVDIM 2304               // DINNER + 2*DSTATE
#define DT_OFF  4352               // 2*DINNER + 2*DSTATE
#define ROWS    (BATCH * SEQLEN)   // 8192
#define NPAD1   4480               // DPROJ padded to multiple of 128

// ---------------- scratch (device globals; no allocation allowed) ----------
__device__ float g_zxbcdt[(size_t)ROWS * DPROJ];
__device__ float g_xBC[(size_t)ROWS * CONVDIM];
__device__ float g_dt[ROWS * NHEADS];
__device__ float g_acs[NBC * NHEADS * CHUNK];
__device__ float g_asum[NBC * NHEADS];
__device__ __half g_CB[(size_t)NBC * CHUNK * CHUNK];       // fp16 now
__device__ float g_Y[(size_t)ROWS * DINNER];
__device__ float g_S[(size_t)NBC * NHEADS * HEADDIM * DSTATE];
__device__ __half g_Sinit[(size_t)NBC * NHEADS * HEADDIM * DSTATE];  // fp16 now

// fp16 GEMM operands
__device__ __half g_uf[(size_t)ROWS * DMODEL];
__device__ __half g_wif[(size_t)DMODEL * NPAD1];
__device__ __half g_wof[(size_t)DINNER * DMODEL];
__device__ __half g_yg[(size_t)ROWS * DINNER];

// ---------------- helpers ---------------------------------------------------
__device__ __forceinline__ uint32_t s2u(const void* p) {
    return (uint32_t)__cvta_generic_to_shared(p);
}
#define CP16(dst, src) \
    asm volatile("cp.async.cg.shared.global [%0], [%1], 16;\n" :: "r"(dst), "l"(src))
#define CP_COMMIT() asm volatile("cp.async.commit_group;\n")
#define CP_WAIT1()  asm volatile("cp.async.wait_group 1;\n")

__device__ __forceinline__ void ldsm4(uint32_t& r0, uint32_t& r1, uint32_t& r2,
                                      uint32_t& r3, uint32_t addr) {
    asm volatile("ldmatrix.sync.aligned.m8n8.x4.shared.b16 {%0,%1,%2,%3}, [%4];"
                 : "=r"(r0), "=r"(r1), "=r"(r2), "=r"(r3) : "r"(addr));
}
__device__ __forceinline__ void ldsm4t(uint32_t& r0, uint32_t& r1, uint32_t& r2,
                                       uint32_t& r3, uint32_t addr) {
    asm volatile("ldmatrix.sync.aligned.m8n8.x4.trans.shared.b16 {%0,%1,%2,%3}, [%4];"
                 : "=r"(r0), "=r"(r1), "=r"(r2), "=r"(r3) : "r"(addr));
}
// fp16 mma
__device__ __forceinline__ void mma16816h(float* d, const uint32_t* a, const uint32_t* b) {
    asm volatile(
        "mma.sync.aligned.m16n8k16.row.col.f32.f16.f16.f32 "
        "{%0,%1,%2,%3}, {%4,%5,%6,%7}, {%8,%9}, {%0,%1,%2,%3};"
        : "+f"(d[0]), "+f"(d[1]), "+f"(d[2]), "+f"(d[3])
        : "r"(a[0]), "r"(a[1]), "r"(a[2]), "r"(a[3]), "r"(b[0]), "r"(b[1]));
}
// bf16 mma (cb)
__device__ __forceinline__ void mma16816(float* d, const uint32_t* a, const uint32_t* b) {
    asm volatile(
        "mma.sync.aligned.m16n8k16.row.col.f32.bf16.bf16.f32 "
        "{%0,%1,%2,%3}, {%4,%5,%6,%7}, {%8,%9}, {%0,%1,%2,%3};"
        : "+f"(d[0]), "+f"(d[1]), "+f"(d[2]), "+f"(d[3])
        : "r"(a[0]), "r"(a[1]), "r"(a[2]), "r"(a[3]), "r"(b[0]), "r"(b[1]));
}
__device__ __forceinline__ void split2(float a, float b,
                                       __nv_bfloat162& h, __nv_bfloat162& l) {
    __nv_bfloat16 ha = __float2bfloat16(a), hb = __float2bfloat16(b);
    h = __halves2bfloat162(ha, hb);
    l = __halves2bfloat162(__float2bfloat16(a - __bfloat162float(ha)),
                           __float2bfloat16(b - __bfloat162float(hb)));
}
__device__ __forceinline__ void split2h(float a, float b, __half2& h, __half2& l) {
    __half ha = __float2half(a), hb = __float2half(b);
    h = __halves2half2(ha, hb);
    l = __halves2half2(__float2half(a - __half2float(ha)),
                       __float2half(b - __half2float(hb)));
}

// ---------------- GEMM smem layout (bytes), tile 128x128, BK=64 -------------
#define A_B        18432         // 128*72*2
#define B_B        17408         // 64*136*2
#define OFF_B      A_B
#define STAGE_B    (A_B + B_B)                     // 35840
#define NSTAGE     3
#define GEMM_SMEM  (NSTAGE * STAGE_B)              // 107520

// ---------------- fp16 tensor-core GEMM, BK=64, 2 CTAs/SM -------------------
__global__ __launch_bounds__(256, 2) void mma_gemm(
    const __half* __restrict__ A, const __half* __restrict__ B,
    float* __restrict__ C, int M, int N, int K, int ldb, int ldc)
{
    extern __shared__ __half smem[];
    const uint32_t sbase = s2u(smem);
    const int rowBase = blockIdx.y * 128;
    const int colBase = blockIdx.x * 128;
    const int t = threadIdx.x;

    const int ar = t >> 3, aq = t & 7;
    const __half* aS = A + (size_t)(rowBase + ar) * K + aq * 8;
    const uint32_t aD = sbase + (ar * 72 + aq * 8) * 2;
    const int br = t >> 4, bq = t & 15;
    const __half* bS = B + (size_t)br * ldb + colBase + bq * 8;
    const uint32_t bD = sbase + OFF_B + (br * 136 + bq * 8) * 2;

    const int lane = t & 31, warp = t >> 5;
    const int wm = warp >> 2, wn = warp & 3;
    const int grp = lane >> 3, rr = lane & 7;

    uint32_t aAddr[4], bAddr[2];
#pragma unroll
    for (int mi = 0; mi < 4; mi++)
        aAddr[mi] = sbase + ((wm * 64 + mi * 16 + (grp & 1) * 8 + rr) * 72
                             + (grp >> 1) * 8) * 2;
#pragma unroll
    for (int pi = 0; pi < 2; pi++)
        bAddr[pi] = sbase + OFF_B + (((grp & 1) * 8 + rr) * 136
                             + wn * 32 + pi * 16 + (grp >> 1) * 8) * 2;

    float d[4][4][4];
#pragma unroll
    for (int mi = 0; mi < 4; mi++)
#pragma unroll
        for (int ni = 0; ni < 4; ni++)
#pragma unroll
            for (int k = 0; k < 4; k++) d[mi][ni][k] = 0.f;

    const int nk = K / 64;

#define LOAD_SLAB(st, kt) do {                                                  \
    const uint32_t _d = (st) * STAGE_B;                                         \
    const int _k = (kt) * 64;                                                   \
    _Pragma("unroll")                                                           \
    for (int i = 0; i < 4; i++)                                                 \
        CP16(aD + _d + (uint32_t)i * 32 * 72 * 2,                               \
             aS + (size_t)(i * 32) * K + _k);                                   \
    _Pragma("unroll")                                                           \
    for (int i = 0; i < 4; i++)                                                 \
        CP16(bD + _d + (uint32_t)i * 16 * 136 * 2,                              \
             bS + (size_t)(_k + i * 16) * ldb);                                 \
} while (0)

#define FRAGS_MMA(sd, ks) do {                                                  \
    const uint32_t _ka = (ks) * 32;                                             \
    const uint32_t _kb = (uint32_t)(ks) * 16 * 136 * 2;                         \
    uint32_t a_f[4][4], b_f[4][2];                                              \
    _Pragma("unroll")                                                           \
    for (int mi = 0; mi < 4; mi++)                                              \
        ldsm4(a_f[mi][0], a_f[mi][1], a_f[mi][2], a_f[mi][3],                   \
              aAddr[mi] + (sd) + _ka);                                          \
    _Pragma("unroll")                                                           \
    for (int pi = 0; pi < 2; pi++)                                              \
        ldsm4t(b_f[2*pi][0], b_f[2*pi][1], b_f[2*pi+1][0], b_f[2*pi+1][1],      \
               bAddr[pi] + (sd) + _kb);                                         \
    _Pragma("unroll")                                                           \
    for (int mi = 0; mi < 4; mi++)                                              \
        _Pragma("unroll")                                                       \
        for (int ni = 0; ni < 4; ni++)                                          \
            mma16816h(d[mi][ni], a_f[mi], b_f[ni]);                             \
} while (0)

    LOAD_SLAB(0, 0); CP_COMMIT();
    LOAD_SLAB(1, 1); CP_COMMIT();
    CP_WAIT1();
    __syncthreads();

    for (int kt = 0; kt < nk; kt++) {
        const uint32_t sd = (uint32_t)(kt % 3) * STAGE_B;
        if (kt + 2 < nk) LOAD_SLAB((kt + 2) % 3, kt + 2);
        CP_COMMIT();
        FRAGS_MMA(sd, 0);
        FRAGS_MMA(sd, 1);
        FRAGS_MMA(sd, 2);
        FRAGS_MMA(sd, 3);
        if (kt + 1 < nk) {
            CP_WAIT1();
            __syncthreads();
        }
    }

    const int r0 = rowBase + wm * 64 + (lane >> 2);
    const int c0 = colBase + wn * 32 + (lane & 3) * 2;
#pragma unroll
    for (int mi = 0; mi < 4; mi++)
#pragma unroll
        for (int ni = 0; ni < 4; ni++) {
            int col = c0 + ni * 8;
            if (col < N) {
                float2 v0 = make_float2(d[mi][ni][0], d[mi][ni][1]);
                float2 v1 = make_float2(d[mi][ni][2], d[mi][ni][3]);
                *(float2*)&C[(size_t)(r0 + mi * 16) * ldc + col] = v0;
                *(float2*)&C[(size_t)(r0 + mi * 16 + 8) * ldc + col] = v1;
            }
        }
#undef LOAD_SLAB
#undef FRAGS_MMA
}

// ---------------- CB gram via mma (bf16 3-term, fp16 output) ----------------
#define CB_AH    0
#define CB_AL    17408               // 64*136*2
#define CB_BH    34816
#define CB_BL    52224
#define CB_SMEM  69632

__global__ __launch_bounds__(256, 2) void cb_mma_kernel()
{
    extern __shared__ char csm[];
    __nv_bfloat16* Ah = (__nv_bfloat16*)(csm + CB_AH);
    __nv_bfloat16* Al = (__nv_bfloat16*)(csm + CB_AL);
    __nv_bfloat16* Bh = (__nv_bfloat16*)(csm + CB_BH);
    __nv_bfloat16* Bl = (__nv_bfloat16*)(csm + CB_BL);

    const int bc = blockIdx.x, lt = blockIdx.y;
    const int b = bc >> 4, c = bc & 15;
    const int t = threadIdx.x;
    const size_t rowB = (size_t)b * SEQLEN + c * CHUNK;

    const int lane = t & 31, warp = t >> 5;
    const int wm = warp >> 2, wn = warp & 3;
    const int grp = lane >> 3, rr = lane & 7;
    const uint32_t ahB = s2u(Ah), alB = s2u(Al), bhB = s2u(Bh), blB = s2u(Bl);

    {
        const int r = t >> 2, q = (t & 3) * 32;
        const float* cr = g_xBC + (rowB + lt * 64 + r) * CONVDIM
                          + (DINNER + DSTATE) + q;
        __nv_bfloat162* ah2 = (__nv_bfloat162*)(Ah + r * 136 + q);
        __nv_bfloat162* al2 = (__nv_bfloat162*)(Al + r * 136 + q);
#pragma unroll
        for (int j = 0; j < 32; j += 4) {
            float4 v = *(const float4*)(cr + j);
            __nv_bfloat162 h01, l01, h23, l23;
            split2(v.x, v.y, h01, l01);
            split2(v.z, v.w, h23, l23);
            ah2[(j >> 1) + 0] = h01; ah2[(j >> 1) + 1] = h23;
            al2[(j >> 1) + 0] = l01; al2[(j >> 1) + 1] = l23;
        }
    }

    uint32_t aOff[2];
#pragma unroll
    for (int mi = 0; mi < 2; mi++)
        aOff[mi] = ((wm * 32 + mi * 16 + (grp & 1) * 8 + rr) * 136
                    + (grp >> 1) * 8) * 2;
    const uint32_t bOff = ((wn * 16 + (grp & 1) * 8 + rr) * 136
                           + (grp >> 1) * 8) * 2;

    float d[2][8][4];
#pragma unroll
    for (int mi = 0; mi < 2; mi++)
#pragma unroll
        for (int ni = 0; ni < 8; ni++)
#pragma unroll
            for (int k = 0; k < 4; k++) d[mi][ni][k] = 0.f;

    for (int stile = 0; stile < 4; stile++) {
        {
            const int r = t >> 2, q = (t & 3) * 32;
            const float* br = g_xBC + (rowB + stile * 64 + r) * CONVDIM
                              + DINNER + q;
            __nv_bfloat162* bh2 = (__nv_bfloat162*)(Bh + r * 136 + q);
            __nv_bfloat162* bl2 = (__nv_bfloat162*)(Bl + r * 136 + q);
#pragma unroll
            for (int j = 0; j < 32; j += 4) {
                float4 v = *(const float4*)(br + j);
                __nv_bfloat162 h01, l01, h23, l23;
                split2(v.x, v.y, h01, l01);
                split2(v.z, v.w, h23, l23);
                bh2[(j >> 1) + 0] = h01; bh2[(j >> 1) + 1] = h23;
                bl2[(j >> 1) + 0] = l01; bl2[(j >> 1) + 1] = l23;
            }
        }
        __syncthreads();
#pragma unroll
        for (int k = 0; k < 8; k++) {
            const uint32_t ko = k * 32;
            uint32_t a_h[2][4], a_l[2][4], b4h[4], b4l[4];
#pragma unroll
            for (int mi = 0; mi < 2; mi++) {
                ldsm4(a_h[mi][0], a_h[mi][1], a_h[mi][2], a_h[mi][3],
                      ahB + aOff[mi] + ko);
                ldsm4(a_l[mi][0], a_l[mi][1], a_l[mi][2], a_l[mi][3],
                      alB + aOff[mi] + ko);
            }
            ldsm4(b4h[0], b4h[1], b4h[2], b4h[3], bhB + bOff + ko);
            ldsm4(b4l[0], b4l[1], b4l[2], b4l[3], blB + bOff + ko);
            uint32_t bh0[2] = {b4h[0], b4h[2]};
            uint32_t bh1[2] = {b4h[1], b4h[3]};
            uint32_t bl0[2] = {b4l[0], b4l[2]};
            uint32_t bl1[2] = {b4l[1], b4l[3]};
#pragma unroll
            for (int mi = 0; mi < 2; mi++) {
                mma16816(d[mi][stile * 2 + 0], a_h[mi], bh0);
                mma16816(d[mi][stile * 2 + 0], a_h[mi], bl0);
                mma16816(d[mi][stile * 2 + 0], a_l[mi], bh0);
                mma16816(d[mi][stile * 2 + 1], a_h[mi], bh1);
                mma16816(d[mi][stile * 2 + 1], a_h[mi], bl1);
                mma16816(d[mi][stile * 2 + 1], a_l[mi], bh1);
            }
        }
        __syncthreads();
    }

    const int r0 = lt * 64 + wm * 32 + (lane >> 2);
    const int c0 = (lane & 3) * 2;
#pragma unroll
    for (int mi = 0; mi < 2; mi++) {
        __half* out0 = g_CB + ((size_t)bc * CHUNK + r0 + mi * 16) * CHUNK;
        __half* out1 = out0 + 8 * CHUNK;
#pragma unroll
        for (int st = 0; st < 4; st++)
#pragma unroll
            for (int q = 0; q < 2; q++) {
                int col = st * 64 + wn * 16 + q * 8 + c0;
                float* dd = d[mi][st * 2 + q];
                *(__half2*)&out0[col] = __floats2half2_rn(dd[0], dd[1]);
                *(__half2*)&out1[col] = __floats2half2_rn(dd[2], dd[3]);
            }
    }
}

// ---------------- fused Y (fp16, factored decay + triangular skip) ----------
#define YF_WH    0
#define YF_WL    36864               // 256*72*2
#define YF_XH    73728               // 64*72*2 = 9216
#define YF_ACS   82944
#define YF_DT    83968
#define YF_SCOL  84992
#define YF_SMEM  86016

__global__ __launch_bounds__(256, 2) void yfused_kernel()
{
    extern __shared__ char ysm[];
    __half* Wh = (__half*)(ysm + YF_WH);
    __half* Wl = (__half*)(ysm + YF_WL);
    __half* Xh = (__half*)(ysm + YF_XH);
    float* sacs = (float*)(ysm + YF_ACS);
    float* sdt  = (float*)(ysm + YF_DT);
    float* scol = (float*)(ysm + YF_SCOL);

    const int bc = blockIdx.x, h = blockIdx.y;
    const int b = bc >> 4, c = bc & 15;
    const int t = threadIdx.x;
    const size_t rowB = (size_t)b * SEQLEN + c * CHUNK;

    sacs[t] = g_acs[((size_t)bc * NHEADS + h) * CHUNK + t];
    sdt[t]  = g_dt[(rowB + t) * NHEADS + h];
    __syncthreads();
    const float acs_l = sacs[t];
    scol[t] = __expf(sacs[t | 63] - acs_l);
    __syncthreads();

    const int lane = t & 31, warp = t >> 5;
    const int grp = lane >> 3, rr = lane & 7;
    const uint32_t whB = s2u(Wh), wlB = s2u(Wl), xhB = s2u(Xh);

    uint32_t aOff[2], bOff[4];
#pragma unroll
    for (int mi = 0; mi < 2; mi++)
        aOff[mi] = ((warp * 32 + mi * 16 + (grp & 1) * 8 + rr) * 72
                    + (grp >> 1) * 8) * 2;
#pragma unroll
    for (int pi = 0; pi < 4; pi++)
        bOff[pi] = (((grp & 1) * 8 + rr) * 72 + pi * 16 + (grp >> 1) * 8) * 2;

    float d[2][8][4];
#pragma unroll
    for (int mi = 0; mi < 2; mi++)
#pragma unroll
        for (int ni = 0; ni < 8; ni++)
#pragma unroll
            for (int k = 0; k < 4; k++) d[mi][ni][k] = 0.f;

#define YF_MMA() do {                                                           \
    _Pragma("unroll")                                                           \
    for (int k = 0; k < 4; k++) {                                               \
        const uint32_t ka = k * 32;                                             \
        const uint32_t kb = k * 16 * 144;                                       \
        uint32_t a_h[2][4], a_l[2][4];                                          \
        _Pragma("unroll")                                                       \
        for (int mi = 0; mi < 2; mi++) {                                        \
            ldsm4(a_h[mi][0], a_h[mi][1], a_h[mi][2], a_h[mi][3],               \
                  whB + aOff[mi] + ka);                                         \
            ldsm4(a_l[mi][0], a_l[mi][1], a_l[mi][2], a_l[mi][3],               \
                  wlB + aOff[mi] + ka);                                         \
        }                                                                       \
        _Pragma("unroll")                                                       \
        for (int pi = 0; pi < 4; pi++) {                                        \
            uint32_t bh[2][2];                                                  \
            ldsm4t(bh[0][0], bh[0][1], bh[1][0], bh[1][1],                      \
                   xhB + bOff[pi] + kb);                                        \
            _Pragma("unroll")                                                   \
            for (int mi = 0; mi < 2; mi++)                                      \
                _Pragma("unroll")                                               \
                for (int q = 0; q < 2; q++) {                                   \
                    mma16816h(d[mi][2*pi+q], a_h[mi], bh[q]);                   \
                    mma16816h(d[mi][2*pi+q], a_l[mi], bh[q]);                   \
                }                                                               \
        }                                                                       \
    }                                                                           \
} while (0)

    // ---- part 1: Y_diag, 4 s-tiles of 64, triangular ----
    const __half* CBrow = g_CB + ((size_t)bc * CHUNK + t) * CHUNK;
    for (int st = 0; st < 4; st++) {
        const int s0 = st * 64;
        if (t >= s0) {
            __half2* wh2 = (__half2*)(Wh + t * 72);
            __half2* wl2 = (__half2*)(Wl + t * 72);
            if (t < s0 + 64) {
#pragma unroll
                for (int j = 0; j < 64; j += 4) {
                    __half2 p0 = *(const __half2*)(CBrow + s0 + j);
                    __half2 p1 = *(const __half2*)(CBrow + s0 + j + 2);
                    float2 f0 = __half22float2(p0), f1 = __half22float2(p1);
                    float cbp[4] = {f0.x, f0.y, f1.x, f1.y};
                    float w[4];
#pragma unroll
                    for (int e = 0; e < 4; e++) {
                        int s = s0 + j + e;
                        float arg = fminf(acs_l - sacs[s], 0.f);
                        w[e] = (s <= t) ? cbp[e] * __expf(arg) : 0.f;
                    }
                    __half2 h01, l01, h23, l23;
                    split2h(w[0], w[1], h01, l01);
                    split2h(w[2], w[3], h23, l23);
                    wh2[(j >> 1) + 0] = h01; wh2[(j >> 1) + 1] = h23;
                    wl2[(j >> 1) + 0] = l01; wl2[(j >> 1) + 1] = l23;
                }
            } else {
                const float rowf = __expf(sacs[s0 + 63] >= acs_l ?
                                          acs_l - sacs[s0 + 63] : 0.f);
#pragma unroll
                for (int j = 0; j < 64; j += 4) {
                    __half2 p0 = *(const __half2*)(CBrow + s0 + j);
                    __half2 p1 = *(const __half2*)(CBrow + s0 + j + 2);
                    float2 f0 = __half22float2(p0), f1 = __half22float2(p1);
                    float cbp[4] = {f0.x, f0.y, f1.x, f1.y};
                    float w[4];
#pragma unroll
                    for (int e = 0; e < 4; e++)
                        w[e] = cbp[e] * rowf * scol[s0 + j + e];
                    __half2 h01, l01, h23, l23;
                    split2h(w[0], w[1], h01, l01);
                    split2h(w[2], w[3], h23, l23);
                    wh2[(j >> 1) + 0] = h01; wh2[(j >> 1) + 1] = h23;
                    wl2[(j >> 1) + 0] = l01; wl2[(j >> 1) + 1] = l23;
                }
            }
        }
        {
            const int r = t >> 2, c16 = (t & 3) * 16;
            const float dts = sdt[s0 + r];
            const float* xr = g_xBC + (rowB + s0 + r) * CONVDIM + h * HEADDIM + c16;
            __half2* xh2 = (__half2*)(Xh + r * 72 + c16);
#pragma unroll
            for (int j = 0; j < 16; j += 4) {
                float4 v = *(const float4*)(xr + j);
                xh2[(j >> 1) + 0] = __floats2half2_rn(v.x * dts, v.y * dts);
                xh2[(j >> 1) + 1] = __floats2half2_rn(v.z * dts, v.w * dts);
            }
        }
        __syncthreads();
        if (warp >= st * 2) {
            YF_MMA();
        }
        __syncthreads();
    }

    // ---- part 2: Y_off, 2 n-tiles of 64 ----
    const float el = __expf(acs_l);
    const float* Crow = g_xBC + (rowB + t) * CONVDIM + DINNER + DSTATE;
    const __half* S0p = g_Sinit + ((size_t)bc * NHEADS + h) * (HEADDIM * DSTATE);
    for (int nt = 0; nt < 2; nt++) {
        const int n0 = nt * 64;
        __half2* wh2 = (__half2*)(Wh + t * 72);
        __half2* wl2 = (__half2*)(Wl + t * 72);
#pragma unroll
        for (int j = 0; j < 64; j += 4) {
            float4 c4 = *(const float4*)(Crow + n0 + j);
            __half2 h01, l01, h23, l23;
            split2h(c4.x * el, c4.y * el, h01, l01);
            split2h(c4.z * el, c4.w * el, h23, l23);
            wh2[(j >> 1) + 0] = h01; wh2[(j >> 1) + 1] = h23;
            wl2[(j >> 1) + 0] = l01; wl2[(j >> 1) + 1] = l23;
        }
        {
            const int p = t >> 2, nb = (t & 3) * 16;
            const __half* sp = S0p + (size_t)p * DSTATE + n0 + nb;
#pragma unroll
            for (int j = 0; j < 16; j++)
                Xh[(nb + j) * 72 + p] = sp[j];
        }
        __syncthreads();
        YF_MMA();
        __syncthreads();
    }
#undef YF_MMA

    const int c0 = (lane & 3) * 2;
#pragma unroll
    for (int mi = 0; mi < 2; mi++) {
        const size_t gr0 = (rowB + warp * 32 + (lane >> 2) + mi * 16) * DINNER + h * HEADDIM;
#pragma unroll
        for (int ni = 0; ni < 8; ni++) {
            int col = c0 + ni * 8;
            *(float2*)&g_Y[gr0 + col] = make_float2(d[mi][ni][0], d[mi][ni][1]);
            *(float2*)&g_Y[gr0 + 8 * DINNER + col] = make_float2(d[mi][ni][2], d[mi][ni][3]);
        }
    }
}

// ---------------- state S = x^T . (w.B)  (fp16: x single, w.B split) --------
#define ST_A     0
#define ST_BH    9216                // 64*72*2
#define ST_BL    26624               // + 64*136*2
#define ST_SMEM  44032

__global__ __launch_bounds__(256, 2) void state_mma_kernel()
{
    extern __shared__ char ssm[];
    __half* Ax = (__half*)(ssm + ST_A);
    __half* Bh = (__half*)(ssm + ST_BH);
    __half* Bl = (__half*)(ssm + ST_BL);

    const int bc = blockIdx.x, h = blockIdx.y;
    const int b = bc >> 4, c = bc & 15;
    const int t = threadIdx.x;
    const size_t rowB = (size_t)b * SEQLEN + c * CHUNK;
    const float asum = g_asum[bc * NHEADS + h];
    const float* acsp = g_acs + ((size_t)bc * NHEADS + h) * CHUNK;

    const int lane = t & 31, warp = t >> 5;
    const int wm = warp >> 2, wn = warp & 3;
    const int grp = lane >> 3, rr = lane & 7;
    const uint32_t axB = s2u(Ax), bhB = s2u(Bh), blB = s2u(Bl);

    uint32_t aOff[2], bOff[2];
#pragma unroll
    for (int mi = 0; mi < 2; mi++)
        aOff[mi] = ((wm * 32 + mi * 16 + (grp & 1) * 8 + rr) * 72
                    + (grp >> 1) * 8) * 2;
#pragma unroll
    for (int pi = 0; pi < 2; pi++)
        bOff[pi] = (((grp & 1) * 8 + rr) * 136
                    + wn * 32 + pi * 16 + (grp >> 1) * 8) * 2;

    float d[2][4][4];
#pragma unroll
    for (int mi = 0; mi < 2; mi++)
#pragma unroll
        for (int ni = 0; ni < 4; ni++)
#pragma unroll
            for (int k = 0; k < 4; k++) d[mi][ni][k] = 0.f;

    for (int st4 = 0; st4 < 4; st4++) {
        const int s0 = st4 * 64;
        const int r = t >> 2;
        const float w = g_dt[(rowB + s0 + r) * NHEADS + h] *
                        __expf(asum - acsp[s0 + r]);
        {
            const int q = (t & 3) * 16;
            const float* xr = g_xBC + (rowB + s0 + r) * CONVDIM + h * HEADDIM + q;
#pragma unroll
            for (int j = 0; j < 16; j += 4) {
                float4 v = *(const float4*)(xr + j);
                Ax[(q + j + 0) * 72 + r] = __float2half(v.x);
                Ax[(q + j + 1) * 72 + r] = __float2half(v.y);
                Ax[(q + j + 2) * 72 + r] = __float2half(v.z);
                Ax[(q + j + 3) * 72 + r] = __float2half(v.w);
            }
        }
        {
            const int nq = (t & 3) * 32;
            const float* brp = g_xBC + (rowB + s0 + r) * CONVDIM + DINNER + nq;
            __half2* bh2 = (__half2*)(Bh + r * 136 + nq);
            __half2* bl2 = (__half2*)(Bl + r * 136 + nq);
#pragma unroll
            for (int j = 0; j < 32; j += 4) {
                float4 v = *(const float4*)(brp + j);
                __half2 h01, l01, h23, l23;
                split2h(v.x * w, v.y * w, h01, l01);
                split2h(v.z * w, v.w * w, h23, l23);
                bh2[(j >> 1) + 0] = h01; bh2[(j >> 1) + 1] = h23;
                bl2[(j >> 1) + 0] = l01; bl2[(j >> 1) + 1] = l23;
            }
        }
        __syncthreads();
#pragma unroll
        for (int k = 0; k < 4; k++) {
            const uint32_t ka = k * 32;
            const uint32_t kb = (uint32_t)k * 16 * 136 * 2;
            uint32_t a_f[2][4], bhf[4][2], blf[4][2];
#pragma unroll
            for (int mi = 0; mi < 2; mi++)
                ldsm4(a_f[mi][0], a_f[mi][1], a_f[mi][2], a_f[mi][3],
                      axB + aOff[mi] + ka);
#pragma unroll
            for (int pi = 0; pi < 2; pi++) {
                ldsm4t(bhf[2*pi][0], bhf[2*pi][1], bhf[2*pi+1][0], bhf[2*pi+1][1],
                       bhB + bOff[pi] + kb);
                ldsm4t(blf[2*pi][0], blf[2*pi][1], blf[2*pi+1][0], blf[2*pi+1][1],
                       blB + bOff[pi] + kb);
            }
#pragma unroll
            for (int mi = 0; mi < 2; mi++)
#pragma unroll
                for (int ni = 0; ni < 4; ni++) {
                    mma16816h(d[mi][ni], a_f[mi], bhf[ni]);
                    mma16816h(d[mi][ni], a_f[mi], blf[ni]);
                }
        }
        __syncthreads();
    }

    float* Sout = g_S + ((size_t)bc * NHEADS + h) * (HEADDIM * DSTATE);
    const int p0 = wm * 32 + (lane >> 2);
    const int n0 = wn * 32 + (lane & 3) * 2;
#pragma unroll
    for (int mi = 0; mi < 2; mi++)
#pragma unroll
        for (int ni = 0; ni < 4; ni++) {
            int col = n0 + ni * 8;
            *(float2*)&Sout[(size_t)(p0 + mi * 16) * DSTATE + col] =
                make_float2(d[mi][ni][0], d[mi][ni][1]);
            *(float2*)&Sout[(size_t)(p0 + mi * 16 + 8) * DSTATE + col] =
                make_float2(d[mi][ni][2], d[mi][ni][3]);
        }
}

// ---------------- convert kernels -------------------------------------------
__global__ void tofp16_kernel(const float* __restrict__ x, __half* __restrict__ o, size_t n)
{
    size_t i = (size_t)blockIdx.x * blockDim.x + threadIdx.x;
    if (i >= n) return;
    o[i] = __float2half(x[i]);
}

__global__ void tofp16_pad_kernel(const float* __restrict__ x, __half* __restrict__ o,
                                  int K, int N, int Np)
{
    size_t i = (size_t)blockIdx.x * blockDim.x + threadIdx.x;
    if (i >= (size_t)K * Np) return;
    int r = (int)(i / Np), c = (int)(i % Np);
    o[i] = __float2half((c < N) ? x[(size_t)r * N + c] : 0.f);
}

// ---------------- causal conv1d + SiLU: 8 outputs per thread ----------------
__global__ void conv_silu_kernel(const float* __restrict__ conv_w,
                                 const float* __restrict__ conv_b)
{
    int idx = blockIdx.x * blockDim.x + threadIdx.x;
    if (idx >= (ROWS / 8) * CONVDIM) return;
    int c  = idx % CONVDIM;
    int rg = idx / CONVDIM;
    int row0 = rg * 8;
    int l0 = row0 & (SEQLEN - 1);
    const float* base = g_zxbcdt + (size_t)row0 * DPROJ + DINNER + c;
    const float w0 = conv_w[c * DCONV + 0], w1 = conv_w[c * DCONV + 1];
    const float w2 = conv_w[c * DCONV + 2], w3 = conv_w[c * DCONV + 3];
    const float bias = conv_b[c];
    float v[11];
#pragma unroll
    for (int j = 0; j < 11; j++) {
        int l = l0 - 3 + j;
        v[j] = (l >= 0) ? base[(long)(j - 3) * DPROJ] : 0.f;
    }
#pragma unroll
    for (int i = 0; i < 8; i++) {
        float acc = bias + v[i] * w0 + v[i+1] * w1 + v[i+2] * w2 + v[i+3] * w3;
        g_xBC[(size_t)(row0 + i) * CONVDIM + c] = acc / (1.f + __expf(-acc));
    }
}

// ---------------- fused dt softplus + per-chunk cumsum ----------------------
__global__ void ascan_kernel(const float* __restrict__ A_log,
                             const float* __restrict__ dt_bias)
{
    int bc = blockIdx.x;
    int h  = blockIdx.y;
    int t  = threadIdx.x;
    int b = bc >> 4, c = bc & 15;
    __shared__ float sa[CHUNK];
    int row = b * SEQLEN + c * CHUNK + t;
    float v = g_zxbcdt[(size_t)row * DPROJ + DT_OFF + h] + dt_bias[h];
    float dtv = (v > 20.f) ? v : log1pf(expf(v));
    g_dt[row * NHEADS + h] = dtv;
    float A = -expf(A_log[h]);
    sa[t] = A * dtv;
    __syncthreads();
    for (int off = 1; off < CHUNK; off <<= 1) {
        float vv = (t >= off) ? sa[t - off] : 0.f;
        __syncthreads();
        sa[t] += vv;
        __syncthreads();
    }
    g_acs[(bc * NHEADS + h) * CHUNK + t] = sa[t];
    if (t == CHUNK - 1) g_asum[bc * NHEADS + h] = sa[t];
}

// ---------------- sequential inter-chunk recurrence (4-way split) -----------
// writes Sinit as fp16 directly (bit-identical to yfused's former conversion)
__global__ void chunkrec_kernel()
{
    int b = blockIdx.x, h = blockIdx.y, z = blockIdx.z;
    int t = threadIdx.x;
    float cur[8];
#pragma unroll
    for (int k = 0; k < 8; k++) cur[k] = 0.f;
    for (int c = 0; c < NCHUNK; c++) {
        int bc = b * NCHUNK + c;
        size_t base = ((size_t)bc * NHEADS + h) * (HEADDIM * DSTATE) + z * 2048;
        float dd = __expf(g_asum[bc * NHEADS + h]);
#pragma unroll
        for (int k = 0; k < 8; k++) {
            size_t e = base + t + 256 * k;
            g_Sinit[e] = __float2half(cur[k]);
            cur[k] = cur[k] * dd + g_S[e];
        }
    }
}

// ---------------- layernorm + z-gate (shuffle reduction) -> fp16 yg ---------
__global__ __launch_bounds__(256) void normgate_kernel(const float* __restrict__ norm_w)
{
    int row = blockIdx.x;
    int t = threadIdx.x;
    const int lane = t & 31, warp = t >> 5;
    const float* yrow = g_Y + (size_t)row * DINNER;
    const float* zrow = g_zxbcdt + (size_t)row * DPROJ;
    __shared__ float red[8];
    __shared__ float bres[2];
    float v[8];
    float s = 0.f;
#pragma unroll
    for (int i = 0; i < 8; i++) { v[i] = yrow[t + 256*i]; s += v[i]; }
#pragma unroll
    for (int o = 16; o > 0; o >>= 1) s += __shfl_xor_sync(0xffffffffu, s, o);
    if (lane == 0) red[warp] = s;
    __syncthreads();
    if (t == 0) {
        float tot = 0.f;
#pragma unroll
        for (int i = 0; i < 8; i++) tot += red[i];
        bres[0] = tot * (1.f / DINNER);
    }
    __syncthreads();
    const float mu = bres[0];
    float s2 = 0.f;
#pragma unroll
    for (int i = 0; i < 8; i++) { float dv = v[i] - mu; s2 += dv * dv; }
#pragma unroll
    for (int o = 16; o > 0; o >>= 1) s2 += __shfl_xor_sync(0xffffffffu, s2, o);
    if (lane == 0) red[warp] = s2;
    __syncthreads();
    if (t == 0) {
        float tot = 0.f;
#pragma unroll
        for (int i = 0; i < 8; i++) tot += red[i];
        bres[1] = rsqrtf(tot * (1.f / DINNER) + 1e-5f);
    }
    __syncthreads();
    const float inv = bres[1];
    __half* orow = g_yg + (size_t)row * DINNER;
#pragma unroll
    for (int i = 0; i < 8; i++) {
        int idx = t + 256*i;
        float z = zrow[idx];
        float g = z / (1.f + __expf(-z));
        orow[idx] = __float2half((v[i] - mu) * inv * norm_w[idx] * g);
    }
}

// ---------------- launch ---------------------------------------------------
extern "C" void kernel_launch(void* const* d_in, const int* in_sizes, int n_in,
                              void* d_out, int out_size)
{
    const float* u       = (const float*)d_in[0];
    const float* W_in    = (const float*)d_in[1];
    const float* conv_w  = (const float*)d_in[2];
    const float* conv_b  = (const float*)d_in[3];
    const float* dt_bias = (const float*)d_in[4];
    const float* A_log   = (const float*)d_in[5];
    const float* norm_w  = (const float*)d_in[6];
    const float* W_out   = (const float*)d_in[7];
    float* out = (float*)d_out;

    float* p_zx = nullptr;
    __half *p_uf, *p_wif, *p_wof, *p_yg;
    cudaGetSymbolAddress((void**)&p_zx,  g_zxbcdt);
    cudaGetSymbolAddress((void**)&p_uf,  g_uf);
    cudaGetSymbolAddress((void**)&p_wif, g_wif);
    cudaGetSymbolAddress((void**)&p_wof, g_wof);
    cudaGetSymbolAddress((void**)&p_yg,  g_yg);

    cudaFuncSetAttribute(mma_gemm, cudaFuncAttributeMaxDynamicSharedMemorySize, GEMM_SMEM);
    cudaFuncSetAttribute(yfused_kernel, cudaFuncAttributeMaxDynamicSharedMemorySize, YF_SMEM);
    cudaFuncSetAttribute(state_mma_kernel, cudaFuncAttributeMaxDynamicSharedMemorySize, ST_SMEM);
    cudaFuncSetAttribute(cb_mma_kernel, cudaFuncAttributeMaxDynamicSharedMemorySize, CB_SMEM);

    // 0. fp16 conversions
    {
        size_t n = (size_t)ROWS * DMODEL;
        tofp16_kernel<<<(unsigned)((n + 255) / 256), 256>>>(u, p_uf, n);
    }
    tofp16_pad_kernel<<<(unsigned)(((size_t)DMODEL * NPAD1 + 255) / 256), 256>>>(
        W_in, p_wif, DMODEL, DPROJ, NPAD1);
    {
        size_t n = (size_t)DINNER * DMODEL;
        tofp16_kernel<<<(unsigned)((n + 255) / 256), 256>>>(W_out, p_wof, n);
    }

    // 1. zxbcdt = u @ W_in  (8192 x 4384 x 1024), BK=64
    mma_gemm<<<dim3(NPAD1 / 128, ROWS / 128), 256, GEMM_SMEM>>>(
        p_uf, p_wif, p_zx, ROWS, DPROJ, DMODEL, NPAD1, DPROJ);
    // 2. causal conv1d + SiLU (8 l per thread)
    conv_silu_kernel<<<((ROWS / 8) * CONVDIM + 255) / 256, 256>>>(conv_w, conv_b);
    // 3. fused dt softplus + per-chunk cumsum
    ascan_kernel<<<dim3(NBC, NHEADS), CHUNK>>>(A_log, dt_bias);
    // 4. CB gram matrices (tensor cores, bf16 3-term, fp16 output)
    cb_mma_kernel<<<dim3(NBC, 4), 256, CB_SMEM>>>();
    // 5. per-chunk end states (tensor cores, fp16 2-term)
    state_mma_kernel<<<dim3(NBC, NHEADS), 256, ST_SMEM>>>();
    // 6. inter-chunk recurrence (4-way parallel; fp16 Sinit out)
    chunkrec_kernel<<<dim3(BATCH, NHEADS, 4), 256>>>();
    // 7. fused Y_diag + Y_off (tensor cores, factored decay + tri skip)
    yfused_kernel<<<dim3(NBC, NHEADS), 256, YF_SMEM>>>();
    // 8. layernorm + silu(z) gate (shuffle reduce) -> fp16
    normgate_kernel<<<ROWS, 256>>>(norm_w);
    // 9. out = yg @ W_out  (8192 x 1024 x 2048), BK=64
    mma_gemm<<<dim3(DMODEL / 128, ROWS / 128), 256, GEMM_SMEM>>>(
        p_yg, p_wof, out, ROWS, DMODEL, DINNER, DMODEL, DMODEL);
}

// round 17
// speedup vs baseline: 2.0436x; 1.0104x over previous
#include <cuda_runtime.h>
#include <cuda_bf16.h>
#include <cuda_fp16.h>
#include <math.h>
#include <stdint.h>

#define BATCH   2
#define SEQLEN  4096
#define DMODEL  1024
#define DINNER  2048
#define HEADDIM 64
#define NHEADS  32
#define DSTATE  128
#define DCONV   4
#define CHUNK   256
#define NCHUNK  (SEQLEN / CHUNK)   // 16
#define NBC     (BATCH * NCHUNK)   // 32
#define DPROJ   4384               // 2*DINNER + 2*DSTATE + NHEADS
#define CONVDIM 2304               // DINNER + 2*DSTATE
#define DT_OFF  4352               // 2*DINNER + 2*DSTATE
#define ROWS    (BATCH * SEQLEN)   // 8192
#define NPAD1   4480               // DPROJ padded to multiple of 128

// ---------------- scratch (device globals; no allocation allowed) ----------
__device__ float g_zxbcdt[(size_t)ROWS * DPROJ];
__device__ float g_xBC[(size_t)ROWS * CONVDIM];
__device__ float g_dt[ROWS * NHEADS];
__device__ float g_acs[NBC * NHEADS * CHUNK];
__device__ float g_asum[NBC * NHEADS];
__device__ __half g_CB[(size_t)NBC * CHUNK * CHUNK];
__device__ __half g_Y[(size_t)ROWS * DINNER];                 // fp16 now
__device__ float g_S[(size_t)NBC * NHEADS * HEADDIM * DSTATE];
__device__ __half g_Sinit[(size_t)NBC * NHEADS * HEADDIM * DSTATE];

// fp16 GEMM operands
__device__ __half g_uf[(size_t)ROWS * DMODEL];
__device__ __half g_wif[(size_t)DMODEL * NPAD1];
__device__ __half g_wof[(size_t)DINNER * DMODEL];
__device__ __half g_yg[(size_t)ROWS * DINNER];

// ---------------- helpers ---------------------------------------------------
__device__ __forceinline__ uint32_t s2u(const void* p) {
    return (uint32_t)__cvta_generic_to_shared(p);
}
#define CP16(dst, src) \
    asm volatile("cp.async.cg.shared.global [%0], [%1], 16;\n" :: "r"(dst), "l"(src))
#define CP_COMMIT() asm volatile("cp.async.commit_group;\n")
#define CP_WAIT1()  asm volatile("cp.async.wait_group 1;\n")

__device__ __forceinline__ void ldsm4(uint32_t& r0, uint32_t& r1, uint32_t& r2,
                                      uint32_t& r3, uint32_t addr) {
    asm volatile("ldmatrix.sync.aligned.m8n8.x4.shared.b16 {%0,%1,%2,%3}, [%4];"
                 : "=r"(r0), "=r"(r1), "=r"(r2), "=r"(r3) : "r"(addr));
}
__device__ __forceinline__ void ldsm4t(uint32_t& r0, uint32_t& r1, uint32_t& r2,
                                       uint32_t& r3, uint32_t addr) {
    asm volatile("ldmatrix.sync.aligned.m8n8.x4.trans.shared.b16 {%0,%1,%2,%3}, [%4];"
                 : "=r"(r0), "=r"(r1), "=r"(r2), "=r"(r3) : "r"(addr));
}
// fp16 mma
__device__ __forceinline__ void mma16816h(float* d, const uint32_t* a, const uint32_t* b) {
    asm volatile(
        "mma.sync.aligned.m16n8k16.row.col.f32.f16.f16.f32 "
        "{%0,%1,%2,%3}, {%4,%5,%6,%7}, {%8,%9}, {%0,%1,%2,%3};"
        : "+f"(d[0]), "+f"(d[1]), "+f"(d[2]), "+f"(d[3])
        : "r"(a[0]), "r"(a[1]), "r"(a[2]), "r"(a[3]), "r"(b[0]), "r"(b[1]));
}
__device__ __forceinline__ void split2h(float a, float b, __half2& h, __half2& l) {
    __half ha = __float2half(a), hb = __float2half(b);
    h = __halves2half2(ha, hb);
    l = __halves2half2(__float2half(a - __half2float(ha)),
                       __float2half(b - __half2float(hb)));
}

// ---------------- GEMM smem layout (bytes), tile 128x128, BK=64 -------------
#define A_B        18432         // 128*72*2
#define B_B        17408         // 64*136*2
#define OFF_B      A_B
#define STAGE_B    (A_B + B_B)                     // 35840
#define NSTAGE     3
#define GEMM_SMEM  (NSTAGE * STAGE_B)              // 107520

// ---------------- fp16 tensor-core GEMM, BK=64, 2 CTAs/SM -------------------
__global__ __launch_bounds__(256, 2) void mma_gemm(
    const __half* __restrict__ A, const __half* __restrict__ B,
    float* __restrict__ C, int M, int N, int K, int ldb, int ldc)
{
    extern __shared__ __half smem[];
    const uint32_t sbase = s2u(smem);
    const int rowBase = blockIdx.y * 128;
    const int colBase = blockIdx.x * 128;
    const int t = threadIdx.x;

    const int ar = t >> 3, aq = t & 7;
    const __half* aS = A + (size_t)(rowBase + ar) * K + aq * 8;
    const uint32_t aD = sbase + (ar * 72 + aq * 8) * 2;
    const int br = t >> 4, bq = t & 15;
    const __half* bS = B + (size_t)br * ldb + colBase + bq * 8;
    const uint32_t bD = sbase + OFF_B + (br * 136 + bq * 8) * 2;

    const int lane = t & 31, warp = t >> 5;
    const int wm = warp >> 2, wn = warp & 3;
    const int grp = lane >> 3, rr = lane & 7;

    uint32_t aAddr[4], bAddr[2];
#pragma unroll
    for (int mi = 0; mi < 4; mi++)
        aAddr[mi] = sbase + ((wm * 64 + mi * 16 + (grp & 1) * 8 + rr) * 72
                             + (grp >> 1) * 8) * 2;
#pragma unroll
    for (int pi = 0; pi < 2; pi++)
        bAddr[pi] = sbase + OFF_B + (((grp & 1) * 8 + rr) * 136
                             + wn * 32 + pi * 16 + (grp >> 1) * 8) * 2;

    float d[4][4][4];
#pragma unroll
    for (int mi = 0; mi < 4; mi++)
#pragma unroll
        for (int ni = 0; ni < 4; ni++)
#pragma unroll
            for (int k = 0; k < 4; k++) d[mi][ni][k] = 0.f;

    const int nk = K / 64;

#define LOAD_SLAB(st, kt) do {                                                  \
    const uint32_t _d = (st) * STAGE_B;                                         \
    const int _k = (kt) * 64;                                                   \
    _Pragma("unroll")                                                           \
    for (int i = 0; i < 4; i++)                                                 \
        CP16(aD + _d + (uint32_t)i * 32 * 72 * 2,                               \
             aS + (size_t)(i * 32) * K + _k);                                   \
    _Pragma("unroll")                                                           \
    for (int i = 0; i < 4; i++)                                                 \
        CP16(bD + _d + (uint32_t)i * 16 * 136 * 2,                              \
             bS + (size_t)(_k + i * 16) * ldb);                                 \
} while (0)

#define FRAGS_MMA(sd, ks) do {                                                  \
    const uint32_t _ka = (ks) * 32;                                             \
    const uint32_t _kb = (uint32_t)(ks) * 16 * 136 * 2;                         \
    uint32_t a_f[4][4], b_f[4][2];                                              \
    _Pragma("unroll")                                                           \
    for (int mi = 0; mi < 4; mi++)                                              \
        ldsm4(a_f[mi][0], a_f[mi][1], a_f[mi][2], a_f[mi][3],                   \
              aAddr[mi] + (sd) + _ka);                                          \
    _Pragma("unroll")                                                           \
    for (int pi = 0; pi < 2; pi++)                                              \
        ldsm4t(b_f[2*pi][0], b_f[2*pi][1], b_f[2*pi+1][0], b_f[2*pi+1][1],      \
               bAddr[pi] + (sd) + _kb);                                         \
    _Pragma("unroll")                                                           \
    for (int mi = 0; mi < 4; mi++)                                              \
        _Pragma("unroll")                                                       \
        for (int ni = 0; ni < 4; ni++)                                          \
            mma16816h(d[mi][ni], a_f[mi], b_f[ni]);                             \
} while (0)

    LOAD_SLAB(0, 0); CP_COMMIT();
    LOAD_SLAB(1, 1); CP_COMMIT();
    CP_WAIT1();
    __syncthreads();

    for (int kt = 0; kt < nk; kt++) {
        const uint32_t sd = (uint32_t)(kt % 3) * STAGE_B;
        if (kt + 2 < nk) LOAD_SLAB((kt + 2) % 3, kt + 2);
        CP_COMMIT();
        FRAGS_MMA(sd, 0);
        FRAGS_MMA(sd, 1);
        FRAGS_MMA(sd, 2);
        FRAGS_MMA(sd, 3);
        if (kt + 1 < nk) {
            CP_WAIT1();
            __syncthreads();
        }
    }

    const int r0 = rowBase + wm * 64 + (lane >> 2);
    const int c0 = colBase + wn * 32 + (lane & 3) * 2;
#pragma unroll
    for (int mi = 0; mi < 4; mi++)
#pragma unroll
        for (int ni = 0; ni < 4; ni++) {
            int col = c0 + ni * 8;
            if (col < N) {
                float2 v0 = make_float2(d[mi][ni][0], d[mi][ni][1]);
                float2 v1 = make_float2(d[mi][ni][2], d[mi][ni][3]);
                *(float2*)&C[(size_t)(r0 + mi * 16) * ldc + col] = v0;
                *(float2*)&C[(size_t)(r0 + mi * 16 + 8) * ldc + col] = v1;
            }
        }
#undef LOAD_SLAB
#undef FRAGS_MMA
}

// ---------------- CB gram via mma (fp16 2-term: C split, B single) ----------
#define CB_AH    0
#define CB_AL    17408               // 64*136*2
#define CB_B     34816
#define CB_SMEM  52224

__global__ __launch_bounds__(256, 2) void cb_mma_kernel()
{
    extern __shared__ char csm[];
    __half* Ah = (__half*)(csm + CB_AH);
    __half* Al = (__half*)(csm + CB_AL);
    __half* Bf = (__half*)(csm + CB_B);

    const int bc = blockIdx.x, lt = blockIdx.y;
    const int b = bc >> 4, c = bc & 15;
    const int t = threadIdx.x;
    const size_t rowB = (size_t)b * SEQLEN + c * CHUNK;

    const int lane = t & 31, warp = t >> 5;
    const int wm = warp >> 2, wn = warp & 3;
    const int grp = lane >> 3, rr = lane & 7;
    const uint32_t ahB = s2u(Ah), alB = s2u(Al), bfB = s2u(Bf);

    // load A tile (C slice, hi/lo fp16), rows lt*64 + r
    {
        const int r = t >> 2, q = (t & 3) * 32;
        const float* cr = g_xBC + (rowB + lt * 64 + r) * CONVDIM
                          + (DINNER + DSTATE) + q;
        __half2* ah2 = (__half2*)(Ah + r * 136 + q);
        __half2* al2 = (__half2*)(Al + r * 136 + q);
#pragma unroll
        for (int j = 0; j < 32; j += 4) {
            float4 v = *(const float4*)(cr + j);
            __half2 h01, l01, h23, l23;
            split2h(v.x, v.y, h01, l01);
            split2h(v.z, v.w, h23, l23);
            ah2[(j >> 1) + 0] = h01; ah2[(j >> 1) + 1] = h23;
            al2[(j >> 1) + 0] = l01; al2[(j >> 1) + 1] = l23;
        }
    }

    uint32_t aOff[2];
#pragma unroll
    for (int mi = 0; mi < 2; mi++)
        aOff[mi] = ((wm * 32 + mi * 16 + (grp & 1) * 8 + rr) * 136
                    + (grp >> 1) * 8) * 2;
    const uint32_t bOff = ((wn * 16 + (grp & 1) * 8 + rr) * 136
                           + (grp >> 1) * 8) * 2;

    float d[2][8][4];
#pragma unroll
    for (int mi = 0; mi < 2; mi++)
#pragma unroll
        for (int ni = 0; ni < 8; ni++)
#pragma unroll
            for (int k = 0; k < 4; k++) d[mi][ni][k] = 0.f;

    for (int stile = 0; stile < 4; stile++) {
        // load B tile (single fp16), rows stile*64 + r
        {
            const int r = t >> 2, q = (t & 3) * 32;
            const float* br = g_xBC + (rowB + stile * 64 + r) * CONVDIM
                              + DINNER + q;
            __half2* bf2 = (__half2*)(Bf + r * 136 + q);
#pragma unroll
            for (int j = 0; j < 32; j += 4) {
                float4 v = *(const float4*)(br + j);
                bf2[(j >> 1) + 0] = __floats2half2_rn(v.x, v.y);
                bf2[(j >> 1) + 1] = __floats2half2_rn(v.z, v.w);
            }
        }
        __syncthreads();
#pragma unroll
        for (int k = 0; k < 8; k++) {
            const uint32_t ko = k * 32;
            uint32_t a_h[2][4], a_l[2][4], b4[4];
#pragma unroll
            for (int mi = 0; mi < 2; mi++) {
                ldsm4(a_h[mi][0], a_h[mi][1], a_h[mi][2], a_h[mi][3],
                      ahB + aOff[mi] + ko);
                ldsm4(a_l[mi][0], a_l[mi][1], a_l[mi][2], a_l[mi][3],
                      alB + aOff[mi] + ko);
            }
            ldsm4(b4[0], b4[1], b4[2], b4[3], bfB + bOff + ko);
            uint32_t bh0[2] = {b4[0], b4[2]};
            uint32_t bh1[2] = {b4[1], b4[3]};
#pragma unroll
            for (int mi = 0; mi < 2; mi++) {
                mma16816h(d[mi][stile * 2 + 0], a_h[mi], bh0);
                mma16816h(d[mi][stile * 2 + 0], a_l[mi], bh0);
                mma16816h(d[mi][stile * 2 + 1], a_h[mi], bh1);
                mma16816h(d[mi][stile * 2 + 1], a_l[mi], bh1);
            }
        }
        __syncthreads();
    }

    const int r0 = lt * 64 + wm * 32 + (lane >> 2);
    const int c0 = (lane & 3) * 2;
#pragma unroll
    for (int mi = 0; mi < 2; mi++) {
        __half* out0 = g_CB + ((size_t)bc * CHUNK + r0 + mi * 16) * CHUNK;
        __half* out1 = out0 + 8 * CHUNK;
#pragma unroll
        for (int st = 0; st < 4; st++)
#pragma unroll
            for (int q = 0; q < 2; q++) {
                int col = st * 64 + wn * 16 + q * 8 + c0;
                float* dd = d[mi][st * 2 + q];
                *(__half2*)&out0[col] = __floats2half2_rn(dd[0], dd[1]);
                *(__half2*)&out1[col] = __floats2half2_rn(dd[2], dd[3]);
            }
    }
}

// ---------------- fused Y (fp16, factored decay + triangular skip) ----------
#define YF_WH    0
#define YF_WL    36864               // 256*72*2
#define YF_XH    73728               // 64*72*2 = 9216
#define YF_ACS   82944
#define YF_DT    83968
#define YF_SCOL  84992
#define YF_SMEM  86016

__global__ __launch_bounds__(256, 2) void yfused_kernel()
{
    extern __shared__ char ysm[];
    __half* Wh = (__half*)(ysm + YF_WH);
    __half* Wl = (__half*)(ysm + YF_WL);
    __half* Xh = (__half*)(ysm + YF_XH);
    float* sacs = (float*)(ysm + YF_ACS);
    float* sdt  = (float*)(ysm + YF_DT);
    float* scol = (float*)(ysm + YF_SCOL);

    const int bc = blockIdx.x, h = blockIdx.y;
    const int b = bc >> 4, c = bc & 15;
    const int t = threadIdx.x;
    const size_t rowB = (size_t)b * SEQLEN + c * CHUNK;

    sacs[t] = g_acs[((size_t)bc * NHEADS + h) * CHUNK + t];
    sdt[t]  = g_dt[(rowB + t) * NHEADS + h];
    __syncthreads();
    const float acs_l = sacs[t];
    scol[t] = __expf(sacs[t | 63] - acs_l);
    __syncthreads();

    const int lane = t & 31, warp = t >> 5;
    const int grp = lane >> 3, rr = lane & 7;
    const uint32_t whB = s2u(Wh), wlB = s2u(Wl), xhB = s2u(Xh);

    uint32_t aOff[2], bOff[4];
#pragma unroll
    for (int mi = 0; mi < 2; mi++)
        aOff[mi] = ((warp * 32 + mi * 16 + (grp & 1) * 8 + rr) * 72
                    + (grp >> 1) * 8) * 2;
#pragma unroll
    for (int pi = 0; pi < 4; pi++)
        bOff[pi] = (((grp & 1) * 8 + rr) * 72 + pi * 16 + (grp >> 1) * 8) * 2;

    float d[2][8][4];
#pragma unroll
    for (int mi = 0; mi < 2; mi++)
#pragma unroll
        for (int ni = 0; ni < 8; ni++)
#pragma unroll
            for (int k = 0; k < 4; k++) d[mi][ni][k] = 0.f;

#define YF_MMA() do {                                                           \
    _Pragma("unroll")                                                           \
    for (int k = 0; k < 4; k++) {                                               \
        const uint32_t ka = k * 32;                                             \
        const uint32_t kb = k * 16 * 144;                                       \
        uint32_t a_h[2][4], a_l[2][4];                                          \
        _Pragma("unroll")                                                       \
        for (int mi = 0; mi < 2; mi++) {                                        \
            ldsm4(a_h[mi][0], a_h[mi][1], a_h[mi][2], a_h[mi][3],               \
                  whB + aOff[mi] + ka);                                         \
            ldsm4(a_l[mi][0], a_l[mi][1], a_l[mi][2], a_l[mi][3],               \
                  wlB + aOff[mi] + ka);                                         \
        }                                                                       \
        _Pragma("unroll")                                                       \
        for (int pi = 0; pi < 4; pi++) {                                        \
            uint32_t bh[2][2];                                                  \
            ldsm4t(bh[0][0], bh[0][1], bh[1][0], bh[1][1],                      \
                   xhB + bOff[pi] + kb);                                        \
            _Pragma("unroll")                                                   \
            for (int mi = 0; mi < 2; mi++)                                      \
                _Pragma("unroll")                                               \
                for (int q = 0; q < 2; q++) {                                   \
                    mma16816h(d[mi][2*pi+q], a_h[mi], bh[q]);                   \
                    mma16816h(d[mi][2*pi+q], a_l[mi], bh[q]);                   \
                }                                                               \
        }                                                                       \
    }                                                                           \
} while (0)

    // ---- part 1: Y_diag, 4 s-tiles of 64, triangular ----
    const __half* CBrow = g_CB + ((size_t)bc * CHUNK + t) * CHUNK;
    for (int st = 0; st < 4; st++) {
        const int s0 = st * 64;
        if (t >= s0) {
            __half2* wh2 = (__half2*)(Wh + t * 72);
            __half2* wl2 = (__half2*)(Wl + t * 72);
            if (t < s0 + 64) {
#pragma unroll
                for (int j = 0; j < 64; j += 4) {
                    __half2 p0 = *(const __half2*)(CBrow + s0 + j);
                    __half2 p1 = *(const __half2*)(CBrow + s0 + j + 2);
                    float2 f0 = __half22float2(p0), f1 = __half22float2(p1);
                    float cbp[4] = {f0.x, f0.y, f1.x, f1.y};
                    float w[4];
#pragma unroll
                    for (int e = 0; e < 4; e++) {
                        int s = s0 + j + e;
                        float arg = fminf(acs_l - sacs[s], 0.f);
                        w[e] = (s <= t) ? cbp[e] * __expf(arg) : 0.f;
                    }
                    __half2 h01, l01, h23, l23;
                    split2h(w[0], w[1], h01, l01);
                    split2h(w[2], w[3], h23, l23);
                    wh2[(j >> 1) + 0] = h01; wh2[(j >> 1) + 1] = h23;
                    wl2[(j >> 1) + 0] = l01; wl2[(j >> 1) + 1] = l23;
                }
            } else {
                const float rowf = __expf(sacs[s0 + 63] >= acs_l ?
                                          acs_l - sacs[s0 + 63] : 0.f);
#pragma unroll
                for (int j = 0; j < 64; j += 4) {
                    __half2 p0 = *(const __half2*)(CBrow + s0 + j);
                    __half2 p1 = *(const __half2*)(CBrow + s0 + j + 2);
                    float2 f0 = __half22float2(p0), f1 = __half22float2(p1);
                    float cbp[4] = {f0.x, f0.y, f1.x, f1.y};
                    float w[4];
#pragma unroll
                    for (int e = 0; e < 4; e++)
                        w[e] = cbp[e] * rowf * scol[s0 + j + e];
                    __half2 h01, l01, h23, l23;
                    split2h(w[0], w[1], h01, l01);
                    split2h(w[2], w[3], h23, l23);
                    wh2[(j >> 1) + 0] = h01; wh2[(j >> 1) + 1] = h23;
                    wl2[(j >> 1) + 0] = l01; wl2[(j >> 1) + 1] = l23;
                }
            }
        }
        {
            const int r = t >> 2, c16 = (t & 3) * 16;
            const float dts = sdt[s0 + r];
            const float* xr = g_xBC + (rowB + s0 + r) * CONVDIM + h * HEADDIM + c16;
            __half2* xh2 = (__half2*)(Xh + r * 72 + c16);
#pragma unroll
            for (int j = 0; j < 16; j += 4) {
                float4 v = *(const float4*)(xr + j);
                xh2[(j >> 1) + 0] = __floats2half2_rn(v.x * dts, v.y * dts);
                xh2[(j >> 1) + 1] = __floats2half2_rn(v.z * dts, v.w * dts);
            }
        }
        __syncthreads();
        if (warp >= st * 2) {
            YF_MMA();
        }
        __syncthreads();
    }

    // ---- part 2: Y_off, 2 n-tiles of 64 ----
    const float el = __expf(acs_l);
    const float* Crow = g_xBC + (rowB + t) * CONVDIM + DINNER + DSTATE;
    const __half* S0p = g_Sinit + ((size_t)bc * NHEADS + h) * (HEADDIM * DSTATE);
    for (int nt = 0; nt < 2; nt++) {
        const int n0 = nt * 64;
        __half2* wh2 = (__half2*)(Wh + t * 72);
        __half2* wl2 = (__half2*)(Wl + t * 72);
#pragma unroll
        for (int j = 0; j < 64; j += 4) {
            float4 c4 = *(const float4*)(Crow + n0 + j);
            __half2 h01, l01, h23, l23;
            split2h(c4.x * el, c4.y * el, h01, l01);
            split2h(c4.z * el, c4.w * el, h23, l23);
            wh2[(j >> 1) + 0] = h01; wh2[(j >> 1) + 1] = h23;
            wl2[(j >> 1) + 0] = l01; wl2[(j >> 1) + 1] = l23;
        }
        {
            const int p = t >> 2, nb = (t & 3) * 16;
            const __half* sp = S0p + (size_t)p * DSTATE + n0 + nb;
#pragma unroll
            for (int j = 0; j < 16; j++)
                Xh[(nb + j) * 72 + p] = sp[j];
        }
        __syncthreads();
        YF_MMA();
        __syncthreads();
    }
#undef YF_MMA

    const int c0 = (lane & 3) * 2;
#pragma unroll
    for (int mi = 0; mi < 2; mi++) {
        const size_t gr0 = (rowB + warp * 32 + (lane >> 2) + mi * 16) * DINNER + h * HEADDIM;
#pragma unroll
        for (int ni = 0; ni < 8; ni++) {
            int col = c0 + ni * 8;
            *(__half2*)&g_Y[gr0 + col] = __floats2half2_rn(d[mi][ni][0], d[mi][ni][1]);
            *(__half2*)&g_Y[gr0 + 8 * DINNER + col] =
                __floats2half2_rn(d[mi][ni][2], d[mi][ni][3]);
        }
    }
}

// ---------------- state S = x^T . (w.B)  (fp16: x single, w.B split) --------
#define ST_A     0
#define ST_BH    9216                // 64*72*2
#define ST_BL    26624               // + 64*136*2
#define ST_SMEM  44032

__global__ __launch_bounds__(256, 2) void state_mma_kernel()
{
    extern __shared__ char ssm[];
    __half* Ax = (__half*)(ssm + ST_A);
    __half* Bh = (__half*)(ssm + ST_BH);
    __half* Bl = (__half*)(ssm + ST_BL);

    const int bc = blockIdx.x, h = blockIdx.y;
    const int b = bc >> 4, c = bc & 15;
    const int t = threadIdx.x;
    const size_t rowB = (size_t)b * SEQLEN + c * CHUNK;
    const float asum = g_asum[bc * NHEADS + h];
    const float* acsp = g_acs + ((size_t)bc * NHEADS + h) * CHUNK;

    const int lane = t & 31, warp = t >> 5;
    const int wm = warp >> 2, wn = warp & 3;
    const int grp = lane >> 3, rr = lane & 7;
    const uint32_t axB = s2u(Ax), bhB = s2u(Bh), blB = s2u(Bl);

    uint32_t aOff[2], bOff[2];
#pragma unroll
    for (int mi = 0; mi < 2; mi++)
        aOff[mi] = ((wm * 32 + mi * 16 + (grp & 1) * 8 + rr) * 72
                    + (grp >> 1) * 8) * 2;
#pragma unroll
    for (int pi = 0; pi < 2; pi++)
        bOff[pi] = (((grp & 1) * 8 + rr) * 136
                    + wn * 32 + pi * 16 + (grp >> 1) * 8) * 2;

    float d[2][4][4];
#pragma unroll
    for (int mi = 0; mi < 2; mi++)
#pragma unroll
        for (int ni = 0; ni < 4; ni++)
#pragma unroll
            for (int k = 0; k < 4; k++) d[mi][ni][k] = 0.f;

    for (int st4 = 0; st4 < 4; st4++) {
        const int s0 = st4 * 64;
        const int r = t >> 2;
        const float w = g_dt[(rowB + s0 + r) * NHEADS + h] *
                        __expf(asum - acsp[s0 + r]);
        {
            const int q = (t & 3) * 16;
            const float* xr = g_xBC + (rowB + s0 + r) * CONVDIM + h * HEADDIM + q;
#pragma unroll
            for (int j = 0; j < 16; j += 4) {
                float4 v = *(const float4*)(xr + j);
                Ax[(q + j + 0) * 72 + r] = __float2half(v.x);
                Ax[(q + j + 1) * 72 + r] = __float2half(v.y);
                Ax[(q + j + 2) * 72 + r] = __float2half(v.z);
                Ax[(q + j + 3) * 72 + r] = __float2half(v.w);
            }
        }
        {
            const int nq = (t & 3) * 32;
            const float* brp = g_xBC + (rowB + s0 + r) * CONVDIM + DINNER + nq;
            __half2* bh2 = (__half2*)(Bh + r * 136 + nq);
            __half2* bl2 = (__half2*)(Bl + r * 136 + nq);
#pragma unroll
            for (int j = 0; j < 32; j += 4) {
                float4 v = *(const float4*)(brp + j);
                __half2 h01, l01, h23, l23;
                split2h(v.x * w, v.y * w, h01, l01);
                split2h(v.z * w, v.w * w, h23, l23);
                bh2[(j >> 1) + 0] = h01; bh2[(j >> 1) + 1] = h23;
                bl2[(j >> 1) + 0] = l01; bl2[(j >> 1) + 1] = l23;
            }
        }
        __syncthreads();
#pragma unroll
        for (int k = 0; k < 4; k++) {
            const uint32_t ka = k * 32;
            const uint32_t kb = (uint32_t)k * 16 * 136 * 2;
            uint32_t a_f[2][4], bhf[4][2], blf[4][2];
#pragma unroll
            for (int mi = 0; mi < 2; mi++)
                ldsm4(a_f[mi][0], a_f[mi][1], a_f[mi][2], a_f[mi][3],
                      axB + aOff[mi] + ka);
#pragma unroll
            for (int pi = 0; pi < 2; pi++) {
                ldsm4t(bhf[2*pi][0], bhf[2*pi][1], bhf[2*pi+1][0], bhf[2*pi+1][1],
                       bhB + bOff[pi] + kb);
                ldsm4t(blf[2*pi][0], blf[2*pi][1], blf[2*pi+1][0], blf[2*pi+1][1],
                       blB + bOff[pi] + kb);
            }
#pragma unroll
            for (int mi = 0; mi < 2; mi++)
#pragma unroll
                for (int ni = 0; ni < 4; ni++) {
                    mma16816h(d[mi][ni], a_f[mi], bhf[ni]);
                    mma16816h(d[mi][ni], a_f[mi], blf[ni]);
                }
        }
        __syncthreads();
    }

    float* Sout = g_S + ((size_t)bc * NHEADS + h) * (HEADDIM * DSTATE);
    const int p0 = wm * 32 + (lane >> 2);
    const int n0 = wn * 32 + (lane & 3) * 2;
#pragma unroll
    for (int mi = 0; mi < 2; mi++)
#pragma unroll
        for (int ni = 0; ni < 4; ni++) {
            int col = n0 + ni * 8;
            *(float2*)&Sout[(size_t)(p0 + mi * 16) * DSTATE + col] =
                make_float2(d[mi][ni][0], d[mi][ni][1]);
            *(float2*)&Sout[(size_t)(p0 + mi * 16 + 8) * DSTATE + col] =
                make_float2(d[mi][ni][2], d[mi][ni][3]);
        }
}

// ---------------- fused fp16 converts (u | W_in pad | W_out) ----------------
#define N_U   ((size_t)ROWS * DMODEL)        // 8388608
#define N_WI  ((size_t)DMODEL * NPAD1)       // 4587520
#define N_WO  ((size_t)DINNER * DMODEL)      // 2097152
#define N_CVT (N_U + N_WI + N_WO)

__global__ void convert_all_kernel(const float* __restrict__ u,
                                   const float* __restrict__ W_in,
                                   const float* __restrict__ W_out)
{
    size_t i = (size_t)blockIdx.x * blockDim.x + threadIdx.x;
    if (i < N_U) {
        g_uf[i] = __float2half(u[i]);
    } else if (i < N_U + N_WI) {
        size_t j = i - N_U;
        int r = (int)(j / NPAD1), c = (int)(j % NPAD1);
        g_wif[j] = __float2half((c < DPROJ) ? W_in[(size_t)r * DPROJ + c] : 0.f);
    } else if (i < N_CVT) {
        size_t j = i - N_U - N_WI;
        g_wof[j] = __float2half(W_out[j]);
    }
}

// ---------------- causal conv1d + SiLU: 8 outputs per thread ----------------
__global__ void conv_silu_kernel(const float* __restrict__ conv_w,
                                 const float* __restrict__ conv_b)
{
    int idx = blockIdx.x * blockDim.x + threadIdx.x;
    if (idx >= (ROWS / 8) * CONVDIM) return;
    int c  = idx % CONVDIM;
    int rg = idx / CONVDIM;
    int row0 = rg * 8;
    int l0 = row0 & (SEQLEN - 1);
    const float* base = g_zxbcdt + (size_t)row0 * DPROJ + DINNER + c;
    const float w0 = conv_w[c * DCONV + 0], w1 = conv_w[c * DCONV + 1];
    const float w2 = conv_w[c * DCONV + 2], w3 = conv_w[c * DCONV + 3];
    const float bias = conv_b[c];
    float v[11];
#pragma unroll
    for (int j = 0; j < 11; j++) {
        int l = l0 - 3 + j;
        v[j] = (l >= 0) ? base[(long)(j - 3) * DPROJ] : 0.f;
    }
#pragma unroll
    for (int i = 0; i < 8; i++) {
        float acc = bias + v[i] * w0 + v[i+1] * w1 + v[i+2] * w2 + v[i+3] * w3;
        g_xBC[(size_t)(row0 + i) * CONVDIM + c] = acc / (1.f + __expf(-acc));
    }
}

// ---------------- fused dt softplus + per-chunk cumsum ----------------------
__global__ void ascan_kernel(const float* __restrict__ A_log,
                             const float* __restrict__ dt_bias)
{
    int bc = blockIdx.x;
    int h  = blockIdx.y;
    int t  = threadIdx.x;
    int b = bc >> 4, c = bc & 15;
    __shared__ float sa[CHUNK];
    int row = b * SEQLEN + c * CHUNK + t;
    float v = g_zxbcdt[(size_t)row * DPROJ + DT_OFF + h] + dt_bias[h];
    float dtv = (v > 20.f) ? v : log1pf(expf(v));
    g_dt[row * NHEADS + h] = dtv;
    float A = -expf(A_log[h]);
    sa[t] = A * dtv;
    __syncthreads();
    for (int off = 1; off < CHUNK; off <<= 1) {
        float vv = (t >= off) ? sa[t - off] : 0.f;
        __syncthreads();
        sa[t] += vv;
        __syncthreads();
    }
    g_acs[(bc * NHEADS + h) * CHUNK + t] = sa[t];
    if (t == CHUNK - 1) g_asum[bc * NHEADS + h] = sa[t];
}

// ---------------- sequential inter-chunk recurrence (4-way split) -----------
__global__ void chunkrec_kernel()
{
    int b = blockIdx.x, h = blockIdx.y, z = blockIdx.z;
    int t = threadIdx.x;
    float cur[8];
#pragma unroll
    for (int k = 0; k < 8; k++) cur[k] = 0.f;
    for (int c = 0; c < NCHUNK; c++) {
        int bc = b * NCHUNK + c;
        size_t base = ((size_t)bc * NHEADS + h) * (HEADDIM * DSTATE) + z * 2048;
        float dd = __expf(g_asum[bc * NHEADS + h]);
#pragma unroll
        for (int k = 0; k < 8; k++) {
            size_t e = base + t + 256 * k;
            g_Sinit[e] = __float2half(cur[k]);
            cur[k] = cur[k] * dd + g_S[e];
        }
    }
}

// ---------------- layernorm + z-gate (shuffle reduction) -> fp16 yg ---------
__global__ __launch_bounds__(256) void normgate_kernel(const float* __restrict__ norm_w)
{
    int row = blockIdx.x;
    int t = threadIdx.x;
    const int lane = t & 31, warp = t >> 5;
    const __half* yrow = g_Y + (size_t)row * DINNER;
    const float* zrow = g_zxbcdt + (size_t)row * DPROJ;
    __shared__ float red[8];
    __shared__ float bres[2];
    float v[8];
    float s = 0.f;
#pragma unroll
    for (int i = 0; i < 8; i++) { v[i] = __half2float(yrow[t + 256*i]); s += v[i]; }
#pragma unroll
    for (int o = 16; o > 0; o >>= 1) s += __shfl_xor_sync(0xffffffffu, s, o);
    if (lane == 0) red[warp] = s;
    __syncthreads();
    if (t == 0) {
        float tot = 0.f;
#pragma unroll
        for (int i = 0; i < 8; i++) tot += red[i];
        bres[0] = tot * (1.f / DINNER);
    }
    __syncthreads();
    const float mu = bres[0];
    float s2 = 0.f;
#pragma unroll
    for (int i = 0; i < 8; i++) { float dv = v[i] - mu; s2 += dv * dv; }
#pragma unroll
    for (int o = 16; o > 0; o >>= 1) s2 += __shfl_xor_sync(0xffffffffu, s2, o);
    if (lane == 0) red[warp] = s2;
    __syncthreads();
    if (t == 0) {
        float tot = 0.f;
#pragma unroll
        for (int i = 0; i < 8; i++) tot += red[i];
        bres[1] = rsqrtf(tot * (1.f / DINNER) + 1e-5f);
    }
    __syncthreads();
    const float inv = bres[1];
    __half* orow = g_yg + (size_t)row * DINNER;
#pragma unroll
    for (int i = 0; i < 8; i++) {
        int idx = t + 256*i;
        float z = zrow[idx];
        float g = z / (1.f + __expf(-z));
        orow[idx] = __float2half((v[i] - mu) * inv * norm_w[idx] * g);
    }
}

// ---------------- launch ---------------------------------------------------
extern "C" void kernel_launch(void* const* d_in, const int* in_sizes, int n_in,
                              void* d_out, int out_size)
{
    const float* u       = (const float*)d_in[0];
    const float* W_in    = (const float*)d_in[1];
    const float* conv_w  = (const float*)d_in[2];
    const float* conv_b  = (const float*)d_in[3];
    const float* dt_bias = (const float*)d_in[4];
    const float* A_log   = (const float*)d_in[5];
    const float* norm_w  = (const float*)d_in[6];
    const float* W_out   = (const float*)d_in[7];
    float* out = (float*)d_out;

    float* p_zx = nullptr;
    __half *p_uf, *p_wif, *p_wof, *p_yg;
    cudaGetSymbolAddress((void**)&p_zx,  g_zxbcdt);
    cudaGetSymbolAddress((void**)&p_uf,  g_uf);
    cudaGetSymbolAddress((void**)&p_wif, g_wif);
    cudaGetSymbolAddress((void**)&p_wof, g_wof);
    cudaGetSymbolAddress((void**)&p_yg,  g_yg);

    cudaFuncSetAttribute(mma_gemm, cudaFuncAttributeMaxDynamicSharedMemorySize, GEMM_SMEM);
    cudaFuncSetAttribute(yfused_kernel, cudaFuncAttributeMaxDynamicSharedMemorySize, YF_SMEM);
    cudaFuncSetAttribute(state_mma_kernel, cudaFuncAttributeMaxDynamicSharedMemorySize, ST_SMEM);
    cudaFuncSetAttribute(cb_mma_kernel, cudaFuncAttributeMaxDynamicSharedMemorySize, CB_SMEM);

    // 0. fused fp16 conversions (u | W_in | W_out)
    convert_all_kernel<<<(unsigned)((N_CVT + 255) / 256), 256>>>(u, W_in, W_out);

    // 1. zxbcdt = u @ W_in  (8192 x 4384 x 1024), BK=64
    mma_gemm<<<dim3(NPAD1 / 128, ROWS / 128), 256, GEMM_SMEM>>>(
        p_uf, p_wif, p_zx, ROWS, DPROJ, DMODEL, NPAD1, DPROJ);
    // 2. causal conv1d + SiLU (8 l per thread)
    conv_silu_kernel<<<((ROWS / 8) * CONVDIM + 255) / 256, 256>>>(conv_w, conv_b);
    // 3. fused dt softplus + per-chunk cumsum
    ascan_kernel<<<dim3(NBC, NHEADS), CHUNK>>>(A_log, dt_bias);
    // 4. CB gram matrices (tensor cores, fp16 2-term, fp16 output)
    cb_mma_kernel<<<dim3(NBC, 4), 256, CB_SMEM>>>();
    // 5. per-chunk end states (tensor cores, fp16 2-term)
    state_mma_kernel<<<dim3(NBC, NHEADS), 256, ST_SMEM>>>();
    // 6. inter-chunk recurrence (4-way parallel; fp16 Sinit out)
    chunkrec_kernel<<<dim3(BATCH, NHEADS, 4), 256>>>();
    // 7. fused Y_diag + Y_off (tensor cores; fp16 Y out)
    yfused_kernel<<<dim3(NBC, NHEADS), 256, YF_SMEM>>>();
    // 8. layernorm + silu(z) gate (shuffle reduce) -> fp16
    normgate_kernel<<<ROWS, 256>>>(norm_w);
    // 9. out = yg @ W_out  (8192 x 1024 x 2048), BK=64
    mma_gemm<<<dim3(DMODEL / 128, ROWS / 128), 256, GEMM_SMEM>>>(
        p_yg, p_wof, out, ROWS, DMODEL, DINNER, DMODEL, DMODEL);
}